// round 2
// baseline (speedup 1.0000x reference)
#include <cuda_runtime.h>
#include <math.h>

#define NB 4
#define LQ 2048
#define CH 1024
#define NHD 8
#define HD 128
#define NL (NB * LQ)
#define NHT (NB * NHD)   // 32 (n,h) pairs
#define KVSPLIT 8
#define EPS_ATTN 1e-6f
#define EPS_LN 1e-5f

// ---------------- scratch (device globals; no allocation allowed) ----------------
__device__ float g_ctx[NL * CH];
__device__ float g_q[NL * CH];
__device__ float g_k[NL * CH];
__device__ float g_v[NL * CH];
__device__ float g_attn[NL * CH];
__device__ float g_msg[NL * CH];
__device__ float g_x[NL * CH];
__device__ float g_y[NL * CH];
__device__ float g_h[NL * 2 * CH];
__device__ float g_kvpart[KVSPLIT * NHT * HD * HD];
__device__ float g_kv[NHT * HD * HD];
__device__ float g_kspart[KVSPLIT * NHT * HD];
__device__ float g_ksum[NHT * HD];

// elu(x)+1  (alpha=1):  x>0 ? x+1 : exp(x)
__device__ __forceinline__ float fmap(float x) {
    return x > 0.0f ? x + 1.0f : expf(x);
}

// ---------------- elementwise add ----------------
__global__ void add_kernel(const float* __restrict__ a, const float* __restrict__ b,
                           float* __restrict__ o, int n4) {
    int idx = blockIdx.x * blockDim.x + threadIdx.x;
    int stride = gridDim.x * blockDim.x;
    const float4* a4 = (const float4*)a;
    const float4* b4 = (const float4*)b;
    float4* o4 = (float4*)o;
    for (int i = idx; i < n4; i += stride) {
        float4 x = a4[i], y = b4[i];
        x.x += y.x; x.y += y.y; x.z += y.z; x.w += y.w;
        o4[i] = x;
    }
}

// ---------------- SGEMM: C[M,Nn] = A[M,K] @ B[K,Nn], optional ReLU ----------------
// BM=BN=128, BK=8, 256 threads, 8x8 per thread
template <bool RELU>
__global__ __launch_bounds__(256) void sgemm_kernel(
    const float* __restrict__ A, const float* __restrict__ B, float* __restrict__ Cm,
    int M, int K, int Nn) {
    __shared__ float As[8][128];
    __shared__ float Bs[8][128];
    const int tid = threadIdx.x;
    const int bm = blockIdx.y * 128;
    const int bn = blockIdx.x * 128;
    const int tx = (tid & 15) << 3;
    const int ty = (tid >> 4) << 3;
    const int arow = tid >> 1, acol = (tid & 1) << 2;
    const int brow = tid >> 5, bcol = (tid & 31) << 2;
    const float* Ap = A + (size_t)(bm + arow) * K + acol;
    const float* Bp = B + (size_t)brow * Nn + bn + bcol;

    float acc[8][8];
#pragma unroll
    for (int i = 0; i < 8; i++)
#pragma unroll
        for (int j = 0; j < 8; j++) acc[i][j] = 0.0f;

    for (int k0 = 0; k0 < K; k0 += 8) {
        float4 av = *(const float4*)Ap; Ap += 8;
        float4 bv = *(const float4*)Bp; Bp += (size_t)8 * Nn;
        As[acol + 0][arow] = av.x;
        As[acol + 1][arow] = av.y;
        As[acol + 2][arow] = av.z;
        As[acol + 3][arow] = av.w;
        *(float4*)&Bs[brow][bcol] = bv;
        __syncthreads();
#pragma unroll
        for (int kk = 0; kk < 8; kk++) {
            float ra[8], rb[8];
            *(float4*)(ra)     = *(const float4*)&As[kk][ty];
            *(float4*)(ra + 4) = *(const float4*)&As[kk][ty + 4];
            *(float4*)(rb)     = *(const float4*)&Bs[kk][tx];
            *(float4*)(rb + 4) = *(const float4*)&Bs[kk][tx + 4];
#pragma unroll
            for (int i = 0; i < 8; i++)
#pragma unroll
                for (int j = 0; j < 8; j++)
                    acc[i][j] = fmaf(ra[i], rb[j], acc[i][j]);
        }
        __syncthreads();
    }

#pragma unroll
    for (int i = 0; i < 8; i++) {
        float* Cp = Cm + (size_t)(bm + ty + i) * Nn + bn + tx;
#pragma unroll
        for (int jv = 0; jv < 2; jv++) {
            float4 o;
            o.x = acc[i][jv * 4 + 0];
            o.y = acc[i][jv * 4 + 1];
            o.z = acc[i][jv * 4 + 2];
            o.w = acc[i][jv * 4 + 3];
            if (RELU) {
                o.x = fmaxf(o.x, 0.0f); o.y = fmaxf(o.y, 0.0f);
                o.z = fmaxf(o.z, 0.0f); o.w = fmaxf(o.w, 0.0f);
            }
            *(float4*)(Cp + jv * 4) = o;
        }
    }
}

// ---------------- attention: KV = fmap(K)^T @ V (split over L), plus partial sum(K) ----------------
__global__ __launch_bounds__(256) void attn_kv_kernel(
    const float* __restrict__ Kg, const float* __restrict__ Vg,
    float* __restrict__ kvpart, float* __restrict__ kspart) {
    const int nh = blockIdx.x;     // 0..31
    const int split = blockIdx.y;  // 0..KVSPLIT-1
    const int n = nh >> 3, h = nh & 7;
    const int lbase = split * (LQ / KVSPLIT);
    __shared__ float Ks[8][128];
    __shared__ float Vs[8][128];
    __shared__ float ksp[8][128];
    const int tid = threadIdx.x;
    const int tx = (tid & 15) << 3;  // v
    const int ty = (tid >> 4) << 3;  // d
    const int lrow = tid >> 5;       // 0..7
    const int dcol = (tid & 31) << 2;
    const size_t base = ((size_t)(n * LQ + lbase)) * CH + h * HD;

    float acc[8][8];
#pragma unroll
    for (int i = 0; i < 8; i++)
#pragma unroll
        for (int j = 0; j < 8; j++) acc[i][j] = 0.0f;
    float ksacc0 = 0.f, ksacc1 = 0.f, ksacc2 = 0.f, ksacc3 = 0.f;

    for (int lt = 0; lt < LQ / KVSPLIT; lt += 8) {
        size_t off = base + (size_t)(lt + lrow) * CH + dcol;
        float4 kv4 = *(const float4*)(Kg + off);
        float4 vv4 = *(const float4*)(Vg + off);
        float f0 = fmap(kv4.x), f1 = fmap(kv4.y), f2 = fmap(kv4.z), f3 = fmap(kv4.w);
        ksacc0 += f0; ksacc1 += f1; ksacc2 += f2; ksacc3 += f3;
        Ks[lrow][dcol + 0] = f0; Ks[lrow][dcol + 1] = f1;
        Ks[lrow][dcol + 2] = f2; Ks[lrow][dcol + 3] = f3;
        *(float4*)&Vs[lrow][dcol] = vv4;
        __syncthreads();
#pragma unroll
        for (int kk = 0; kk < 8; kk++) {
            float ra[8], rb[8];
            *(float4*)(ra)     = *(const float4*)&Ks[kk][ty];
            *(float4*)(ra + 4) = *(const float4*)&Ks[kk][ty + 4];
            *(float4*)(rb)     = *(const float4*)&Vs[kk][tx];
            *(float4*)(rb + 4) = *(const float4*)&Vs[kk][tx + 4];
#pragma unroll
            for (int i = 0; i < 8; i++)
#pragma unroll
                for (int j = 0; j < 8; j++)
                    acc[i][j] = fmaf(ra[i], rb[j], acc[i][j]);
        }
        __syncthreads();
    }

    float* o = kvpart + ((size_t)(split * NHT + nh)) * HD * HD;
#pragma unroll
    for (int i = 0; i < 8; i++) {
#pragma unroll
        for (int jv = 0; jv < 2; jv++) {
            float4 w;
            w.x = acc[i][jv * 4 + 0]; w.y = acc[i][jv * 4 + 1];
            w.z = acc[i][jv * 4 + 2]; w.w = acc[i][jv * 4 + 3];
            *(float4*)(o + (ty + i) * HD + tx + jv * 4) = w;
        }
    }

    // deterministic reduction of per-thread sum(K) partials across the 8 l-rows
    ksp[lrow][dcol + 0] = ksacc0; ksp[lrow][dcol + 1] = ksacc1;
    ksp[lrow][dcol + 2] = ksacc2; ksp[lrow][dcol + 3] = ksacc3;
    __syncthreads();
    if (tid < 32) {
#pragma unroll
        for (int c = 0; c < 4; c++) {
            int d = tid * 4 + c;
            float s = 0.0f;
#pragma unroll
            for (int r = 0; r < 8; r++) s += ksp[r][d];
            kspart[(split * NHT + nh) * HD + d] = s;
        }
    }
}

__global__ void kv_reduce_kernel(const float* __restrict__ part, float* __restrict__ kv) {
    int idx = blockIdx.x * 256 + threadIdx.x;
    if (idx < NHT * HD * HD) {
        int nh = idx >> 14;
        int i = idx & 16383;
        float s = 0.0f;
#pragma unroll
        for (int sp = 0; sp < KVSPLIT; sp++)
            s += part[(((size_t)(sp * NHT + nh)) << 14) + i];
        kv[idx] = s;
    }
}

__global__ void ks_reduce_kernel(const float* __restrict__ part, float* __restrict__ ks) {
    int idx = blockIdx.x * 128 + threadIdx.x;  // NHT*HD total
    int nh = idx >> 7, d = idx & 127;
    float s = 0.0f;
#pragma unroll
    for (int sp = 0; sp < KVSPLIT; sp++)
        s += part[(sp * NHT + nh) * HD + d];
    ks[idx] = s;
}

// ---------------- attention out: O = fmap(Q) @ KV, scaled by 1/(fmap(Q)·sumK + eps) ----------------
__global__ __launch_bounds__(256) void attn_out_kernel(
    const float* __restrict__ Qg, const float* __restrict__ KV,
    const float* __restrict__ Ksum, float* __restrict__ Og) {
    const int nh = blockIdx.y;
    const int n = nh >> 3, h = nh & 7;
    const int l0 = blockIdx.x * 128;
    __shared__ float Qs[8][128];  // [d-sub][l]
    __shared__ float Bs[8][128];  // [d-sub][v]
    __shared__ float Kss[8];
    const int tid = threadIdx.x;
    const int tx = (tid & 15) << 3;  // v
    const int ty = (tid >> 4) << 3;  // l
    const int arow = tid >> 1, acol = (tid & 1) << 2;   // l-row, d-off
    const int brow = tid >> 5, bcol = (tid & 31) << 2;  // d-row, v-off
    const size_t qbase = ((size_t)(n * LQ + l0)) * CH + h * HD;
    const float* kvb = KV + (size_t)nh * HD * HD;

    float acc[8][8];
    float qk[8];
#pragma unroll
    for (int i = 0; i < 8; i++) {
        qk[i] = 0.0f;
#pragma unroll
        for (int j = 0; j < 8; j++) acc[i][j] = 0.0f;
    }

    for (int d0 = 0; d0 < HD; d0 += 8) {
        float4 qv = *(const float4*)(Qg + qbase + (size_t)arow * CH + d0 + acol);
        Qs[acol + 0][arow] = fmap(qv.x);
        Qs[acol + 1][arow] = fmap(qv.y);
        Qs[acol + 2][arow] = fmap(qv.z);
        Qs[acol + 3][arow] = fmap(qv.w);
        *(float4*)&Bs[brow][bcol] = *(const float4*)(kvb + (d0 + brow) * HD + bcol);
        if (tid < 8) Kss[tid] = Ksum[nh * HD + d0 + tid];
        __syncthreads();
#pragma unroll
        for (int kk = 0; kk < 8; kk++) {
            float ra[8], rb[8];
            *(float4*)(ra)     = *(const float4*)&Qs[kk][ty];
            *(float4*)(ra + 4) = *(const float4*)&Qs[kk][ty + 4];
            *(float4*)(rb)     = *(const float4*)&Bs[kk][tx];
            *(float4*)(rb + 4) = *(const float4*)&Bs[kk][tx + 4];
            float ksv = Kss[kk];
#pragma unroll
            for (int i = 0; i < 8; i++) {
                qk[i] = fmaf(ra[i], ksv, qk[i]);
#pragma unroll
                for (int j = 0; j < 8; j++)
                    acc[i][j] = fmaf(ra[i], rb[j], acc[i][j]);
            }
        }
        __syncthreads();
    }

#pragma unroll
    for (int i = 0; i < 8; i++) {
        float z = 1.0f / (qk[i] + EPS_ATTN);
        float* op = Og + ((size_t)(n * LQ + l0 + ty + i)) * CH + h * HD + tx;
#pragma unroll
        for (int jv = 0; jv < 2; jv++) {
            float4 w;
            w.x = acc[i][jv * 4 + 0] * z; w.y = acc[i][jv * 4 + 1] * z;
            w.z = acc[i][jv * 4 + 2] * z; w.w = acc[i][jv * 4 + 3] * z;
            *(float4*)(op + jv * 4) = w;
        }
    }
}

// ---------------- fused residual + LayerNorm: out = res + LN(y)*g + b ----------------
__global__ __launch_bounds__(256) void ln_res_kernel(
    const float* __restrict__ res, const float* __restrict__ y,
    const float* __restrict__ g, const float* __restrict__ b,
    float* __restrict__ out) {
    const int row = blockIdx.x;
    const int t = threadIdx.x;
    const size_t off = (size_t)row * CH + t * 4;
    float4 v = *(const float4*)(y + off);
    __shared__ float red[8];
    const int lane = t & 31, w = t >> 5;

    float s = v.x + v.y + v.z + v.w;
#pragma unroll
    for (int o = 16; o; o >>= 1) s += __shfl_xor_sync(0xffffffffu, s, o);
    if (!lane) red[w] = s;
    __syncthreads();
    float tot = red[0];
#pragma unroll
    for (int i = 1; i < 8; i++) tot += red[i];
    const float mean = tot * (1.0f / CH);

    float dx = v.x - mean, dy = v.y - mean, dz = v.z - mean, dw = v.w - mean;
    float sq = dx * dx + dy * dy + dz * dz + dw * dw;
    __syncthreads();
#pragma unroll
    for (int o = 16; o; o >>= 1) sq += __shfl_xor_sync(0xffffffffu, sq, o);
    if (!lane) red[w] = sq;
    __syncthreads();
    float vtot = red[0];
#pragma unroll
    for (int i = 1; i < 8; i++) vtot += red[i];
    const float rstd = rsqrtf(vtot * (1.0f / CH) + EPS_LN);

    float4 gv = *(const float4*)(g + t * 4);
    float4 bv = *(const float4*)(b + t * 4);
    float4 rv = *(const float4*)(res + off);
    float4 o;
    o.x = rv.x + dx * rstd * gv.x + bv.x;
    o.y = rv.y + dy * rstd * gv.y + bv.y;
    o.z = rv.z + dz * rstd * gv.z + bv.z;
    o.w = rv.w + dw * rstd * gv.w + bv.w;
    *(float4*)(out + off) = o;
}

// ---------------- host orchestration ----------------
extern "C" void kernel_launch(void* const* d_in, const int* in_sizes, int n_in,
                              void* d_out, int out_size) {
    const float* depth   = (const float*)d_in[0];
    const float* context = (const float*)d_in[1];
    const float* pos     = (const float*)d_in[2];
    const float* e_wq = (const float*)d_in[3];
    const float* e_wk = (const float*)d_in[4];
    const float* e_wv = (const float*)d_in[5];
    const float* e_wm = (const float*)d_in[6];
    const float* e_w1 = (const float*)d_in[7];
    const float* e_w2 = (const float*)d_in[8];
    const float* e_g1 = (const float*)d_in[9];
    const float* e_b1 = (const float*)d_in[10];
    const float* e_g2 = (const float*)d_in[11];
    const float* e_b2 = (const float*)d_in[12];
    const float* d_wq0 = (const float*)d_in[13];
    const float* d_wk0 = (const float*)d_in[14];
    const float* d_wv0 = (const float*)d_in[15];
    const float* d_wm0 = (const float*)d_in[16];
    const float* d_wq1 = (const float*)d_in[17];
    const float* d_wk1 = (const float*)d_in[18];
    const float* d_wv1 = (const float*)d_in[19];
    const float* d_wm1 = (const float*)d_in[20];
    const float* d_w1 = (const float*)d_in[21];
    const float* d_w2 = (const float*)d_in[22];
    const float* d_g0 = (const float*)d_in[23];
    const float* d_b0 = (const float*)d_in[24];
    const float* d_g1 = (const float*)d_in[25];
    const float* d_b1 = (const float*)d_in[26];
    const float* d_g2 = (const float*)d_in[27];
    const float* d_b2 = (const float*)d_in[28];
    float* out = (float*)d_out;

    float *ctx, *q, *k, *v, *attn, *msg, *x, *yb, *hb, *kvp, *kv, *ksp, *ks;
    cudaGetSymbolAddress((void**)&ctx,  g_ctx);
    cudaGetSymbolAddress((void**)&q,    g_q);
    cudaGetSymbolAddress((void**)&k,    g_k);
    cudaGetSymbolAddress((void**)&v,    g_v);
    cudaGetSymbolAddress((void**)&attn, g_attn);
    cudaGetSymbolAddress((void**)&msg,  g_msg);
    cudaGetSymbolAddress((void**)&x,    g_x);
    cudaGetSymbolAddress((void**)&yb,   g_y);
    cudaGetSymbolAddress((void**)&hb,   g_h);
    cudaGetSymbolAddress((void**)&kvp,  g_kvpart);
    cudaGetSymbolAddress((void**)&kv,   g_kv);
    cudaGetSymbolAddress((void**)&ksp,  g_kspart);
    cudaGetSymbolAddress((void**)&ks,   g_ksum);

    const dim3 blk(256);
    const dim3 gU(CH / 128, NL / 128);       // 1024-wide GEMM
    const dim3 gF1(2 * CH / 128, NL / 128);  // 2048-wide GEMM

    auto attention = [&](const float* qp, const float* kp, const float* vp) {
        attn_kv_kernel<<<dim3(NHT, KVSPLIT), blk>>>(kp, vp, kvp, ksp);
        kv_reduce_kernel<<<(NHT * HD * HD + 255) / 256, blk>>>(kvp, kv);
        ks_reduce_kernel<<<NHT, 128>>>(ksp, ks);
        attn_out_kernel<<<dim3(LQ / 128, NHT), blk>>>(qp, kv, ks, attn);
    };

    // ===== encoder =====
    add_kernel<<<2048, blk>>>(context, pos, ctx, NL * CH / 4);
    sgemm_kernel<false><<<gU, blk>>>(ctx, e_wq, q, NL, CH, CH);
    sgemm_kernel<false><<<gU, blk>>>(ctx, e_wk, k, NL, CH, CH);
    sgemm_kernel<false><<<gU, blk>>>(ctx, e_wv, v, NL, CH, CH);
    attention(q, k, v);
    sgemm_kernel<false><<<gU, blk>>>(attn, e_wm, msg, NL, CH, CH);
    ln_res_kernel<<<NL, blk>>>(ctx, msg, e_g1, e_b1, x);
    sgemm_kernel<true><<<gF1, blk>>>(x, e_w1, hb, NL, CH, 2 * CH);
    sgemm_kernel<false><<<gU, blk>>>(hb, e_w2, msg, NL, 2 * CH, CH);
    ln_res_kernel<<<NL, blk>>>(x, msg, e_g2, e_b2, ctx);  // encoder output in ctx

    // ===== decoder: self-attention =====
    sgemm_kernel<false><<<gU, blk>>>(depth, d_wq0, q, NL, CH, CH);
    sgemm_kernel<false><<<gU, blk>>>(depth, d_wk0, k, NL, CH, CH);
    sgemm_kernel<false><<<gU, blk>>>(depth, d_wv0, v, NL, CH, CH);
    attention(q, k, v);
    sgemm_kernel<false><<<gU, blk>>>(attn, d_wm0, msg, NL, CH, CH);
    ln_res_kernel<<<NL, blk>>>(depth, msg, d_g0, d_b0, x);

    // ===== decoder: cross-attention =====
    sgemm_kernel<false><<<gU, blk>>>(x, d_wq1, q, NL, CH, CH);
    sgemm_kernel<false><<<gU, blk>>>(ctx, d_wk1, k, NL, CH, CH);
    sgemm_kernel<false><<<gU, blk>>>(ctx, d_wv1, v, NL, CH, CH);
    attention(q, k, v);
    sgemm_kernel<false><<<gU, blk>>>(attn, d_wm1, msg, NL, CH, CH);
    ln_res_kernel<<<NL, blk>>>(x, msg, d_g1, d_b1, yb);

    // ===== decoder: FFN =====
    sgemm_kernel<true><<<gF1, blk>>>(yb, d_w1, hb, NL, CH, 2 * CH);
    sgemm_kernel<false><<<gU, blk>>>(hb, d_w2, msg, NL, 2 * CH, CH);
    ln_res_kernel<<<NL, blk>>>(yb, msg, d_g2, d_b2, out);
}

// round 4
// speedup vs baseline: 1.7410x; 1.7410x over previous
#include <cuda_runtime.h>
#include <cstdint>
#include <math.h>

#define NB 4
#define LQ 2048
#define CH 1024
#define NHD 8
#define HD 128
#define NL (NB * LQ)
#define NHT (NB * NHD)
#define KVSPLIT 8
#define EPS_ATTN 1e-6f
#define EPS_LN 1e-5f

#define BKD 16
#define AS_STRIDE 20
#define BS_STRIDE 136

// ---------------- scratch ----------------
__device__ float g_ctx[NL * CH];
__device__ float g_q[NL * CH];
__device__ float g_k[NL * CH];
__device__ float g_v[NL * CH];
__device__ float g_attn[NL * CH];
__device__ float g_msg[NL * CH];
__device__ float g_x[NL * CH];
__device__ float g_y[NL * CH];
__device__ float g_h[NL * 2 * CH];
__device__ float g_kvpart[KVSPLIT * NHT * HD * HD];
__device__ float g_kv[NHT * HD * HD];
__device__ float g_kspart[KVSPLIT * NHT * HD];
__device__ float g_ksum[NHT * HD];

__device__ __forceinline__ float fmap(float x) { return x > 0.0f ? x + 1.0f : expf(x); }

__device__ __forceinline__ uint32_t tf32r(float x) {
    uint32_t u;
    asm("cvt.rna.tf32.f32 %0, %1;" : "=r"(u) : "f"(x));
    return u;
}

__device__ __forceinline__ void mma_tf32(float& d0, float& d1, float& d2, float& d3,
                                         uint32_t a0, uint32_t a1, uint32_t a2, uint32_t a3,
                                         uint32_t b0, uint32_t b1) {
    asm volatile(
        "mma.sync.aligned.m16n8k8.row.col.f32.tf32.tf32.f32 "
        "{%0,%1,%2,%3}, {%4,%5,%6,%7}, {%8,%9}, {%0,%1,%2,%3};"
        : "+f"(d0), "+f"(d1), "+f"(d2), "+f"(d3)
        : "r"(a0), "r"(a1), "r"(a2), "r"(a3), "r"(b0), "r"(b1));
}

// ---------------- tf32 tensor-core GEMM: C[M,Nn] = A[M,K] @ B[K,Nn] ----------------
// CTA 128x128, BK=16, 256 threads, 8 warps (4M x 2N), warp tile 32x64.
template <bool RELU>
__global__ __launch_bounds__(256) void gemm_mma(
    const float* __restrict__ A, const float* __restrict__ B, float* __restrict__ Cm,
    int M, int K, int Nn) {
    __shared__ uint32_t As[2][128 * AS_STRIDE];
    __shared__ uint32_t Bs[2][BKD * BS_STRIDE];

    const int tid = threadIdx.x;
    const int wid = tid >> 5, lane = tid & 31;
    const int bm = blockIdx.y * 128;
    const int bn = blockIdx.x * 128;
    const int wm = (wid & 3) * 32;
    const int wn = (wid >> 2) * 64;
    const int r = lane >> 2, cq = lane & 3;

    // prefetch mappings
    const int ag = (tid & 3) * 4;   // A k-col offset {0,4,8,12}
    const int am = tid >> 2;        // A row 0..63 (+64)
    const int bn4 = (tid & 31) * 4; // B n offset
    const int bk = tid >> 5;        // B k row 0..7 (+8)

    const float* Aptr = A + (size_t)(bm + am) * K + ag;
    const float* Bptr = B + (size_t)bk * Nn + bn + bn4;
    const size_t AstepRow = (size_t)64 * K;
    const size_t BstepRow = (size_t)8 * Nn;

    float acc[2][8][4];
#pragma unroll
    for (int i = 0; i < 2; i++)
#pragma unroll
        for (int j = 0; j < 8; j++)
#pragma unroll
            for (int c = 0; c < 4; c++) acc[i][j][c] = 0.0f;

    float4 pa0, pa1, pb0, pb1;
    pa0 = *(const float4*)(Aptr);
    pa1 = *(const float4*)(Aptr + AstepRow);
    pb0 = *(const float4*)(Bptr);
    pb1 = *(const float4*)(Bptr + BstepRow);

    auto stage = [&](int buf) {
        uint32_t* a0p = &As[buf][am * AS_STRIDE + ag];
        a0p[0] = tf32r(pa0.x); a0p[1] = tf32r(pa0.y); a0p[2] = tf32r(pa0.z); a0p[3] = tf32r(pa0.w);
        uint32_t* a1p = &As[buf][(am + 64) * AS_STRIDE + ag];
        a1p[0] = tf32r(pa1.x); a1p[1] = tf32r(pa1.y); a1p[2] = tf32r(pa1.z); a1p[3] = tf32r(pa1.w);
        uint32_t* b0p = &Bs[buf][bk * BS_STRIDE + bn4];
        b0p[0] = tf32r(pb0.x); b0p[1] = tf32r(pb0.y); b0p[2] = tf32r(pb0.z); b0p[3] = tf32r(pb0.w);
        uint32_t* b1p = &Bs[buf][(bk + 8) * BS_STRIDE + bn4];
        b1p[0] = tf32r(pb1.x); b1p[1] = tf32r(pb1.y); b1p[2] = tf32r(pb1.z); b1p[3] = tf32r(pb1.w);
    };

    stage(0);
    __syncthreads();

    const int KT = K / BKD;
    for (int kt = 0; kt < KT; kt++) {
        const int buf = kt & 1;
        if (kt + 1 < KT) {
            const float* Ap = Aptr + (size_t)(kt + 1) * BKD;
            const float* Bp = Bptr + (size_t)(kt + 1) * BKD * Nn;
            pa0 = *(const float4*)(Ap);
            pa1 = *(const float4*)(Ap + AstepRow);
            pb0 = *(const float4*)(Bp);
            pb1 = *(const float4*)(Bp + BstepRow);
        }

#pragma unroll
        for (int s = 0; s < 2; s++) {
            uint32_t af[2][4];
#pragma unroll
            for (int i = 0; i < 2; i++) {
                const int arow = wm + 16 * i + r;
                const int kc = 8 * s + cq;
                af[i][0] = As[buf][arow * AS_STRIDE + kc];
                af[i][1] = As[buf][(arow + 8) * AS_STRIDE + kc];
                af[i][2] = As[buf][arow * AS_STRIDE + kc + 4];
                af[i][3] = As[buf][(arow + 8) * AS_STRIDE + kc + 4];
            }
            uint32_t bf[8][2];
#pragma unroll
            for (int j = 0; j < 8; j++) {
                const int ncol = wn + 8 * j + r;
                bf[j][0] = Bs[buf][(8 * s + cq) * BS_STRIDE + ncol];
                bf[j][1] = Bs[buf][(8 * s + cq + 4) * BS_STRIDE + ncol];
            }
#pragma unroll
            for (int i = 0; i < 2; i++)
#pragma unroll
                for (int j = 0; j < 8; j++)
                    mma_tf32(acc[i][j][0], acc[i][j][1], acc[i][j][2], acc[i][j][3],
                             af[i][0], af[i][1], af[i][2], af[i][3], bf[j][0], bf[j][1]);
        }

        if (kt + 1 < KT) {
            stage((kt + 1) & 1);
        }
        __syncthreads();
    }

    // epilogue
#pragma unroll
    for (int i = 0; i < 2; i++) {
        const int row0 = bm + wm + 16 * i + r;
#pragma unroll
        for (int j = 0; j < 8; j++) {
            const int col = bn + wn + 8 * j + 2 * cq;
            float2 v0, v1;
            v0.x = acc[i][j][0]; v0.y = acc[i][j][1];
            v1.x = acc[i][j][2]; v1.y = acc[i][j][3];
            if (RELU) {
                v0.x = fmaxf(v0.x, 0.f); v0.y = fmaxf(v0.y, 0.f);
                v1.x = fmaxf(v1.x, 0.f); v1.y = fmaxf(v1.y, 0.f);
            }
            *(float2*)(Cm + (size_t)row0 * Nn + col) = v0;
            *(float2*)(Cm + (size_t)(row0 + 8) * Nn + col) = v1;
        }
    }
}

// ---------------- elementwise add ----------------
__global__ void add_kernel(const float* __restrict__ a, const float* __restrict__ b,
                           float* __restrict__ o, int n4) {
    int idx = blockIdx.x * blockDim.x + threadIdx.x;
    int stride = gridDim.x * blockDim.x;
    const float4* a4 = (const float4*)a;
    const float4* b4 = (const float4*)b;
    float4* o4 = (float4*)o;
    for (int i = idx; i < n4; i += stride) {
        float4 x = a4[i], y = b4[i];
        x.x += y.x; x.y += y.y; x.z += y.z; x.w += y.w;
        o4[i] = x;
    }
}

// ---------------- attention: KV = fmap(K)^T @ V (split over L) + partial sum(K) ----------------
__global__ __launch_bounds__(256) void attn_kv_kernel(
    const float* __restrict__ Kg, const float* __restrict__ Vg,
    float* __restrict__ kvpart, float* __restrict__ kspart) {
    const int nh = blockIdx.x;
    const int split = blockIdx.y;
    const int n = nh >> 3, h = nh & 7;
    const int lbase = split * (LQ / KVSPLIT);
    __shared__ float Ks[8][128];
    __shared__ float Vs[8][128];
    __shared__ float ksp[8][128];
    const int tid = threadIdx.x;
    const int tx = (tid & 15) << 3;
    const int ty = (tid >> 4) << 3;
    const int lrow = tid >> 5;
    const int dcol = (tid & 31) << 2;
    const size_t base = ((size_t)(n * LQ + lbase)) * CH + h * HD;

    float acc[8][8];
#pragma unroll
    for (int i = 0; i < 8; i++)
#pragma unroll
        for (int j = 0; j < 8; j++) acc[i][j] = 0.0f;
    float ks0 = 0.f, ks1 = 0.f, ks2 = 0.f, ks3 = 0.f;

    for (int lt = 0; lt < LQ / KVSPLIT; lt += 8) {
        size_t off = base + (size_t)(lt + lrow) * CH + dcol;
        float4 kv4 = *(const float4*)(Kg + off);
        float4 vv4 = *(const float4*)(Vg + off);
        float f0 = fmap(kv4.x), f1 = fmap(kv4.y), f2 = fmap(kv4.z), f3 = fmap(kv4.w);
        ks0 += f0; ks1 += f1; ks2 += f2; ks3 += f3;
        Ks[lrow][dcol + 0] = f0; Ks[lrow][dcol + 1] = f1;
        Ks[lrow][dcol + 2] = f2; Ks[lrow][dcol + 3] = f3;
        *(float4*)&Vs[lrow][dcol] = vv4;
        __syncthreads();
#pragma unroll
        for (int kk = 0; kk < 8; kk++) {
            float ra[8], rb[8];
            *(float4*)(ra)     = *(const float4*)&Ks[kk][ty];
            *(float4*)(ra + 4) = *(const float4*)&Ks[kk][ty + 4];
            *(float4*)(rb)     = *(const float4*)&Vs[kk][tx];
            *(float4*)(rb + 4) = *(const float4*)&Vs[kk][tx + 4];
#pragma unroll
            for (int i = 0; i < 8; i++)
#pragma unroll
                for (int j = 0; j < 8; j++)
                    acc[i][j] = fmaf(ra[i], rb[j], acc[i][j]);
        }
        __syncthreads();
    }

    float* o = kvpart + ((size_t)(split * NHT + nh)) * HD * HD;
#pragma unroll
    for (int i = 0; i < 8; i++) {
#pragma unroll
        for (int jv = 0; jv < 2; jv++) {
            float4 w;
            w.x = acc[i][jv * 4 + 0]; w.y = acc[i][jv * 4 + 1];
            w.z = acc[i][jv * 4 + 2]; w.w = acc[i][jv * 4 + 3];
            *(float4*)(o + (ty + i) * HD + tx + jv * 4) = w;
        }
    }

    ksp[lrow][dcol + 0] = ks0; ksp[lrow][dcol + 1] = ks1;
    ksp[lrow][dcol + 2] = ks2; ksp[lrow][dcol + 3] = ks3;
    __syncthreads();
    if (tid < 32) {
#pragma unroll
        for (int c = 0; c < 4; c++) {
            int d = tid * 4 + c;
            float s = 0.0f;
#pragma unroll
            for (int rr = 0; rr < 8; rr++) s += ksp[rr][d];
            kspart[(split * NHT + nh) * HD + d] = s;
        }
    }
}

__global__ void kv_reduce_kernel(const float* __restrict__ part, float* __restrict__ kv) {
    int idx = blockIdx.x * 256 + threadIdx.x;
    if (idx < NHT * HD * HD) {
        int nh = idx >> 14;
        int i = idx & 16383;
        float s = 0.0f;
#pragma unroll
        for (int sp = 0; sp < KVSPLIT; sp++)
            s += part[(((size_t)(sp * NHT + nh)) << 14) + i];
        kv[idx] = s;
    }
}

__global__ void ks_reduce_kernel(const float* __restrict__ part, float* __restrict__ ks) {
    int idx = blockIdx.x * 128 + threadIdx.x;
    int nh = idx >> 7, d = idx & 127;
    float s = 0.0f;
#pragma unroll
    for (int sp = 0; sp < KVSPLIT; sp++)
        s += part[(sp * NHT + nh) * HD + d];
    ks[idx] = s;
}

// ---------------- attention out: O = fmap(Q) @ KV, scaled by 1/(fmap(Q)·sumK + eps) ----------------
__global__ __launch_bounds__(256) void attn_out_kernel(
    const float* __restrict__ Qg, const float* __restrict__ KV,
    const float* __restrict__ Ksum, float* __restrict__ Og) {
    const int nh = blockIdx.y;
    const int n = nh >> 3, h = nh & 7;
    const int l0 = blockIdx.x * 128;
    __shared__ float Qs[8][128];
    __shared__ float Bs2[8][128];
    __shared__ float Kss[8];
    const int tid = threadIdx.x;
    const int tx = (tid & 15) << 3;
    const int ty = (tid >> 4) << 3;
    const int arow = tid >> 1, acol = (tid & 1) << 2;
    const int brow = tid >> 5, bcol = (tid & 31) << 2;
    const size_t qbase = ((size_t)(n * LQ + l0)) * CH + h * HD;
    const float* kvb = KV + (size_t)nh * HD * HD;

    float acc[8][8];
    float qk[8];
#pragma unroll
    for (int i = 0; i < 8; i++) {
        qk[i] = 0.0f;
#pragma unroll
        for (int j = 0; j < 8; j++) acc[i][j] = 0.0f;
    }

    for (int d0 = 0; d0 < HD; d0 += 8) {
        float4 qv = *(const float4*)(Qg + qbase + (size_t)arow * CH + d0 + acol);
        Qs[acol + 0][arow] = fmap(qv.x);
        Qs[acol + 1][arow] = fmap(qv.y);
        Qs[acol + 2][arow] = fmap(qv.z);
        Qs[acol + 3][arow] = fmap(qv.w);
        *(float4*)&Bs2[brow][bcol] = *(const float4*)(kvb + (d0 + brow) * HD + bcol);
        if (tid < 8) Kss[tid] = Ksum[nh * HD + d0 + tid];
        __syncthreads();
#pragma unroll
        for (int kk = 0; kk < 8; kk++) {
            float ra[8], rb[8];
            *(float4*)(ra)     = *(const float4*)&Qs[kk][ty];
            *(float4*)(ra + 4) = *(const float4*)&Qs[kk][ty + 4];
            *(float4*)(rb)     = *(const float4*)&Bs2[kk][tx];
            *(float4*)(rb + 4) = *(const float4*)&Bs2[kk][tx + 4];
            float ksv = Kss[kk];
#pragma unroll
            for (int i = 0; i < 8; i++) {
                qk[i] = fmaf(ra[i], ksv, qk[i]);
#pragma unroll
                for (int j = 0; j < 8; j++)
                    acc[i][j] = fmaf(ra[i], rb[j], acc[i][j]);
            }
        }
        __syncthreads();
    }

#pragma unroll
    for (int i = 0; i < 8; i++) {
        float z = 1.0f / (qk[i] + EPS_ATTN);
        float* op = Og + ((size_t)(n * LQ + l0 + ty + i)) * CH + h * HD + tx;
#pragma unroll
        for (int jv = 0; jv < 2; jv++) {
            float4 w;
            w.x = acc[i][jv * 4 + 0] * z; w.y = acc[i][jv * 4 + 1] * z;
            w.z = acc[i][jv * 4 + 2] * z; w.w = acc[i][jv * 4 + 3] * z;
            *(float4*)(op + jv * 4) = w;
        }
    }
}

// ---------------- fused residual + LayerNorm ----------------
__global__ __launch_bounds__(256) void ln_res_kernel(
    const float* __restrict__ res, const float* __restrict__ y,
    const float* __restrict__ g, const float* __restrict__ b,
    float* __restrict__ out) {
    const int row = blockIdx.x;
    const int t = threadIdx.x;
    const size_t off = (size_t)row * CH + t * 4;
    float4 v = *(const float4*)(y + off);
    __shared__ float red[8];
    const int lane = t & 31, w = t >> 5;

    float s = v.x + v.y + v.z + v.w;
#pragma unroll
    for (int o = 16; o; o >>= 1) s += __shfl_xor_sync(0xffffffffu, s, o);
    if (!lane) red[w] = s;
    __syncthreads();
    float tot = red[0];
#pragma unroll
    for (int i = 1; i < 8; i++) tot += red[i];
    const float mean = tot * (1.0f / CH);

    float dx = v.x - mean, dy = v.y - mean, dz = v.z - mean, dw = v.w - mean;
    float sq = dx * dx + dy * dy + dz * dz + dw * dw;
    __syncthreads();
#pragma unroll
    for (int o = 16; o; o >>= 1) sq += __shfl_xor_sync(0xffffffffu, sq, o);
    if (!lane) red[w] = sq;
    __syncthreads();
    float vtot = red[0];
#pragma unroll
    for (int i = 1; i < 8; i++) vtot += red[i];
    const float rstd = rsqrtf(vtot * (1.0f / CH) + EPS_LN);

    float4 gv = *(const float4*)(g + t * 4);
    float4 bv = *(const float4*)(b + t * 4);
    float4 rv = *(const float4*)(res + off);
    float4 o;
    o.x = rv.x + dx * rstd * gv.x + bv.x;
    o.y = rv.y + dy * rstd * gv.y + bv.y;
    o.z = rv.z + dz * rstd * gv.z + bv.z;
    o.w = rv.w + dw * rstd * gv.w + bv.w;
    *(float4*)(out + off) = o;
}

// ---------------- host orchestration ----------------
extern "C" void kernel_launch(void* const* d_in, const int* in_sizes, int n_in,
                              void* d_out, int out_size) {
    const float* depth   = (const float*)d_in[0];
    const float* context = (const float*)d_in[1];
    const float* pos     = (const float*)d_in[2];
    const float* e_wq = (const float*)d_in[3];
    const float* e_wk = (const float*)d_in[4];
    const float* e_wv = (const float*)d_in[5];
    const float* e_wm = (const float*)d_in[6];
    const float* e_w1 = (const float*)d_in[7];
    const float* e_w2 = (const float*)d_in[8];
    const float* e_g1 = (const float*)d_in[9];
    const float* e_b1 = (const float*)d_in[10];
    const float* e_g2 = (const float*)d_in[11];
    const float* e_b2 = (const float*)d_in[12];
    const float* d_wq0 = (const float*)d_in[13];
    const float* d_wk0 = (const float*)d_in[14];
    const float* d_wv0 = (const float*)d_in[15];
    const float* d_wm0 = (const float*)d_in[16];
    const float* d_wq1 = (const float*)d_in[17];
    const float* d_wk1 = (const float*)d_in[18];
    const float* d_wv1 = (const float*)d_in[19];
    const float* d_wm1 = (const float*)d_in[20];
    const float* d_w1 = (const float*)d_in[21];
    const float* d_w2 = (const float*)d_in[22];
    const float* d_g0 = (const float*)d_in[23];
    const float* d_b0 = (const float*)d_in[24];
    const float* d_g1 = (const float*)d_in[25];
    const float* d_b1 = (const float*)d_in[26];
    const float* d_g2 = (const float*)d_in[27];
    const float* d_b2 = (const float*)d_in[28];
    float* out = (float*)d_out;

    float *ctx, *q, *k, *v, *attn, *msg, *x, *yb, *hb, *kvp, *kv, *ksp, *ks;
    cudaGetSymbolAddress((void**)&ctx,  g_ctx);
    cudaGetSymbolAddress((void**)&q,    g_q);
    cudaGetSymbolAddress((void**)&k,    g_k);
    cudaGetSymbolAddress((void**)&v,    g_v);
    cudaGetSymbolAddress((void**)&attn, g_attn);
    cudaGetSymbolAddress((void**)&msg,  g_msg);
    cudaGetSymbolAddress((void**)&x,    g_x);
    cudaGetSymbolAddress((void**)&yb,   g_y);
    cudaGetSymbolAddress((void**)&hb,   g_h);
    cudaGetSymbolAddress((void**)&kvp,  g_kvpart);
    cudaGetSymbolAddress((void**)&kv,   g_kv);
    cudaGetSymbolAddress((void**)&ksp,  g_kspart);
    cudaGetSymbolAddress((void**)&ks,   g_ksum);

    const dim3 blk(256);
    const dim3 gU(CH / 128, NL / 128);        // N=1024
    const dim3 gF(2 * CH / 128, NL / 128);    // N=2048

    auto attention = [&](const float* qp, const float* kp, const float* vp) {
        attn_kv_kernel<<<dim3(NHT, KVSPLIT), blk>>>(kp, vp, kvp, ksp);
        kv_reduce_kernel<<<(NHT * HD * HD + 255) / 256, blk>>>(kvp, kv);
        ks_reduce_kernel<<<NHT, 128>>>(ksp, ks);
        attn_out_kernel<<<dim3(LQ / 128, NHT), blk>>>(qp, kv, ks, attn);
    };

    // ===== encoder =====
    add_kernel<<<2048, blk>>>(context, pos, ctx, NL * CH / 4);
    gemm_mma<false><<<gU, blk>>>(ctx, e_wq, q, NL, CH, CH);
    gemm_mma<false><<<gU, blk>>>(ctx, e_wk, k, NL, CH, CH);
    gemm_mma<false><<<gU, blk>>>(ctx, e_wv, v, NL, CH, CH);
    attention(q, k, v);
    gemm_mma<false><<<gU, blk>>>(attn, e_wm, msg, NL, CH, CH);
    ln_res_kernel<<<NL, blk>>>(ctx, msg, e_g1, e_b1, x);
    gemm_mma<true><<<gF, blk>>>(x, e_w1, hb, NL, CH, 2 * CH);
    gemm_mma<false><<<gU, blk>>>(hb, e_w2, msg, NL, 2 * CH, CH);
    ln_res_kernel<<<NL, blk>>>(x, msg, e_g2, e_b2, ctx);

    // ===== decoder: self-attention =====
    gemm_mma<false><<<gU, blk>>>(depth, d_wq0, q, NL, CH, CH);
    gemm_mma<false><<<gU, blk>>>(depth, d_wk0, k, NL, CH, CH);
    gemm_mma<false><<<gU, blk>>>(depth, d_wv0, v, NL, CH, CH);
    attention(q, k, v);
    gemm_mma<false><<<gU, blk>>>(attn, d_wm0, msg, NL, CH, CH);
    ln_res_kernel<<<NL, blk>>>(depth, msg, d_g0, d_b0, x);

    // ===== decoder: cross-attention =====
    gemm_mma<false><<<gU, blk>>>(x, d_wq1, q, NL, CH, CH);
    gemm_mma<false><<<gU, blk>>>(ctx, d_wk1, k, NL, CH, CH);
    gemm_mma<false><<<gU, blk>>>(ctx, d_wv1, v, NL, CH, CH);
    attention(q, k, v);
    gemm_mma<false><<<gU, blk>>>(attn, d_wm1, msg, NL, CH, CH);
    ln_res_kernel<<<NL, blk>>>(x, msg, d_g1, d_b1, yb);

    // ===== decoder: FFN =====
    gemm_mma<true><<<gF, blk>>>(yb, d_w1, hb, NL, CH, 2 * CH);
    gemm_mma<false><<<gU, blk>>>(hb, d_w2, msg, NL, 2 * CH, CH);
    ln_res_kernel<<<NL, blk>>>(yb, msg, d_g2, d_b2, out);
}

// round 5
// speedup vs baseline: 2.8163x; 1.6177x over previous
#include <cuda_runtime.h>
#include <cstdint>
#include <math.h>

#define NB 4
#define LQ 2048
#define CH 1024
#define NHD 8
#define HD 128
#define NL (NB * LQ)
#define NHT (NB * NHD)
#define KVSPLIT 8
#define EPS_ATTN 1e-6f
#define EPS_LN 1e-5f

#define BKD 16
#define STAGES 3
#define ASTR 20
#define BSTR 136
#define STAGE_WORDS 4736          // A: 128*20=2560 words, B: 16*136=2176 words
#define A_WORDS 2560
#define GEMM_SMEM_BYTES (STAGES * STAGE_WORDS * 4)   // 56832

// ---------------- scratch ----------------
__device__ float g_ctx[NL * CH];
__device__ float g_ctx_r[NL * CH];
__device__ float g_q[NL * CH];
__device__ float g_k[NL * CH];
__device__ float g_v[NL * CH];
__device__ float g_attn[NL * CH];
__device__ float g_msg[NL * CH];
__device__ float g_x[NL * CH];
__device__ float g_x_r[NL * CH];
__device__ float g_y[NL * CH];
__device__ float g_y_r[NL * CH];
__device__ float g_h[NL * 2 * CH];
__device__ float g_depth_r[NL * CH];
__device__ float g_wt[20 * 1024 * 1024];
__device__ float g_kvpart[KVSPLIT * NHT * HD * HD];
__device__ float g_kv[NHT * HD * HD];
__device__ float g_kspart[KVSPLIT * NHT * HD];
__device__ float g_ksum[NHT * HD];

__device__ __forceinline__ float fmap(float x) { return x > 0.0f ? x + 1.0f : expf(x); }

__device__ __forceinline__ float tf32rf(float x) {
    uint32_t u;
    asm("cvt.rna.tf32.f32 %0, %1;" : "=r"(u) : "f"(x));
    return __uint_as_float(u);
}

__device__ __forceinline__ void cp16(uint32_t saddr, const void* g) {
    asm volatile("cp.async.cg.shared.global [%0], [%1], 16;" :: "r"(saddr), "l"(g));
}

__device__ __forceinline__ uint32_t smem_u32(const void* p) {
    uint32_t a;
    asm("{ .reg .u64 t; cvta.to.shared.u64 t, %1; cvt.u32.u64 %0, t; }" : "=r"(a) : "l"(p));
    return a;
}

__device__ __forceinline__ void mma_tf32(float* d,
                                         uint32_t a0, uint32_t a1, uint32_t a2, uint32_t a3,
                                         uint32_t b0, uint32_t b1) {
    asm volatile(
        "mma.sync.aligned.m16n8k8.row.col.f32.tf32.tf32.f32 "
        "{%0,%1,%2,%3}, {%4,%5,%6,%7}, {%8,%9}, {%0,%1,%2,%3};"
        : "+f"(d[0]), "+f"(d[1]), "+f"(d[2]), "+f"(d[3])
        : "r"(a0), "r"(a1), "r"(a2), "r"(a3), "r"(b0), "r"(b1));
}

// ---------------- round-copy: out = rna_tf32(in) ----------------
__global__ void round_copy(const float4* __restrict__ in, float4* __restrict__ out, int n4) {
    int idx = blockIdx.x * blockDim.x + threadIdx.x;
    int stride = gridDim.x * blockDim.x;
    for (int i = idx; i < n4; i += stride) {
        float4 v = in[i];
        v.x = tf32rf(v.x); v.y = tf32rf(v.y); v.z = tf32rf(v.z); v.w = tf32rf(v.w);
        out[i] = v;
    }
}

// ---------------- tf32 tensor-core GEMM (cp.async 3-stage) ----------------
// C[M,Nn] = A[M,K] @ B[K,Nn]; A,B already tf32-rounded. CTA 128x128, 128 thr, warp 64x64.
template <bool RELU, bool ROUND>
__global__ __launch_bounds__(128) void gemm_mma(
    const float* __restrict__ A, const float* __restrict__ B, float* __restrict__ Cm,
    int M, int K, int Nn) {
    extern __shared__ uint32_t sm[];
    const uint32_t smaddr = smem_u32(sm);
    const int tid = threadIdx.x;
    const int wid = tid >> 5, lane = tid & 31;
    const int bm = blockIdx.y * 128;
    const int bn = blockIdx.x * 128;
    const int wm = (wid & 1) * 64;
    const int wn = (wid >> 1) * 64;
    const int r = lane >> 2, cq = lane & 3;

    float acc[4][8][4];
#pragma unroll
    for (int i = 0; i < 4; i++)
#pragma unroll
        for (int j = 0; j < 8; j++)
#pragma unroll
            for (int c = 0; c < 4; c++) acc[i][j][c] = 0.0f;

    const int KT = K / BKD;

    auto issue = [&](int s, int kt) {
        const uint32_t sbA = smaddr + s * (STAGE_WORDS * 4);
        const float* Ag = A + (size_t)bm * K + (size_t)kt * BKD;
#pragma unroll
        for (int i = 0; i < 4; i++) {
            int idx = tid + 128 * i;
            int row = idx >> 2, c4 = (idx & 3) * 4;
            cp16(sbA + (row * ASTR + c4) * 4, Ag + (size_t)row * K + c4);
        }
        const uint32_t sbB = sbA + A_WORDS * 4;
        const float* Bg = B + (size_t)kt * BKD * Nn + bn;
#pragma unroll
        for (int i = 0; i < 4; i++) {
            int idx = tid + 128 * i;
            int kk = idx >> 5, n4 = (idx & 31) * 4;
            cp16(sbB + (kk * BSTR + n4) * 4, Bg + (size_t)kk * Nn + n4);
        }
        asm volatile("cp.async.commit_group;" ::: "memory");
    };

    issue(0, 0);
    issue(1, 1);

    for (int kt = 0; kt < KT; kt++) {
        asm volatile("cp.async.wait_group 1;" ::: "memory");
        __syncthreads();
        if (kt + 2 < KT) issue((kt + 2) % STAGES, kt + 2);

        const uint32_t* Asb = sm + (kt % STAGES) * STAGE_WORDS;
        const uint32_t* Bsb = Asb + A_WORDS;
#pragma unroll
        for (int s = 0; s < 2; s++) {
            uint32_t af[4][4];
#pragma unroll
            for (int i = 0; i < 4; i++) {
                const int arow = wm + 16 * i + r;
                const int kc = 8 * s + cq;
                af[i][0] = Asb[arow * ASTR + kc];
                af[i][1] = Asb[(arow + 8) * ASTR + kc];
                af[i][2] = Asb[arow * ASTR + kc + 4];
                af[i][3] = Asb[(arow + 8) * ASTR + kc + 4];
            }
            uint32_t bf[8][2];
#pragma unroll
            for (int j = 0; j < 8; j++) {
                const int ncol = wn + 8 * j + r;
                bf[j][0] = Bsb[(8 * s + cq) * BSTR + ncol];
                bf[j][1] = Bsb[(8 * s + cq + 4) * BSTR + ncol];
            }
#pragma unroll
            for (int i = 0; i < 4; i++)
#pragma unroll
                for (int j = 0; j < 8; j++)
                    mma_tf32(acc[i][j], af[i][0], af[i][1], af[i][2], af[i][3],
                             bf[j][0], bf[j][1]);
        }
    }

    // epilogue
#pragma unroll
    for (int i = 0; i < 4; i++) {
        const int row0 = bm + wm + 16 * i + r;
#pragma unroll
        for (int j = 0; j < 8; j++) {
            const int col = bn + wn + 8 * j + 2 * cq;
            float2 v0, v1;
            v0.x = acc[i][j][0]; v0.y = acc[i][j][1];
            v1.x = acc[i][j][2]; v1.y = acc[i][j][3];
            if (RELU) {
                v0.x = fmaxf(v0.x, 0.f); v0.y = fmaxf(v0.y, 0.f);
                v1.x = fmaxf(v1.x, 0.f); v1.y = fmaxf(v1.y, 0.f);
            }
            if (ROUND) {
                v0.x = tf32rf(v0.x); v0.y = tf32rf(v0.y);
                v1.x = tf32rf(v1.x); v1.y = tf32rf(v1.y);
            }
            *(float2*)(Cm + (size_t)row0 * Nn + col) = v0;
            *(float2*)(Cm + (size_t)(row0 + 8) * Nn + col) = v1;
        }
    }
}

// ---------------- elementwise add (+ rounded copy) ----------------
__global__ void add_kernel(const float* __restrict__ a, const float* __restrict__ b,
                           float* __restrict__ o, float* __restrict__ o_r, int n4) {
    int idx = blockIdx.x * blockDim.x + threadIdx.x;
    int stride = gridDim.x * blockDim.x;
    const float4* a4 = (const float4*)a;
    const float4* b4 = (const float4*)b;
    float4* o4 = (float4*)o;
    float4* r4 = (float4*)o_r;
    for (int i = idx; i < n4; i += stride) {
        float4 x = a4[i], y = b4[i];
        x.x += y.x; x.y += y.y; x.z += y.z; x.w += y.w;
        o4[i] = x;
        float4 rr;
        rr.x = tf32rf(x.x); rr.y = tf32rf(x.y); rr.z = tf32rf(x.z); rr.w = tf32rf(x.w);
        r4[i] = rr;
    }
}

// ---------------- attention: KV = fmap(K)^T @ V (split over L) + partial sum(K) ----------------
__global__ __launch_bounds__(256) void attn_kv_kernel(
    const float* __restrict__ Kg, const float* __restrict__ Vg,
    float* __restrict__ kvpart, float* __restrict__ kspart) {
    const int nh = blockIdx.x;
    const int split = blockIdx.y;
    const int n = nh >> 3, h = nh & 7;
    const int lbase = split * (LQ / KVSPLIT);
    __shared__ float Ks[8][128];
    __shared__ float Vs[8][128];
    __shared__ float ksp[8][128];
    const int tid = threadIdx.x;
    const int tx = (tid & 15) << 3;
    const int ty = (tid >> 4) << 3;
    const int lrow = tid >> 5;
    const int dcol = (tid & 31) << 2;
    const size_t base = ((size_t)(n * LQ + lbase)) * CH + h * HD;

    float acc[8][8];
#pragma unroll
    for (int i = 0; i < 8; i++)
#pragma unroll
        for (int j = 0; j < 8; j++) acc[i][j] = 0.0f;
    float ks0 = 0.f, ks1 = 0.f, ks2 = 0.f, ks3 = 0.f;

    for (int lt = 0; lt < LQ / KVSPLIT; lt += 8) {
        size_t off = base + (size_t)(lt + lrow) * CH + dcol;
        float4 kv4 = *(const float4*)(Kg + off);
        float4 vv4 = *(const float4*)(Vg + off);
        float f0 = fmap(kv4.x), f1 = fmap(kv4.y), f2 = fmap(kv4.z), f3 = fmap(kv4.w);
        ks0 += f0; ks1 += f1; ks2 += f2; ks3 += f3;
        Ks[lrow][dcol + 0] = f0; Ks[lrow][dcol + 1] = f1;
        Ks[lrow][dcol + 2] = f2; Ks[lrow][dcol + 3] = f3;
        *(float4*)&Vs[lrow][dcol] = vv4;
        __syncthreads();
#pragma unroll
        for (int kk = 0; kk < 8; kk++) {
            float ra[8], rb[8];
            *(float4*)(ra)     = *(const float4*)&Ks[kk][ty];
            *(float4*)(ra + 4) = *(const float4*)&Ks[kk][ty + 4];
            *(float4*)(rb)     = *(const float4*)&Vs[kk][tx];
            *(float4*)(rb + 4) = *(const float4*)&Vs[kk][tx + 4];
#pragma unroll
            for (int i = 0; i < 8; i++)
#pragma unroll
                for (int j = 0; j < 8; j++)
                    acc[i][j] = fmaf(ra[i], rb[j], acc[i][j]);
        }
        __syncthreads();
    }

    float* o = kvpart + ((size_t)(split * NHT + nh)) * HD * HD;
#pragma unroll
    for (int i = 0; i < 8; i++) {
#pragma unroll
        for (int jv = 0; jv < 2; jv++) {
            float4 w;
            w.x = acc[i][jv * 4 + 0]; w.y = acc[i][jv * 4 + 1];
            w.z = acc[i][jv * 4 + 2]; w.w = acc[i][jv * 4 + 3];
            *(float4*)(o + (ty + i) * HD + tx + jv * 4) = w;
        }
    }

    ksp[lrow][dcol + 0] = ks0; ksp[lrow][dcol + 1] = ks1;
    ksp[lrow][dcol + 2] = ks2; ksp[lrow][dcol + 3] = ks3;
    __syncthreads();
    if (tid < 32) {
#pragma unroll
        for (int c = 0; c < 4; c++) {
            int d = tid * 4 + c;
            float s = 0.0f;
#pragma unroll
            for (int rr = 0; rr < 8; rr++) s += ksp[rr][d];
            kspart[(split * NHT + nh) * HD + d] = s;
        }
    }
}

__global__ void kv_reduce_kernel(const float* __restrict__ part, float* __restrict__ kv) {
    int idx = blockIdx.x * 256 + threadIdx.x;
    if (idx < NHT * HD * HD) {
        int nh = idx >> 14;
        int i = idx & 16383;
        float s = 0.0f;
#pragma unroll
        for (int sp = 0; sp < KVSPLIT; sp++)
            s += part[(((size_t)(sp * NHT + nh)) << 14) + i];
        kv[idx] = s;
    }
}

__global__ void ks_reduce_kernel(const float* __restrict__ part, float* __restrict__ ks) {
    int idx = blockIdx.x * 128 + threadIdx.x;
    int nh = idx >> 7, d = idx & 127;
    float s = 0.0f;
#pragma unroll
    for (int sp = 0; sp < KVSPLIT; sp++)
        s += part[(sp * NHT + nh) * HD + d];
    ks[idx] = s;
}

// ---------------- attention out (tf32-rounded output; feeds GEMM only) ----------------
__global__ __launch_bounds__(256) void attn_out_kernel(
    const float* __restrict__ Qg, const float* __restrict__ KV,
    const float* __restrict__ Ksum, float* __restrict__ Og) {
    const int nh = blockIdx.y;
    const int n = nh >> 3, h = nh & 7;
    const int l0 = blockIdx.x * 128;
    __shared__ float Qs[8][128];
    __shared__ float Bs2[8][128];
    __shared__ float Kss[8];
    const int tid = threadIdx.x;
    const int tx = (tid & 15) << 3;
    const int ty = (tid >> 4) << 3;
    const int arow = tid >> 1, acol = (tid & 1) << 2;
    const int brow = tid >> 5, bcol = (tid & 31) << 2;
    const size_t qbase = ((size_t)(n * LQ + l0)) * CH + h * HD;
    const float* kvb = KV + (size_t)nh * HD * HD;

    float acc[8][8];
    float qk[8];
#pragma unroll
    for (int i = 0; i < 8; i++) {
        qk[i] = 0.0f;
#pragma unroll
        for (int j = 0; j < 8; j++) acc[i][j] = 0.0f;
    }

    for (int d0 = 0; d0 < HD; d0 += 8) {
        float4 qv = *(const float4*)(Qg + qbase + (size_t)arow * CH + d0 + acol);
        Qs[acol + 0][arow] = fmap(qv.x);
        Qs[acol + 1][arow] = fmap(qv.y);
        Qs[acol + 2][arow] = fmap(qv.z);
        Qs[acol + 3][arow] = fmap(qv.w);
        *(float4*)&Bs2[brow][bcol] = *(const float4*)(kvb + (d0 + brow) * HD + bcol);
        if (tid < 8) Kss[tid] = Ksum[nh * HD + d0 + tid];
        __syncthreads();
#pragma unroll
        for (int kk = 0; kk < 8; kk++) {
            float ra[8], rb[8];
            *(float4*)(ra)     = *(const float4*)&Qs[kk][ty];
            *(float4*)(ra + 4) = *(const float4*)&Qs[kk][ty + 4];
            *(float4*)(rb)     = *(const float4*)&Bs2[kk][tx];
            *(float4*)(rb + 4) = *(const float4*)&Bs2[kk][tx + 4];
            float ksv = Kss[kk];
#pragma unroll
            for (int i = 0; i < 8; i++) {
                qk[i] = fmaf(ra[i], ksv, qk[i]);
#pragma unroll
                for (int j = 0; j < 8; j++)
                    acc[i][j] = fmaf(ra[i], rb[j], acc[i][j]);
            }
        }
        __syncthreads();
    }

#pragma unroll
    for (int i = 0; i < 8; i++) {
        float z = 1.0f / (qk[i] + EPS_ATTN);
        float* op = Og + ((size_t)(n * LQ + l0 + ty + i)) * CH + h * HD + tx;
#pragma unroll
        for (int jv = 0; jv < 2; jv++) {
            float4 w;
            w.x = tf32rf(acc[i][jv * 4 + 0] * z); w.y = tf32rf(acc[i][jv * 4 + 1] * z);
            w.z = tf32rf(acc[i][jv * 4 + 2] * z); w.w = tf32rf(acc[i][jv * 4 + 3] * z);
            *(float4*)(op + jv * 4) = w;
        }
    }
}

// ---------------- fused residual + LayerNorm (+ optional rounded copy) ----------------
__global__ __launch_bounds__(256) void ln_res_kernel(
    const float* __restrict__ res, const float* __restrict__ y,
    const float* __restrict__ g, const float* __restrict__ b,
    float* __restrict__ out, float* __restrict__ out_r) {
    const int row = blockIdx.x;
    const int t = threadIdx.x;
    const size_t off = (size_t)row * CH + t * 4;
    float4 v = *(const float4*)(y + off);
    __shared__ float red[8];
    const int lane = t & 31, w = t >> 5;

    float s = v.x + v.y + v.z + v.w;
#pragma unroll
    for (int o = 16; o; o >>= 1) s += __shfl_xor_sync(0xffffffffu, s, o);
    if (!lane) red[w] = s;
    __syncthreads();
    float tot = red[0];
#pragma unroll
    for (int i = 1; i < 8; i++) tot += red[i];
    const float mean = tot * (1.0f / CH);

    float dx = v.x - mean, dy = v.y - mean, dz = v.z - mean, dw = v.w - mean;
    float sq = dx * dx + dy * dy + dz * dz + dw * dw;
    __syncthreads();
#pragma unroll
    for (int o = 16; o; o >>= 1) sq += __shfl_xor_sync(0xffffffffu, sq, o);
    if (!lane) red[w] = sq;
    __syncthreads();
    float vtot = red[0];
#pragma unroll
    for (int i = 1; i < 8; i++) vtot += red[i];
    const float rstd = rsqrtf(vtot * (1.0f / CH) + EPS_LN);

    float4 gv = *(const float4*)(g + t * 4);
    float4 bv = *(const float4*)(b + t * 4);
    float4 rv = *(const float4*)(res + off);
    float4 o;
    o.x = rv.x + dx * rstd * gv.x + bv.x;
    o.y = rv.y + dy * rstd * gv.y + bv.y;
    o.z = rv.z + dz * rstd * gv.z + bv.z;
    o.w = rv.w + dw * rstd * gv.w + bv.w;
    *(float4*)(out + off) = o;
    if (out_r) {
        float4 rr;
        rr.x = tf32rf(o.x); rr.y = tf32rf(o.y); rr.z = tf32rf(o.z); rr.w = tf32rf(o.w);
        *(float4*)(out_r + off) = rr;
    }
}

// ---------------- host orchestration ----------------
extern "C" void kernel_launch(void* const* d_in, const int* in_sizes, int n_in,
                              void* d_out, int out_size) {
    const float* depth   = (const float*)d_in[0];
    const float* context = (const float*)d_in[1];
    const float* pos     = (const float*)d_in[2];
    const float* wsrc[16] = {
        (const float*)d_in[3],  (const float*)d_in[4],  (const float*)d_in[5],
        (const float*)d_in[6],                                                  // e_wq..e_wm
        (const float*)d_in[13], (const float*)d_in[14], (const float*)d_in[15],
        (const float*)d_in[16],                                                 // d_wq0..d_wm0
        (const float*)d_in[17], (const float*)d_in[18], (const float*)d_in[19],
        (const float*)d_in[20],                                                 // d_wq1..d_wm1
        (const float*)d_in[7],  (const float*)d_in[21],                         // e_w1, d_w1 (2M)
        (const float*)d_in[8],  (const float*)d_in[22]                          // e_w2, d_w2 (2M)
    };
    const float* e_g1 = (const float*)d_in[9];
    const float* e_b1 = (const float*)d_in[10];
    const float* e_g2 = (const float*)d_in[11];
    const float* e_b2 = (const float*)d_in[12];
    const float* d_g0 = (const float*)d_in[23];
    const float* d_b0 = (const float*)d_in[24];
    const float* d_g1 = (const float*)d_in[25];
    const float* d_b1 = (const float*)d_in[26];
    const float* d_g2 = (const float*)d_in[27];
    const float* d_b2 = (const float*)d_in[28];
    float* out = (float*)d_out;

    float *ctx, *ctxr, *q, *k, *v, *attn, *msg, *x, *xr, *yb, *ybr, *hb;
    float *depr, *wt, *kvp, *kv, *ksp, *ks;
    cudaGetSymbolAddress((void**)&ctx,  g_ctx);
    cudaGetSymbolAddress((void**)&ctxr, g_ctx_r);
    cudaGetSymbolAddress((void**)&q,    g_q);
    cudaGetSymbolAddress((void**)&k,    g_k);
    cudaGetSymbolAddress((void**)&v,    g_v);
    cudaGetSymbolAddress((void**)&attn, g_attn);
    cudaGetSymbolAddress((void**)&msg,  g_msg);
    cudaGetSymbolAddress((void**)&x,    g_x);
    cudaGetSymbolAddress((void**)&xr,   g_x_r);
    cudaGetSymbolAddress((void**)&yb,   g_y);
    cudaGetSymbolAddress((void**)&ybr,  g_y_r);
    cudaGetSymbolAddress((void**)&hb,   g_h);
    cudaGetSymbolAddress((void**)&depr, g_depth_r);
    cudaGetSymbolAddress((void**)&wt,   g_wt);
    cudaGetSymbolAddress((void**)&kvp,  g_kvpart);
    cudaGetSymbolAddress((void**)&kv,   g_kv);
    cudaGetSymbolAddress((void**)&ksp,  g_kspart);
    cudaGetSymbolAddress((void**)&ks,   g_ksum);

    cudaFuncSetAttribute(gemm_mma<false, false>, cudaFuncAttributeMaxDynamicSharedMemorySize, GEMM_SMEM_BYTES);
    cudaFuncSetAttribute(gemm_mma<true, true>,   cudaFuncAttributeMaxDynamicSharedMemorySize, GEMM_SMEM_BYTES);

    // rounded weights: 12 square (1M) then 4 rect (2M)
    const size_t MSQ = 1024 * 1024;
    float* wr[16];
    for (int i = 0; i < 12; i++) wr[i] = wt + i * MSQ;
    for (int i = 0; i < 4; i++)  wr[12 + i] = wt + 12 * MSQ + i * 2 * MSQ;
    const int wn4[16] = {
        (int)(MSQ / 4), (int)(MSQ / 4), (int)(MSQ / 4), (int)(MSQ / 4),
        (int)(MSQ / 4), (int)(MSQ / 4), (int)(MSQ / 4), (int)(MSQ / 4),
        (int)(MSQ / 4), (int)(MSQ / 4), (int)(MSQ / 4), (int)(MSQ / 4),
        (int)(MSQ / 2), (int)(MSQ / 2), (int)(MSQ / 2), (int)(MSQ / 2)
    };
    for (int i = 0; i < 16; i++)
        round_copy<<<512, 256>>>((const float4*)wsrc[i], (float4*)wr[i], wn4[i]);
    round_copy<<<1024, 256>>>((const float4*)depth, (float4*)depr, NL * CH / 4);

    // rounded weight aliases
    float *t_ewq = wr[0], *t_ewk = wr[1], *t_ewv = wr[2], *t_ewm = wr[3];
    float *t_dwq0 = wr[4], *t_dwk0 = wr[5], *t_dwv0 = wr[6], *t_dwm0 = wr[7];
    float *t_dwq1 = wr[8], *t_dwk1 = wr[9], *t_dwv1 = wr[10], *t_dwm1 = wr[11];
    float *t_ew1 = wr[12], *t_dw1 = wr[13], *t_ew2 = wr[14], *t_dw2 = wr[15];

    const dim3 blk(256);
    const dim3 gblk(128);
    const dim3 gU(CH / 128, NL / 128);        // N=1024
    const dim3 gF(2 * CH / 128, NL / 128);    // N=2048

    auto attention = [&](const float* qp, const float* kp, const float* vp) {
        attn_kv_kernel<<<dim3(NHT, KVSPLIT), blk>>>(kp, vp, kvp, ksp);
        kv_reduce_kernel<<<(NHT * HD * HD + 255) / 256, blk>>>(kvp, kv);
        ks_reduce_kernel<<<NHT, 128>>>(ksp, ks);
        attn_out_kernel<<<dim3(LQ / 128, NHT), blk>>>(qp, kv, ks, attn);
    };

    // ===== encoder =====
    add_kernel<<<2048, blk>>>(context, pos, ctx, ctxr, NL * CH / 4);
    gemm_mma<false, false><<<gU, gblk, GEMM_SMEM_BYTES>>>(ctxr, t_ewq, q, NL, CH, CH);
    gemm_mma<false, false><<<gU, gblk, GEMM_SMEM_BYTES>>>(ctxr, t_ewk, k, NL, CH, CH);
    gemm_mma<false, false><<<gU, gblk, GEMM_SMEM_BYTES>>>(ctxr, t_ewv, v, NL, CH, CH);
    attention(q, k, v);
    gemm_mma<false, false><<<gU, gblk, GEMM_SMEM_BYTES>>>(attn, t_ewm, msg, NL, CH, CH);
    ln_res_kernel<<<NL, blk>>>(ctx, msg, e_g1, e_b1, x, xr);
    gemm_mma<true, true><<<gF, gblk, GEMM_SMEM_BYTES>>>(xr, t_ew1, hb, NL, CH, 2 * CH);
    gemm_mma<false, false><<<gU, gblk, GEMM_SMEM_BYTES>>>(hb, t_ew2, msg, NL, 2 * CH, CH);
    ln_res_kernel<<<NL, blk>>>(x, msg, e_g2, e_b2, ctx, ctxr);

    // ===== decoder: self-attention =====
    gemm_mma<false, false><<<gU, gblk, GEMM_SMEM_BYTES>>>(depr, t_dwq0, q, NL, CH, CH);
    gemm_mma<false, false><<<gU, gblk, GEMM_SMEM_BYTES>>>(depr, t_dwk0, k, NL, CH, CH);
    gemm_mma<false, false><<<gU, gblk, GEMM_SMEM_BYTES>>>(depr, t_dwv0, v, NL, CH, CH);
    attention(q, k, v);
    gemm_mma<false, false><<<gU, gblk, GEMM_SMEM_BYTES>>>(attn, t_dwm0, msg, NL, CH, CH);
    ln_res_kernel<<<NL, blk>>>(depth, msg, d_g0, d_b0, x, xr);

    // ===== decoder: cross-attention =====
    gemm_mma<false, false><<<gU, gblk, GEMM_SMEM_BYTES>>>(xr, t_dwq1, q, NL, CH, CH);
    gemm_mma<false, false><<<gU, gblk, GEMM_SMEM_BYTES>>>(ctxr, t_dwk1, k, NL, CH, CH);
    gemm_mma<false, false><<<gU, gblk, GEMM_SMEM_BYTES>>>(ctxr, t_dwv1, v, NL, CH, CH);
    attention(q, k, v);
    gemm_mma<false, false><<<gU, gblk, GEMM_SMEM_BYTES>>>(attn, t_dwm1, msg, NL, CH, CH);
    ln_res_kernel<<<NL, blk>>>(x, msg, d_g1, d_b1, yb, ybr);

    // ===== decoder: FFN =====
    gemm_mma<true, true><<<gF, gblk, GEMM_SMEM_BYTES>>>(ybr, t_dw1, hb, NL, CH, 2 * CH);
    gemm_mma<false, false><<<gU, gblk, GEMM_SMEM_BYTES>>>(hb, t_dw2, msg, NL, 2 * CH, CH);
    ln_res_kernel<<<NL, blk>>>(yb, msg, d_g2, d_b2, out, nullptr);
}

// round 8
// speedup vs baseline: 3.0593x; 1.0863x over previous
#include <cuda_runtime.h>
#include <cstdint>
#include <math.h>

#define NB 4
#define LQ 2048
#define CH 1024
#define NHD 8
#define HD 128
#define NL (NB * LQ)
#define NHT (NB * NHD)
#define KVSPLIT 8
#define EPS_ATTN 1e-6f
#define EPS_LN 1e-5f

#define BKD 16
#define STAGES 3
#define ASTR 20
#define BSTR 136
#define KV_ASTR 17
#define STAGE_WORDS 4736
#define A_WORDS 2560
#define GEMM_SMEM_BYTES (STAGES * STAGE_WORDS * 4)

// ---------------- scratch ----------------
__device__ float g_ctx[NL * CH];
__device__ float g_ctx_r[NL * CH];
__device__ float g_q[NL * CH];
__device__ float g_k[NL * CH];
__device__ float g_v[NL * CH];
__device__ float g_attn[NL * CH];
__device__ float g_msg[NL * CH];
__device__ float g_x[NL * CH];
__device__ float g_x_r[NL * CH];
__device__ float g_y[NL * CH];
__device__ float g_y_r[NL * CH];
__device__ float g_h[NL * 2 * CH];
__device__ float g_depth_r[NL * CH];
__device__ float g_wt[20 * 1024 * 1024];
__device__ float g_kvpart[KVSPLIT * NHT * HD * HD];
__device__ float g_kv[NHT * HD * HD];
__device__ float g_kspart[KVSPLIT * NHT * HD];
__device__ float g_ksum[NHT * HD];

__device__ __forceinline__ float fmap(float x) { return x > 0.0f ? x + 1.0f : expf(x); }

__device__ __forceinline__ float tf32rf(float x) {
    uint32_t u;
    asm("cvt.rna.tf32.f32 %0, %1;" : "=r"(u) : "f"(x));
    return __uint_as_float(u);
}

__device__ __forceinline__ void cp16(uint32_t saddr, const void* g) {
    asm volatile("cp.async.cg.shared.global [%0], [%1], 16;" :: "r"(saddr), "l"(g));
}

__device__ __forceinline__ uint32_t smem_u32(const void* p) {
    uint32_t a;
    asm("{ .reg .u64 t; cvta.to.shared.u64 t, %1; cvt.u32.u64 %0, t; }" : "=r"(a) : "l"(p));
    return a;
}

__device__ __forceinline__ void mma_tf32(float* d,
                                         uint32_t a0, uint32_t a1, uint32_t a2, uint32_t a3,
                                         uint32_t b0, uint32_t b1) {
    asm volatile(
        "mma.sync.aligned.m16n8k8.row.col.f32.tf32.tf32.f32 "
        "{%0,%1,%2,%3}, {%4,%5,%6,%7}, {%8,%9}, {%0,%1,%2,%3};"
        : "+f"(d[0]), "+f"(d[1]), "+f"(d[2]), "+f"(d[3])
        : "r"(a0), "r"(a1), "r"(a2), "r"(a3), "r"(b0), "r"(b1));
}

// ---------------- merged round-copy (17 segments in one launch) ----------------
struct RCArgs {
    const float4* src[17];
    float4* dst[17];
    int n4[17];
};
__global__ void round_copy_multi(RCArgs a) {
    const int seg = blockIdx.y;
    const float4* __restrict__ in = a.src[seg];
    float4* __restrict__ out = a.dst[seg];
    const int n4 = a.n4[seg];
    int idx = blockIdx.x * blockDim.x + threadIdx.x;
    int stride = gridDim.x * blockDim.x;
    for (int i = idx; i < n4; i += stride) {
        float4 v = in[i];
        v.x = tf32rf(v.x); v.y = tf32rf(v.y); v.z = tf32rf(v.z); v.w = tf32rf(v.w);
        out[i] = v;
    }
}

// ---------------- tf32 tensor-core GEMM (cp.async 3-stage) ----------------
template <bool RELU, bool ROUND>
__global__ __launch_bounds__(128) void gemm_mma(
    const float* __restrict__ A, const float* __restrict__ B, float* __restrict__ Cm,
    int M, int K, int Nn) {
    extern __shared__ uint32_t sm[];
    const uint32_t smaddr = smem_u32(sm);
    const int tid = threadIdx.x;
    const int wid = tid >> 5, lane = tid & 31;
    const int bm = blockIdx.y * 128;
    const int bn = blockIdx.x * 128;
    const int wm = (wid & 1) * 64;
    const int wn = (wid >> 1) * 64;
    const int r = lane >> 2, cq = lane & 3;

    float acc[4][8][4];
#pragma unroll
    for (int i = 0; i < 4; i++)
#pragma unroll
        for (int j = 0; j < 8; j++)
#pragma unroll
            for (int c = 0; c < 4; c++) acc[i][j][c] = 0.0f;

    const int KT = K / BKD;

    auto issue = [&](int s, int kt) {
        const uint32_t sbA = smaddr + s * (STAGE_WORDS * 4);
        const float* Ag = A + (size_t)bm * K + (size_t)kt * BKD;
#pragma unroll
        for (int i = 0; i < 4; i++) {
            int idx = tid + 128 * i;
            int row = idx >> 2, c4 = (idx & 3) * 4;
            cp16(sbA + (row * ASTR + c4) * 4, Ag + (size_t)row * K + c4);
        }
        const uint32_t sbB = sbA + A_WORDS * 4;
        const float* Bg = B + (size_t)kt * BKD * Nn + bn;
#pragma unroll
        for (int i = 0; i < 4; i++) {
            int idx = tid + 128 * i;
            int kk = idx >> 5, n4 = (idx & 31) * 4;
            cp16(sbB + (kk * BSTR + n4) * 4, Bg + (size_t)kk * Nn + n4);
        }
        asm volatile("cp.async.commit_group;" ::: "memory");
    };

    issue(0, 0);
    issue(1, 1);

    for (int kt = 0; kt < KT; kt++) {
        asm volatile("cp.async.wait_group 1;" ::: "memory");
        __syncthreads();
        if (kt + 2 < KT) issue((kt + 2) % STAGES, kt + 2);

        const uint32_t* Asb = sm + (kt % STAGES) * STAGE_WORDS;
        const uint32_t* Bsb = Asb + A_WORDS;
#pragma unroll
        for (int s = 0; s < 2; s++) {
            uint32_t af[4][4];
#pragma unroll
            for (int i = 0; i < 4; i++) {
                const int arow = wm + 16 * i + r;
                const int kc = 8 * s + cq;
                af[i][0] = Asb[arow * ASTR + kc];
                af[i][1] = Asb[(arow + 8) * ASTR + kc];
                af[i][2] = Asb[arow * ASTR + kc + 4];
                af[i][3] = Asb[(arow + 8) * ASTR + kc + 4];
            }
            uint32_t bf[8][2];
#pragma unroll
            for (int j = 0; j < 8; j++) {
                const int ncol = wn + 8 * j + r;
                bf[j][0] = Bsb[(8 * s + cq) * BSTR + ncol];
                bf[j][1] = Bsb[(8 * s + cq + 4) * BSTR + ncol];
            }
#pragma unroll
            for (int i = 0; i < 4; i++)
#pragma unroll
                for (int j = 0; j < 8; j++)
                    mma_tf32(acc[i][j], af[i][0], af[i][1], af[i][2], af[i][3],
                             bf[j][0], bf[j][1]);
        }
    }

#pragma unroll
    for (int i = 0; i < 4; i++) {
        const int row0 = bm + wm + 16 * i + r;
#pragma unroll
        for (int j = 0; j < 8; j++) {
            const int col = bn + wn + 8 * j + 2 * cq;
            float2 v0, v1;
            v0.x = acc[i][j][0]; v0.y = acc[i][j][1];
            v1.x = acc[i][j][2]; v1.y = acc[i][j][3];
            if (RELU) {
                v0.x = fmaxf(v0.x, 0.f); v0.y = fmaxf(v0.y, 0.f);
                v1.x = fmaxf(v1.x, 0.f); v1.y = fmaxf(v1.y, 0.f);
            }
            if (ROUND) {
                v0.x = tf32rf(v0.x); v0.y = tf32rf(v0.y);
                v1.x = tf32rf(v1.x); v1.y = tf32rf(v1.y);
            }
            *(float2*)(Cm + (size_t)row0 * Nn + col) = v0;
            *(float2*)(Cm + (size_t)(row0 + 8) * Nn + col) = v1;
        }
    }
}

// ---------------- elementwise add (+ rounded copy) ----------------
__global__ void add_kernel(const float* __restrict__ a, const float* __restrict__ b,
                           float* __restrict__ o, float* __restrict__ o_r, int n4) {
    int idx = blockIdx.x * blockDim.x + threadIdx.x;
    int stride = gridDim.x * blockDim.x;
    const float4* a4 = (const float4*)a;
    const float4* b4 = (const float4*)b;
    float4* o4 = (float4*)o;
    float4* r4 = (float4*)o_r;
    for (int i = idx; i < n4; i += stride) {
        float4 x = a4[i], y = b4[i];
        x.x += y.x; x.y += y.y; x.z += y.z; x.w += y.w;
        o4[i] = x;
        float4 rr;
        rr.x = tf32rf(x.x); rr.y = tf32rf(x.y); rr.z = tf32rf(x.z); rr.w = tf32rf(x.w);
        r4[i] = rr;
    }
}

// ---------------- tensor-core attn KV: KV = fmap(K)^T @ V over L-slice + ksum ----------------
__global__ __launch_bounds__(128) void attn_kv_tc(
    const float* __restrict__ Kg, const float* __restrict__ Vg,
    float* __restrict__ kvpart, float* __restrict__ kspart) {
    __shared__ uint32_t Kt[2][128 * KV_ASTR];
    __shared__ uint32_t Vs[2][BKD * BSTR];
    __shared__ float ksred[4][128];
    const uint32_t VsAddr = smem_u32(Vs);

    const int nh = blockIdx.x;
    const int split = blockIdx.y;
    const int n = nh >> 3, h = nh & 7;
    const int lbase = split * (LQ / KVSPLIT);
    const int tid = threadIdx.x;
    const int wid = tid >> 5, lane = tid & 31;
    const int wm = (wid & 1) * 64;
    const int wn = (wid >> 1) * 64;
    const int r = lane >> 2, cq = lane & 3;

    const int lrow = wid * 4 + (lane >> 3);
    const int dbase = (lane & 7) * 4;
    const size_t base = ((size_t)(n * LQ + lbase)) * CH + h * HD;

    float acc[4][8][4];
#pragma unroll
    for (int i = 0; i < 4; i++)
#pragma unroll
        for (int j = 0; j < 8; j++)
#pragma unroll
            for (int c = 0; c < 4; c++) acc[i][j][c] = 0.0f;
    float ksl[4][4];
#pragma unroll
    for (int i = 0; i < 4; i++)
#pragma unroll
        for (int j = 0; j < 4; j++) ksl[i][j] = 0.0f;

    float4 kreg[4];
    const int KT = (LQ / KVSPLIT) / BKD;

    auto ldgK = [&](int kt) {
#pragma unroll
        for (int i = 0; i < 4; i++)
            kreg[i] = *(const float4*)(Kg + base + (size_t)(kt * BKD + lrow) * CH + dbase + 32 * i);
    };
    auto stsK = [&](int buf) {
#pragma unroll
        for (int i = 0; i < 4; i++) {
            float fv[4] = {fmap(kreg[i].x), fmap(kreg[i].y), fmap(kreg[i].z), fmap(kreg[i].w)};
#pragma unroll
            for (int j = 0; j < 4; j++) {
                float rv = tf32rf(fv[j]);
                ksl[i][j] += rv;
                Kt[buf][(dbase + 32 * i + j) * KV_ASTR + lrow] = __float_as_uint(rv);
            }
        }
    };
    auto cpV = [&](int buf, int kt) {
#pragma unroll
        for (int i = 0; i < 4; i++) {
            int idx = tid + 128 * i;
            int kk = idx >> 5, n4 = (idx & 31) * 4;
            cp16(VsAddr + (buf * (BKD * BSTR) + kk * BSTR + n4) * 4,
                 Vg + base + (size_t)(kt * BKD + kk) * CH + n4);
        }
        asm volatile("cp.async.commit_group;" ::: "memory");
    };

    ldgK(0);
    cpV(0, 0);
    stsK(0);
    asm volatile("cp.async.wait_group 0;" ::: "memory");
    __syncthreads();

    for (int kt = 0; kt < KT; kt++) {
        const int buf = kt & 1;
        if (kt + 1 < KT) {
            cpV(buf ^ 1, kt + 1);
            ldgK(kt + 1);
        }
        const uint32_t* Asb = Kt[buf];
        const uint32_t* Bsb = Vs[buf];
#pragma unroll
        for (int s = 0; s < 2; s++) {
            uint32_t af[4][4];
#pragma unroll
            for (int i = 0; i < 4; i++) {
                const int arow = wm + 16 * i + r;
                const int kc = 8 * s + cq;
                af[i][0] = Asb[arow * KV_ASTR + kc];
                af[i][1] = Asb[(arow + 8) * KV_ASTR + kc];
                af[i][2] = Asb[arow * KV_ASTR + kc + 4];
                af[i][3] = Asb[(arow + 8) * KV_ASTR + kc + 4];
            }
            uint32_t bf[8][2];
#pragma unroll
            for (int j = 0; j < 8; j++) {
                const int ncol = wn + 8 * j + r;
                bf[j][0] = Bsb[(8 * s + cq) * BSTR + ncol];
                bf[j][1] = Bsb[(8 * s + cq + 4) * BSTR + ncol];
            }
#pragma unroll
            for (int i = 0; i < 4; i++)
#pragma unroll
                for (int j = 0; j < 8; j++)
                    mma_tf32(acc[i][j], af[i][0], af[i][1], af[i][2], af[i][3],
                             bf[j][0], bf[j][1]);
        }
        if (kt + 1 < KT) stsK(buf ^ 1);
        asm volatile("cp.async.wait_group 0;" ::: "memory");
        __syncthreads();
    }

    float* o = kvpart + (((size_t)(split * NHT + nh)) << 14);
#pragma unroll
    for (int i = 0; i < 4; i++) {
        const int row0 = wm + 16 * i + r;
#pragma unroll
        for (int j = 0; j < 8; j++) {
            const int col = wn + 8 * j + 2 * cq;
            float2 v0, v1;
            v0.x = acc[i][j][0]; v0.y = acc[i][j][1];
            v1.x = acc[i][j][2]; v1.y = acc[i][j][3];
            *(float2*)(o + (size_t)row0 * HD + col) = v0;
            *(float2*)(o + (size_t)(row0 + 8) * HD + col) = v1;
        }
    }

#pragma unroll
    for (int i = 0; i < 4; i++)
#pragma unroll
        for (int j = 0; j < 4; j++) {
            float v = ksl[i][j];
            v += __shfl_xor_sync(0xffffffffu, v, 8);
            v += __shfl_xor_sync(0xffffffffu, v, 16);
            ksl[i][j] = v;
        }
    if (lane < 8) {
#pragma unroll
        for (int i = 0; i < 4; i++)
#pragma unroll
            for (int j = 0; j < 4; j++)
                ksred[wid][32 * i + 4 * lane + j] = ksl[i][j];
    }
    __syncthreads();
    {
        int d = tid;
        float s = ksred[0][d] + ksred[1][d] + ksred[2][d] + ksred[3][d];
        kspart[(split * NHT + nh) * HD + d] = s;
    }
}

__global__ void kv_reduce_kernel(const float* __restrict__ part, float* __restrict__ kv) {
    int idx = blockIdx.x * 256 + threadIdx.x;
    if (idx < NHT * HD * HD) {
        int nh = idx >> 14;
        int i = idx & 16383;
        float s = 0.0f;
#pragma unroll
        for (int sp = 0; sp < KVSPLIT; sp++)
            s += part[(((size_t)(sp * NHT + nh)) << 14) + i];
        kv[idx] = tf32rf(s);
    }
}

__global__ void ks_reduce_kernel(const float* __restrict__ part, float* __restrict__ ks) {
    int idx = blockIdx.x * 128 + threadIdx.x;
    int nh = idx >> 7, d = idx & 127;
    float s = 0.0f;
#pragma unroll
    for (int sp = 0; sp < KVSPLIT; sp++)
        s += part[(sp * NHT + nh) * HD + d];
    ks[idx] = s;
}

// ---------------- tensor-core attn out: O = fmap(Q) @ KV * Z ----------------
__global__ __launch_bounds__(128) void attn_out_tc(
    const float* __restrict__ Qg, const float* __restrict__ KV,
    const float* __restrict__ Ksum, float* __restrict__ Og) {
    __shared__ uint32_t Qs[2][128 * ASTR];
    __shared__ uint32_t Bs[2][BKD * BSTR];
    __shared__ float kss[HD];
    __shared__ float qks[128];
    const uint32_t BsAddr = smem_u32(Bs);

    const int nh = blockIdx.y;
    const int n = nh >> 3, h = nh & 7;
    const int l0 = blockIdx.x * 128;
    const int tid = threadIdx.x;
    const int wid = tid >> 5, lane = tid & 31;
    const int wm = (wid & 1) * 64;
    const int wn = (wid >> 1) * 64;
    const int r = lane >> 2, cq = lane & 3;

    kss[tid] = Ksum[nh * HD + tid];

    const size_t qbase = ((size_t)(n * LQ + l0)) * CH + h * HD;
    const float* kvb = KV + ((size_t)nh << 14);

    const int qrow0 = tid >> 2;
    const int qc4 = (tid & 3) * 4;

    float acc[4][8][4];
#pragma unroll
    for (int i = 0; i < 4; i++)
#pragma unroll
        for (int j = 0; j < 8; j++)
#pragma unroll
            for (int c = 0; c < 4; c++) acc[i][j][c] = 0.0f;
    float qkp[4] = {0.f, 0.f, 0.f, 0.f};

    float4 qreg[4];
    const int KT = HD / BKD;

    auto ldgQ = [&](int kt) {
#pragma unroll
        for (int i = 0; i < 4; i++)
            qreg[i] = *(const float4*)(Qg + qbase + (size_t)(qrow0 + 32 * i) * CH + kt * BKD + qc4);
    };
    auto stsQ = [&](int buf, int kt) {
#pragma unroll
        for (int i = 0; i < 4; i++) {
            float f0 = tf32rf(fmap(qreg[i].x));
            float f1 = tf32rf(fmap(qreg[i].y));
            float f2 = tf32rf(fmap(qreg[i].z));
            float f3 = tf32rf(fmap(qreg[i].w));
            const int dc = kt * BKD + qc4;
            qkp[i] += f0 * kss[dc] + f1 * kss[dc + 1] + f2 * kss[dc + 2] + f3 * kss[dc + 3];
            uint32_t* p = &Qs[buf][(qrow0 + 32 * i) * ASTR + qc4];
            p[0] = __float_as_uint(f0); p[1] = __float_as_uint(f1);
            p[2] = __float_as_uint(f2); p[3] = __float_as_uint(f3);
        }
    };
    auto cpB = [&](int buf, int kt) {
#pragma unroll
        for (int i = 0; i < 4; i++) {
            int idx = tid + 128 * i;
            int kk = idx >> 5, n4 = (idx & 31) * 4;
            cp16(BsAddr + (buf * (BKD * BSTR) + kk * BSTR + n4) * 4,
                 kvb + (size_t)(kt * BKD + kk) * HD + n4);
        }
        asm volatile("cp.async.commit_group;" ::: "memory");
    };

    ldgQ(0);
    cpB(0, 0);
    __syncthreads();   // kss visible to all warps BEFORE first stsQ reads it
    stsQ(0, 0);
    asm volatile("cp.async.wait_group 0;" ::: "memory");
    __syncthreads();

    for (int kt = 0; kt < KT; kt++) {
        const int buf = kt & 1;
        if (kt + 1 < KT) {
            cpB(buf ^ 1, kt + 1);
            ldgQ(kt + 1);
        }
        const uint32_t* Asb = Qs[buf];
        const uint32_t* Bsb = Bs[buf];
#pragma unroll
        for (int s = 0; s < 2; s++) {
            uint32_t af[4][4];
#pragma unroll
            for (int i = 0; i < 4; i++) {
                const int arow = wm + 16 * i + r;
                const int kc = 8 * s + cq;
                af[i][0] = Asb[arow * ASTR + kc];
                af[i][1] = Asb[(arow + 8) * ASTR + kc];
                af[i][2] = Asb[arow * ASTR + kc + 4];
                af[i][3] = Asb[(arow + 8) * ASTR + kc + 4];
            }
            uint32_t bf[8][2];
#pragma unroll
            for (int j = 0; j < 8; j++) {
                const int ncol = wn + 8 * j + r;
                bf[j][0] = Bsb[(8 * s + cq) * BSTR + ncol];
                bf[j][1] = Bsb[(8 * s + cq + 4) * BSTR + ncol];
            }
#pragma unroll
            for (int i = 0; i < 4; i++)
#pragma unroll
                for (int j = 0; j < 8; j++)
                    mma_tf32(acc[i][j], af[i][0], af[i][1], af[i][2], af[i][3],
                             bf[j][0], bf[j][1]);
        }
        if (kt + 1 < KT) stsQ(buf ^ 1, kt + 1);
        asm volatile("cp.async.wait_group 0;" ::: "memory");
        __syncthreads();
    }

#pragma unroll
    for (int i = 0; i < 4; i++) {
        float v = qkp[i];
        v += __shfl_xor_sync(0xffffffffu, v, 1);
        v += __shfl_xor_sync(0xffffffffu, v, 2);
        if ((lane & 3) == 0) qks[qrow0 + 32 * i] = v;
    }
    __syncthreads();

#pragma unroll
    for (int i = 0; i < 4; i++) {
        const int row0 = wm + 16 * i + r;
        const float z0 = 1.0f / (qks[row0] + EPS_ATTN);
        const float z1 = 1.0f / (qks[row0 + 8] + EPS_ATTN);
        float* op0 = Og + ((size_t)(n * LQ + l0 + row0)) * CH + h * HD;
        float* op1 = Og + ((size_t)(n * LQ + l0 + row0 + 8)) * CH + h * HD;
#pragma unroll
        for (int j = 0; j < 8; j++) {
            const int col = wn + 8 * j + 2 * cq;
            float2 v0, v1;
            v0.x = tf32rf(acc[i][j][0] * z0); v0.y = tf32rf(acc[i][j][1] * z0);
            v1.x = tf32rf(acc[i][j][2] * z1); v1.y = tf32rf(acc[i][j][3] * z1);
            *(float2*)(op0 + col) = v0;
            *(float2*)(op1 + col) = v1;
        }
    }
}

// ---------------- fused residual + LayerNorm (+ optional rounded copy) ----------------
__global__ __launch_bounds__(256) void ln_res_kernel(
    const float* __restrict__ res, const float* __restrict__ y,
    const float* __restrict__ g, const float* __restrict__ b,
    float* __restrict__ out, float* __restrict__ out_r) {
    const int row = blockIdx.x;
    const int t = threadIdx.x;
    const size_t off = (size_t)row * CH + t * 4;
    float4 v = *(const float4*)(y + off);
    __shared__ float red[8];
    const int lane = t & 31, w = t >> 5;

    float s = v.x + v.y + v.z + v.w;
#pragma unroll
    for (int o = 16; o; o >>= 1) s += __shfl_xor_sync(0xffffffffu, s, o);
    if (!lane) red[w] = s;
    __syncthreads();
    float tot = red[0];
#pragma unroll
    for (int i = 1; i < 8; i++) tot += red[i];
    const float mean = tot * (1.0f / CH);

    float dx = v.x - mean, dy = v.y - mean, dz = v.z - mean, dw = v.w - mean;
    float sq = dx * dx + dy * dy + dz * dz + dw * dw;
    __syncthreads();
#pragma unroll
    for (int o = 16; o; o >>= 1) sq += __shfl_xor_sync(0xffffffffu, sq, o);
    if (!lane) red[w] = sq;
    __syncthreads();
    float vtot = red[0];
#pragma unroll
    for (int i = 1; i < 8; i++) vtot += red[i];
    const float rstd = rsqrtf(vtot * (1.0f / CH) + EPS_LN);

    float4 gv = *(const float4*)(g + t * 4);
    float4 bv = *(const float4*)(b + t * 4);
    float4 rv = *(const float4*)(res + off);
    float4 o;
    o.x = rv.x + dx * rstd * gv.x + bv.x;
    o.y = rv.y + dy * rstd * gv.y + bv.y;
    o.z = rv.z + dz * rstd * gv.z + bv.z;
    o.w = rv.w + dw * rstd * gv.w + bv.w;
    *(float4*)(out + off) = o;
    if (out_r) {
        float4 rr;
        rr.x = tf32rf(o.x); rr.y = tf32rf(o.y); rr.z = tf32rf(o.z); rr.w = tf32rf(o.w);
        *(float4*)(out_r + off) = rr;
    }
}

// ---------------- host orchestration ----------------
extern "C" void kernel_launch(void* const* d_in, const int* in_sizes, int n_in,
                              void* d_out, int out_size) {
    const float* depth   = (const float*)d_in[0];
    const float* context = (const float*)d_in[1];
    const float* pos     = (const float*)d_in[2];
    const float* wsrc[16] = {
        (const float*)d_in[3],  (const float*)d_in[4],  (const float*)d_in[5],
        (const float*)d_in[6],
        (const float*)d_in[13], (const float*)d_in[14], (const float*)d_in[15],
        (const float*)d_in[16],
        (const float*)d_in[17], (const float*)d_in[18], (const float*)d_in[19],
        (const float*)d_in[20],
        (const float*)d_in[7],  (const float*)d_in[21],
        (const float*)d_in[8],  (const float*)d_in[22]
    };
    const float* e_g1 = (const float*)d_in[9];
    const float* e_b1 = (const float*)d_in[10];
    const float* e_g2 = (const float*)d_in[11];
    const float* e_b2 = (const float*)d_in[12];
    const float* d_g0 = (const float*)d_in[23];
    const float* d_b0 = (const float*)d_in[24];
    const float* d_g1 = (const float*)d_in[25];
    const float* d_b1 = (const float*)d_in[26];
    const float* d_g2 = (const float*)d_in[27];
    const float* d_b2 = (const float*)d_in[28];
    float* out = (float*)d_out;

    float *ctx, *ctxr, *q, *k, *v, *attn, *msg, *x, *xr, *yb, *ybr, *hb;
    float *depr, *wt, *kvp, *kv, *ksp, *ks;
    cudaGetSymbolAddress((void**)&ctx,  g_ctx);
    cudaGetSymbolAddress((void**)&ctxr, g_ctx_r);
    cudaGetSymbolAddress((void**)&q,    g_q);
    cudaGetSymbolAddress((void**)&k,    g_k);
    cudaGetSymbolAddress((void**)&v,    g_v);
    cudaGetSymbolAddress((void**)&attn, g_attn);
    cudaGetSymbolAddress((void**)&msg,  g_msg);
    cudaGetSymbolAddress((void**)&x,    g_x);
    cudaGetSymbolAddress((void**)&xr,   g_x_r);
    cudaGetSymbolAddress((void**)&yb,   g_y);
    cudaGetSymbolAddress((void**)&ybr,  g_y_r);
    cudaGetSymbolAddress((void**)&hb,   g_h);
    cudaGetSymbolAddress((void**)&depr, g_depth_r);
    cudaGetSymbolAddress((void**)&wt,   g_wt);
    cudaGetSymbolAddress((void**)&kvp,  g_kvpart);
    cudaGetSymbolAddress((void**)&kv,   g_kv);
    cudaGetSymbolAddress((void**)&ksp,  g_kspart);
    cudaGetSymbolAddress((void**)&ks,   g_ksum);

    cudaFuncSetAttribute(gemm_mma<false, false>, cudaFuncAttributeMaxDynamicSharedMemorySize, GEMM_SMEM_BYTES);
    cudaFuncSetAttribute(gemm_mma<false, true>,  cudaFuncAttributeMaxDynamicSharedMemorySize, GEMM_SMEM_BYTES);
    cudaFuncSetAttribute(gemm_mma<true, true>,   cudaFuncAttributeMaxDynamicSharedMemorySize, GEMM_SMEM_BYTES);

    const size_t MSQ = 1024 * 1024;
    float* wr[16];
    for (int i = 0; i < 12; i++) wr[i] = wt + i * MSQ;
    for (int i = 0; i < 4; i++)  wr[12 + i] = wt + 12 * MSQ + i * 2 * MSQ;

    RCArgs rc;
    for (int i = 0; i < 16; i++) {
        rc.src[i] = (const float4*)wsrc[i];
        rc.dst[i] = (float4*)wr[i];
        rc.n4[i] = (i < 12) ? (int)(MSQ / 4) : (int)(MSQ / 2);
    }
    rc.src[16] = (const float4*)depth;
    rc.dst[16] = (float4*)depr;
    rc.n4[16] = NL * CH / 4;
    round_copy_multi<<<dim3(256, 17), 256>>>(rc);

    float *t_ewq = wr[0], *t_ewk = wr[1], *t_ewv = wr[2], *t_ewm = wr[3];
    float *t_dwq0 = wr[4], *t_dwk0 = wr[5], *t_dwv0 = wr[6], *t_dwm0 = wr[7];
    float *t_dwq1 = wr[8], *t_dwk1 = wr[9], *t_dwv1 = wr[10], *t_dwm1 = wr[11];
    float *t_ew1 = wr[12], *t_dw1 = wr[13], *t_ew2 = wr[14], *t_dw2 = wr[15];

    const dim3 blk(256);
    const dim3 gblk(128);
    const dim3 gU(CH / 128, NL / 128);
    const dim3 gF(2 * CH / 128, NL / 128);

    auto attention = [&](const float* qp, const float* kp, const float* vp) {
        attn_kv_tc<<<dim3(NHT, KVSPLIT), gblk>>>(kp, vp, kvp, ksp);
        kv_reduce_kernel<<<(NHT * HD * HD + 255) / 256, blk>>>(kvp, kv);
        ks_reduce_kernel<<<NHT, 128>>>(ksp, ks);
        attn_out_tc<<<dim3(LQ / 128, NHT), gblk>>>(qp, kv, ks, attn);
    };

    // ===== encoder =====
    add_kernel<<<2048, blk>>>(context, pos, ctx, ctxr, NL * CH / 4);
    gemm_mma<false, false><<<gU, gblk, GEMM_SMEM_BYTES>>>(ctxr, t_ewq, q, NL, CH, CH);
    gemm_mma<false, false><<<gU, gblk, GEMM_SMEM_BYTES>>>(ctxr, t_ewk, k, NL, CH, CH);
    gemm_mma<false, true><<<gU, gblk, GEMM_SMEM_BYTES>>>(ctxr, t_ewv, v, NL, CH, CH);
    attention(q, k, v);
    gemm_mma<false, false><<<gU, gblk, GEMM_SMEM_BYTES>>>(attn, t_ewm, msg, NL, CH, CH);
    ln_res_kernel<<<NL, blk>>>(ctx, msg, e_g1, e_b1, x, xr);
    gemm_mma<true, true><<<gF, gblk, GEMM_SMEM_BYTES>>>(xr, t_ew1, hb, NL, CH, 2 * CH);
    gemm_mma<false, false><<<gU, gblk, GEMM_SMEM_BYTES>>>(hb, t_ew2, msg, NL, 2 * CH, CH);
    ln_res_kernel<<<NL, blk>>>(x, msg, e_g2, e_b2, ctx, ctxr);

    // ===== decoder: self-attention =====
    gemm_mma<false, false><<<gU, gblk, GEMM_SMEM_BYTES>>>(depr, t_dwq0, q, NL, CH, CH);
    gemm_mma<false, false><<<gU, gblk, GEMM_SMEM_BYTES>>>(depr, t_dwk0, k, NL, CH, CH);
    gemm_mma<false, true><<<gU, gblk, GEMM_SMEM_BYTES>>>(depr, t_dwv0, v, NL, CH, CH);
    attention(q, k, v);
    gemm_mma<false, false><<<gU, gblk, GEMM_SMEM_BYTES>>>(attn, t_dwm0, msg, NL, CH, CH);
    ln_res_kernel<<<NL, blk>>>(depth, msg, d_g0, d_b0, x, xr);

    // ===== decoder: cross-attention =====
    gemm_mma<false, false><<<gU, gblk, GEMM_SMEM_BYTES>>>(xr, t_dwq1, q, NL, CH, CH);
    gemm_mma<false, false><<<gU, gblk, GEMM_SMEM_BYTES>>>(ctxr, t_dwk1, k, NL, CH, CH);
    gemm_mma<false, true><<<gU, gblk, GEMM_SMEM_BYTES>>>(ctxr, t_dwv1, v, NL, CH, CH);
    attention(q, k, v);
    gemm_mma<false, false><<<gU, gblk, GEMM_SMEM_BYTES>>>(attn, t_dwm1, msg, NL, CH, CH);
    ln_res_kernel<<<NL, blk>>>(x, msg, d_g1, d_b1, yb, ybr);

    // ===== decoder: FFN =====
    gemm_mma<true, true><<<gF, gblk, GEMM_SMEM_BYTES>>>(ybr, t_dw1, hb, NL, CH, 2 * CH);
    gemm_mma<false, false><<<gU, gblk, GEMM_SMEM_BYTES>>>(hb, t_dw2, msg, NL, 2 * CH, CH);
    ln_res_kernel<<<NL, blk>>>(yb, msg, d_g2, d_b2, out, nullptr);
}

// round 9
// speedup vs baseline: 3.5465x; 1.1593x over previous
#include <cuda_runtime.h>
#include <cstdint>
#include <math.h>

#define NB 4
#define LQ 2048
#define CH 1024
#define NHD 8
#define HD 128
#define NL (NB * LQ)
#define NHT (NB * NHD)
#define KVSPLIT 8
#define EPS_ATTN 1e-6f
#define EPS_LN 1e-5f

// attention tiles
#define BKD 16
#define ASTR 20
#define BSTR 136
#define KV_ASTR 17

// GEMM tiles (BK=32)
#define STAGES 3
#define BK2 32
#define ASTR2 36
#define A2_WORDS (128 * ASTR2)            // 4608
#define B2_WORDS (BK2 * BSTR)             // 4352
#define STG2_WORDS (A2_WORDS + B2_WORDS)  // 8960
#define GEMM_SMEM2 (STAGES * STG2_WORDS * 4)  // 107520

// ---------------- scratch ----------------
__device__ float g_ctx[NL * CH];
__device__ float g_ctx_r[NL * CH];
__device__ float g_q[NL * CH];
__device__ float g_qkv[NL * 3 * CH];
__device__ float g_attn[NL * CH];
__device__ float g_msg[NL * CH];
__device__ float g_x[NL * CH];
__device__ float g_x_r[NL * CH];
__device__ float g_y[NL * CH];
__device__ float g_y_r[NL * CH];
__device__ float g_h[NL * 2 * CH];
__device__ float g_depth_r[NL * CH];
__device__ float g_wt[20 * 1024 * 1024];
__device__ float g_kvpart[KVSPLIT * NHT * HD * HD];
__device__ float g_kv[NHT * HD * HD];
__device__ float g_kspart[KVSPLIT * NHT * HD];
__device__ float g_ksum[NHT * HD];

__device__ __forceinline__ float fmap(float x) { return x > 0.0f ? x + 1.0f : expf(x); }

__device__ __forceinline__ float tf32rf(float x) {
    uint32_t u;
    asm("cvt.rna.tf32.f32 %0, %1;" : "=r"(u) : "f"(x));
    return __uint_as_float(u);
}

__device__ __forceinline__ void cp16(uint32_t saddr, const void* g) {
    asm volatile("cp.async.cg.shared.global [%0], [%1], 16;" :: "r"(saddr), "l"(g));
}

__device__ __forceinline__ uint32_t smem_u32(const void* p) {
    uint32_t a;
    asm("{ .reg .u64 t; cvta.to.shared.u64 t, %1; cvt.u32.u64 %0, t; }" : "=r"(a) : "l"(p));
    return a;
}

__device__ __forceinline__ void mma_tf32(float* d,
                                         uint32_t a0, uint32_t a1, uint32_t a2, uint32_t a3,
                                         uint32_t b0, uint32_t b1) {
    asm volatile(
        "mma.sync.aligned.m16n8k8.row.col.f32.tf32.tf32.f32 "
        "{%0,%1,%2,%3}, {%4,%5,%6,%7}, {%8,%9}, {%0,%1,%2,%3};"
        : "+f"(d[0]), "+f"(d[1]), "+f"(d[2]), "+f"(d[3])
        : "r"(a0), "r"(a1), "r"(a2), "r"(a3), "r"(b0), "r"(b1));
}

// ---------------- merged round-copy (17 segments; optional column packing) ----------------
// Packed segments have 1024-float rows (256 float4): dst index = (i>>8)*dstride4 + (i&255).
struct RCArgs {
    const float4* src[17];
    float4* dst[17];
    int n4[17];
    int dstride4[17];   // 0 = contiguous
};
__global__ void round_copy_multi(RCArgs a) {
    const int seg = blockIdx.y;
    const float4* __restrict__ in = a.src[seg];
    float4* __restrict__ out = a.dst[seg];
    const int n4 = a.n4[seg];
    const int ds = a.dstride4[seg];
    int idx = blockIdx.x * blockDim.x + threadIdx.x;
    int stride = gridDim.x * blockDim.x;
    for (int i = idx; i < n4; i += stride) {
        float4 v = in[i];
        v.x = tf32rf(v.x); v.y = tf32rf(v.y); v.z = tf32rf(v.z); v.w = tf32rf(v.w);
        int o = ds ? ((i >> 8) * ds + (i & 255)) : i;
        out[o] = v;
    }
}

// ---------------- tf32 tensor-core GEMM (cp.async 3-stage, BK=32) ----------------
template <bool RELU, bool ROUND>
__global__ __launch_bounds__(128) void gemm_mma(
    const float* __restrict__ A, const float* __restrict__ B, float* __restrict__ Cm,
    int M, int K, int Nn) {
    extern __shared__ uint32_t sm[];
    const uint32_t smaddr = smem_u32(sm);
    const int tid = threadIdx.x;
    const int wid = tid >> 5, lane = tid & 31;
    const int bm = blockIdx.y * 128;
    const int bn = blockIdx.x * 128;
    const int wm = (wid & 1) * 64;
    const int wn = (wid >> 1) * 64;
    const int r = lane >> 2, cq = lane & 3;

    float acc[4][8][4];
#pragma unroll
    for (int i = 0; i < 4; i++)
#pragma unroll
        for (int j = 0; j < 8; j++)
#pragma unroll
            for (int c = 0; c < 4; c++) acc[i][j][c] = 0.0f;

    const int KT = K / BK2;

    auto issue = [&](int s, int kt) {
        const uint32_t sbA = smaddr + s * (STG2_WORDS * 4);
        const float* Ag = A + (size_t)bm * K + (size_t)kt * BK2;
#pragma unroll
        for (int i = 0; i < 8; i++) {
            int idx = tid + 128 * i;
            int row = idx >> 3, c4 = (idx & 7) * 4;
            cp16(sbA + (row * ASTR2 + c4) * 4, Ag + (size_t)row * K + c4);
        }
        const uint32_t sbB = sbA + A2_WORDS * 4;
        const float* Bg = B + (size_t)kt * BK2 * Nn + bn;
#pragma unroll
        for (int i = 0; i < 8; i++) {
            int idx = tid + 128 * i;
            int kk = idx >> 5, n4 = (idx & 31) * 4;
            cp16(sbB + (kk * BSTR + n4) * 4, Bg + (size_t)kk * Nn + n4);
        }
        asm volatile("cp.async.commit_group;" ::: "memory");
    };

    issue(0, 0);
    issue(1, 1);

    for (int kt = 0; kt < KT; kt++) {
        asm volatile("cp.async.wait_group 1;" ::: "memory");
        __syncthreads();
        if (kt + 2 < KT) issue((kt + 2) % STAGES, kt + 2);

        const uint32_t* Asb = sm + (kt % STAGES) * STG2_WORDS;
        const uint32_t* Bsb = Asb + A2_WORDS;
#pragma unroll
        for (int s = 0; s < 4; s++) {
            uint32_t af[4][4];
#pragma unroll
            for (int i = 0; i < 4; i++) {
                const int arow = wm + 16 * i + r;
                const int kc = 8 * s + cq;
                af[i][0] = Asb[arow * ASTR2 + kc];
                af[i][1] = Asb[(arow + 8) * ASTR2 + kc];
                af[i][2] = Asb[arow * ASTR2 + kc + 4];
                af[i][3] = Asb[(arow + 8) * ASTR2 + kc + 4];
            }
            uint32_t bf[8][2];
#pragma unroll
            for (int j = 0; j < 8; j++) {
                const int ncol = wn + 8 * j + r;
                bf[j][0] = Bsb[(8 * s + cq) * BSTR + ncol];
                bf[j][1] = Bsb[(8 * s + cq + 4) * BSTR + ncol];
            }
#pragma unroll
            for (int i = 0; i < 4; i++)
#pragma unroll
                for (int j = 0; j < 8; j++)
                    mma_tf32(acc[i][j], af[i][0], af[i][1], af[i][2], af[i][3],
                             bf[j][0], bf[j][1]);
        }
    }

#pragma unroll
    for (int i = 0; i < 4; i++) {
        const int row0 = bm + wm + 16 * i + r;
#pragma unroll
        for (int j = 0; j < 8; j++) {
            const int col = bn + wn + 8 * j + 2 * cq;
            float2 v0, v1;
            v0.x = acc[i][j][0]; v0.y = acc[i][j][1];
            v1.x = acc[i][j][2]; v1.y = acc[i][j][3];
            if (RELU) {
                v0.x = fmaxf(v0.x, 0.f); v0.y = fmaxf(v0.y, 0.f);
                v1.x = fmaxf(v1.x, 0.f); v1.y = fmaxf(v1.y, 0.f);
            }
            if (ROUND) {
                v0.x = tf32rf(v0.x); v0.y = tf32rf(v0.y);
                v1.x = tf32rf(v1.x); v1.y = tf32rf(v1.y);
            }
            *(float2*)(Cm + (size_t)row0 * Nn + col) = v0;
            *(float2*)(Cm + (size_t)(row0 + 8) * Nn + col) = v1;
        }
    }
}

// ---------------- elementwise add (+ rounded copy) ----------------
__global__ void add_kernel(const float* __restrict__ a, const float* __restrict__ b,
                           float* __restrict__ o, float* __restrict__ o_r, int n4) {
    int idx = blockIdx.x * blockDim.x + threadIdx.x;
    int stride = gridDim.x * blockDim.x;
    const float4* a4 = (const float4*)a;
    const float4* b4 = (const float4*)b;
    float4* o4 = (float4*)o;
    float4* r4 = (float4*)o_r;
    for (int i = idx; i < n4; i += stride) {
        float4 x = a4[i], y = b4[i];
        x.x += y.x; x.y += y.y; x.z += y.z; x.w += y.w;
        o4[i] = x;
        float4 rr;
        rr.x = tf32rf(x.x); rr.y = tf32rf(x.y); rr.z = tf32rf(x.z); rr.w = tf32rf(x.w);
        r4[i] = rr;
    }
}

// ---------------- tensor-core attn KV (row stride ld) ----------------
__global__ __launch_bounds__(128) void attn_kv_tc(
    const float* __restrict__ Kg, const float* __restrict__ Vg, int ld,
    float* __restrict__ kvpart, float* __restrict__ kspart) {
    __shared__ uint32_t Kt[2][128 * KV_ASTR];
    __shared__ uint32_t Vs[2][BKD * BSTR];
    __shared__ float ksred[4][128];
    const uint32_t VsAddr = smem_u32(Vs);

    const int nh = blockIdx.x;
    const int split = blockIdx.y;
    const int n = nh >> 3, h = nh & 7;
    const int lbase = split * (LQ / KVSPLIT);
    const int tid = threadIdx.x;
    const int wid = tid >> 5, lane = tid & 31;
    const int wm = (wid & 1) * 64;
    const int wn = (wid >> 1) * 64;
    const int r = lane >> 2, cq = lane & 3;

    const int lrow = wid * 4 + (lane >> 3);
    const int dbase = (lane & 7) * 4;
    const size_t base = ((size_t)(n * LQ + lbase)) * ld + h * HD;

    float acc[4][8][4];
#pragma unroll
    for (int i = 0; i < 4; i++)
#pragma unroll
        for (int j = 0; j < 8; j++)
#pragma unroll
            for (int c = 0; c < 4; c++) acc[i][j][c] = 0.0f;
    float ksl[4][4];
#pragma unroll
    for (int i = 0; i < 4; i++)
#pragma unroll
        for (int j = 0; j < 4; j++) ksl[i][j] = 0.0f;

    float4 kreg[4];
    const int KT = (LQ / KVSPLIT) / BKD;

    auto ldgK = [&](int kt) {
#pragma unroll
        for (int i = 0; i < 4; i++)
            kreg[i] = *(const float4*)(Kg + base + (size_t)(kt * BKD + lrow) * ld + dbase + 32 * i);
    };
    auto stsK = [&](int buf) {
#pragma unroll
        for (int i = 0; i < 4; i++) {
            float fv[4] = {fmap(kreg[i].x), fmap(kreg[i].y), fmap(kreg[i].z), fmap(kreg[i].w)};
#pragma unroll
            for (int j = 0; j < 4; j++) {
                float rv = tf32rf(fv[j]);
                ksl[i][j] += rv;
                Kt[buf][(dbase + 32 * i + j) * KV_ASTR + lrow] = __float_as_uint(rv);
            }
        }
    };
    auto cpV = [&](int buf, int kt) {
#pragma unroll
        for (int i = 0; i < 4; i++) {
            int idx = tid + 128 * i;
            int kk = idx >> 5, n4 = (idx & 31) * 4;
            cp16(VsAddr + (buf * (BKD * BSTR) + kk * BSTR + n4) * 4,
                 Vg + base + (size_t)(kt * BKD + kk) * ld + n4);
        }
        asm volatile("cp.async.commit_group;" ::: "memory");
    };

    ldgK(0);
    cpV(0, 0);
    stsK(0);
    asm volatile("cp.async.wait_group 0;" ::: "memory");
    __syncthreads();

    for (int kt = 0; kt < KT; kt++) {
        const int buf = kt & 1;
        if (kt + 1 < KT) {
            cpV(buf ^ 1, kt + 1);
            ldgK(kt + 1);
        }
        const uint32_t* Asb = Kt[buf];
        const uint32_t* Bsb = Vs[buf];
#pragma unroll
        for (int s = 0; s < 2; s++) {
            uint32_t af[4][4];
#pragma unroll
            for (int i = 0; i < 4; i++) {
                const int arow = wm + 16 * i + r;
                const int kc = 8 * s + cq;
                af[i][0] = Asb[arow * KV_ASTR + kc];
                af[i][1] = Asb[(arow + 8) * KV_ASTR + kc];
                af[i][2] = Asb[arow * KV_ASTR + kc + 4];
                af[i][3] = Asb[(arow + 8) * KV_ASTR + kc + 4];
            }
            uint32_t bf[8][2];
#pragma unroll
            for (int j = 0; j < 8; j++) {
                const int ncol = wn + 8 * j + r;
                bf[j][0] = Bsb[(8 * s + cq) * BSTR + ncol];
                bf[j][1] = Bsb[(8 * s + cq + 4) * BSTR + ncol];
            }
#pragma unroll
            for (int i = 0; i < 4; i++)
#pragma unroll
                for (int j = 0; j < 8; j++)
                    mma_tf32(acc[i][j], af[i][0], af[i][1], af[i][2], af[i][3],
                             bf[j][0], bf[j][1]);
        }
        if (kt + 1 < KT) stsK(buf ^ 1);
        asm volatile("cp.async.wait_group 0;" ::: "memory");
        __syncthreads();
    }

    float* o = kvpart + (((size_t)(split * NHT + nh)) << 14);
#pragma unroll
    for (int i = 0; i < 4; i++) {
        const int row0 = wm + 16 * i + r;
#pragma unroll
        for (int j = 0; j < 8; j++) {
            const int col = wn + 8 * j + 2 * cq;
            float2 v0, v1;
            v0.x = acc[i][j][0]; v0.y = acc[i][j][1];
            v1.x = acc[i][j][2]; v1.y = acc[i][j][3];
            *(float2*)(o + (size_t)row0 * HD + col) = v0;
            *(float2*)(o + (size_t)(row0 + 8) * HD + col) = v1;
        }
    }

#pragma unroll
    for (int i = 0; i < 4; i++)
#pragma unroll
        for (int j = 0; j < 4; j++) {
            float v = ksl[i][j];
            v += __shfl_xor_sync(0xffffffffu, v, 8);
            v += __shfl_xor_sync(0xffffffffu, v, 16);
            ksl[i][j] = v;
        }
    if (lane < 8) {
#pragma unroll
        for (int i = 0; i < 4; i++)
#pragma unroll
            for (int j = 0; j < 4; j++)
                ksred[wid][32 * i + 4 * lane + j] = ksl[i][j];
    }
    __syncthreads();
    {
        int d = tid;
        float s = ksred[0][d] + ksred[1][d] + ksred[2][d] + ksred[3][d];
        kspart[(split * NHT + nh) * HD + d] = s;
    }
}

__global__ void kv_reduce_kernel(const float* __restrict__ part, float* __restrict__ kv) {
    int idx = blockIdx.x * 256 + threadIdx.x;
    if (idx < NHT * HD * HD) {
        int nh = idx >> 14;
        int i = idx & 16383;
        float s = 0.0f;
#pragma unroll
        for (int sp = 0; sp < KVSPLIT; sp++)
            s += part[(((size_t)(sp * NHT + nh)) << 14) + i];
        kv[idx] = tf32rf(s);
    }
}

__global__ void ks_reduce_kernel(const float* __restrict__ part, float* __restrict__ ks) {
    int idx = blockIdx.x * 128 + threadIdx.x;
    int nh = idx >> 7, d = idx & 127;
    float s = 0.0f;
#pragma unroll
    for (int sp = 0; sp < KVSPLIT; sp++)
        s += part[(sp * NHT + nh) * HD + d];
    ks[idx] = s;
}

// ---------------- tensor-core attn out (q row stride ldq) ----------------
__global__ __launch_bounds__(128) void attn_out_tc(
    const float* __restrict__ Qg, int ldq, const float* __restrict__ KV,
    const float* __restrict__ Ksum, float* __restrict__ Og) {
    __shared__ uint32_t Qs[2][128 * ASTR];
    __shared__ uint32_t Bs[2][BKD * BSTR];
    __shared__ float kss[HD];
    __shared__ float qks[128];
    const uint32_t BsAddr = smem_u32(Bs);

    const int nh = blockIdx.y;
    const int n = nh >> 3, h = nh & 7;
    const int l0 = blockIdx.x * 128;
    const int tid = threadIdx.x;
    const int wid = tid >> 5, lane = tid & 31;
    const int wm = (wid & 1) * 64;
    const int wn = (wid >> 1) * 64;
    const int r = lane >> 2, cq = lane & 3;

    kss[tid] = Ksum[nh * HD + tid];

    const size_t qbase = ((size_t)(n * LQ + l0)) * ldq + h * HD;
    const float* kvb = KV + ((size_t)nh << 14);

    const int qrow0 = tid >> 2;
    const int qc4 = (tid & 3) * 4;

    float acc[4][8][4];
#pragma unroll
    for (int i = 0; i < 4; i++)
#pragma unroll
        for (int j = 0; j < 8; j++)
#pragma unroll
            for (int c = 0; c < 4; c++) acc[i][j][c] = 0.0f;
    float qkp[4] = {0.f, 0.f, 0.f, 0.f};

    float4 qreg[4];
    const int KT = HD / BKD;

    auto ldgQ = [&](int kt) {
#pragma unroll
        for (int i = 0; i < 4; i++)
            qreg[i] = *(const float4*)(Qg + qbase + (size_t)(qrow0 + 32 * i) * ldq + kt * BKD + qc4);
    };
    auto stsQ = [&](int buf, int kt) {
#pragma unroll
        for (int i = 0; i < 4; i++) {
            float f0 = tf32rf(fmap(qreg[i].x));
            float f1 = tf32rf(fmap(qreg[i].y));
            float f2 = tf32rf(fmap(qreg[i].z));
            float f3 = tf32rf(fmap(qreg[i].w));
            const int dc = kt * BKD + qc4;
            qkp[i] += f0 * kss[dc] + f1 * kss[dc + 1] + f2 * kss[dc + 2] + f3 * kss[dc + 3];
            uint32_t* p = &Qs[buf][(qrow0 + 32 * i) * ASTR + qc4];
            p[0] = __float_as_uint(f0); p[1] = __float_as_uint(f1);
            p[2] = __float_as_uint(f2); p[3] = __float_as_uint(f3);
        }
    };
    auto cpB = [&](int buf, int kt) {
#pragma unroll
        for (int i = 0; i < 4; i++) {
            int idx = tid + 128 * i;
            int kk = idx >> 5, n4 = (idx & 31) * 4;
            cp16(BsAddr + (buf * (BKD * BSTR) + kk * BSTR + n4) * 4,
                 kvb + (size_t)(kt * BKD + kk) * HD + n4);
        }
        asm volatile("cp.async.commit_group;" ::: "memory");
    };

    ldgQ(0);
    cpB(0, 0);
    __syncthreads();   // kss visible to all warps before first stsQ
    stsQ(0, 0);
    asm volatile("cp.async.wait_group 0;" ::: "memory");
    __syncthreads();

    for (int kt = 0; kt < KT; kt++) {
        const int buf = kt & 1;
        if (kt + 1 < KT) {
            cpB(buf ^ 1, kt + 1);
            ldgQ(kt + 1);
        }
        const uint32_t* Asb = Qs[buf];
        const uint32_t* Bsb = Bs[buf];
#pragma unroll
        for (int s = 0; s < 2; s++) {
            uint32_t af[4][4];
#pragma unroll
            for (int i = 0; i < 4; i++) {
                const int arow = wm + 16 * i + r;
                const int kc = 8 * s + cq;
                af[i][0] = Asb[arow * ASTR + kc];
                af[i][1] = Asb[(arow + 8) * ASTR + kc];
                af[i][2] = Asb[arow * ASTR + kc + 4];
                af[i][3] = Asb[(arow + 8) * ASTR + kc + 4];
            }
            uint32_t bf[8][2];
#pragma unroll
            for (int j = 0; j < 8; j++) {
                const int ncol = wn + 8 * j + r;
                bf[j][0] = Bsb[(8 * s + cq) * BSTR + ncol];
                bf[j][1] = Bsb[(8 * s + cq + 4) * BSTR + ncol];
            }
#pragma unroll
            for (int i = 0; i < 4; i++)
#pragma unroll
                for (int j = 0; j < 8; j++)
                    mma_tf32(acc[i][j], af[i][0], af[i][1], af[i][2], af[i][3],
                             bf[j][0], bf[j][1]);
        }
        if (kt + 1 < KT) stsQ(buf ^ 1, kt + 1);
        asm volatile("cp.async.wait_group 0;" ::: "memory");
        __syncthreads();
    }

#pragma unroll
    for (int i = 0; i < 4; i++) {
        float v = qkp[i];
        v += __shfl_xor_sync(0xffffffffu, v, 1);
        v += __shfl_xor_sync(0xffffffffu, v, 2);
        if ((lane & 3) == 0) qks[qrow0 + 32 * i] = v;
    }
    __syncthreads();

#pragma unroll
    for (int i = 0; i < 4; i++) {
        const int row0 = wm + 16 * i + r;
        const float z0 = 1.0f / (qks[row0] + EPS_ATTN);
        const float z1 = 1.0f / (qks[row0 + 8] + EPS_ATTN);
        float* op0 = Og + ((size_t)(n * LQ + l0 + row0)) * CH + h * HD;
        float* op1 = Og + ((size_t)(n * LQ + l0 + row0 + 8)) * CH + h * HD;
#pragma unroll
        for (int j = 0; j < 8; j++) {
            const int col = wn + 8 * j + 2 * cq;
            float2 v0, v1;
            v0.x = tf32rf(acc[i][j][0] * z0); v0.y = tf32rf(acc[i][j][1] * z0);
            v1.x = tf32rf(acc[i][j][2] * z1); v1.y = tf32rf(acc[i][j][3] * z1);
            *(float2*)(op0 + col) = v0;
            *(float2*)(op1 + col) = v1;
        }
    }
}

// ---------------- fused residual + LayerNorm (+ optional rounded copy) ----------------
__global__ __launch_bounds__(256) void ln_res_kernel(
    const float* __restrict__ res, const float* __restrict__ y,
    const float* __restrict__ g, const float* __restrict__ b,
    float* __restrict__ out, float* __restrict__ out_r) {
    const int row = blockIdx.x;
    const int t = threadIdx.x;
    const size_t off = (size_t)row * CH + t * 4;
    float4 v = *(const float4*)(y + off);
    __shared__ float red[8];
    const int lane = t & 31, w = t >> 5;

    float s = v.x + v.y + v.z + v.w;
#pragma unroll
    for (int o = 16; o; o >>= 1) s += __shfl_xor_sync(0xffffffffu, s, o);
    if (!lane) red[w] = s;
    __syncthreads();
    float tot = red[0];
#pragma unroll
    for (int i = 1; i < 8; i++) tot += red[i];
    const float mean = tot * (1.0f / CH);

    float dx = v.x - mean, dy = v.y - mean, dz = v.z - mean, dw = v.w - mean;
    float sq = dx * dx + dy * dy + dz * dz + dw * dw;
    __syncthreads();
#pragma unroll
    for (int o = 16; o; o >>= 1) sq += __shfl_xor_sync(0xffffffffu, sq, o);
    if (!lane) red[w] = sq;
    __syncthreads();
    float vtot = red[0];
#pragma unroll
    for (int i = 1; i < 8; i++) vtot += red[i];
    const float rstd = rsqrtf(vtot * (1.0f / CH) + EPS_LN);

    float4 gv = *(const float4*)(g + t * 4);
    float4 bv = *(const float4*)(b + t * 4);
    float4 rv = *(const float4*)(res + off);
    float4 o;
    o.x = rv.x + dx * rstd * gv.x + bv.x;
    o.y = rv.y + dy * rstd * gv.y + bv.y;
    o.z = rv.z + dz * rstd * gv.z + bv.z;
    o.w = rv.w + dw * rstd * gv.w + bv.w;
    *(float4*)(out + off) = o;
    if (out_r) {
        float4 rr;
        rr.x = tf32rf(o.x); rr.y = tf32rf(o.y); rr.z = tf32rf(o.z); rr.w = tf32rf(o.w);
        *(float4*)(out_r + off) = rr;
    }
}

// ---------------- host orchestration ----------------
extern "C" void kernel_launch(void* const* d_in, const int* in_sizes, int n_in,
                              void* d_out, int out_size) {
    const float* depth   = (const float*)d_in[0];
    const float* context = (const float*)d_in[1];
    const float* pos     = (const float*)d_in[2];
    const float* e_wq = (const float*)d_in[3];
    const float* e_wk = (const float*)d_in[4];
    const float* e_wv = (const float*)d_in[5];
    const float* e_wm = (const float*)d_in[6];
    const float* e_w1 = (const float*)d_in[7];
    const float* e_w2 = (const float*)d_in[8];
    const float* e_g1 = (const float*)d_in[9];
    const float* e_b1 = (const float*)d_in[10];
    const float* e_g2 = (const float*)d_in[11];
    const float* e_b2 = (const float*)d_in[12];
    const float* d_wq0 = (const float*)d_in[13];
    const float* d_wk0 = (const float*)d_in[14];
    const float* d_wv0 = (const float*)d_in[15];
    const float* d_wm0 = (const float*)d_in[16];
    const float* d_wq1 = (const float*)d_in[17];
    const float* d_wk1 = (const float*)d_in[18];
    const float* d_wv1 = (const float*)d_in[19];
    const float* d_wm1 = (const float*)d_in[20];
    const float* d_w1 = (const float*)d_in[21];
    const float* d_w2 = (const float*)d_in[22];
    const float* d_g0 = (const float*)d_in[23];
    const float* d_b0 = (const float*)d_in[24];
    const float* d_g1 = (const float*)d_in[25];
    const float* d_b1 = (const float*)d_in[26];
    const float* d_g2 = (const float*)d_in[27];
    const float* d_b2 = (const float*)d_in[28];
    float* out = (float*)d_out;

    float *ctx, *ctxr, *q, *qkv, *attn, *msg, *x, *xr, *yb, *ybr, *hb;
    float *depr, *wt, *kvp, *kv, *ksp, *ks;
    cudaGetSymbolAddress((void**)&ctx,  g_ctx);
    cudaGetSymbolAddress((void**)&ctxr, g_ctx_r);
    cudaGetSymbolAddress((void**)&q,    g_q);
    cudaGetSymbolAddress((void**)&qkv,  g_qkv);
    cudaGetSymbolAddress((void**)&attn, g_attn);
    cudaGetSymbolAddress((void**)&msg,  g_msg);
    cudaGetSymbolAddress((void**)&x,    g_x);
    cudaGetSymbolAddress((void**)&xr,   g_x_r);
    cudaGetSymbolAddress((void**)&yb,   g_y);
    cudaGetSymbolAddress((void**)&ybr,  g_y_r);
    cudaGetSymbolAddress((void**)&hb,   g_h);
    cudaGetSymbolAddress((void**)&depr, g_depth_r);
    cudaGetSymbolAddress((void**)&wt,   g_wt);
    cudaGetSymbolAddress((void**)&kvp,  g_kvpart);
    cudaGetSymbolAddress((void**)&kv,   g_kv);
    cudaGetSymbolAddress((void**)&ksp,  g_kspart);
    cudaGetSymbolAddress((void**)&ks,   g_ksum);

    cudaFuncSetAttribute(gemm_mma<false, false>, cudaFuncAttributeMaxDynamicSharedMemorySize, GEMM_SMEM2);
    cudaFuncSetAttribute(gemm_mma<false, true>,  cudaFuncAttributeMaxDynamicSharedMemorySize, GEMM_SMEM2);
    cudaFuncSetAttribute(gemm_mma<true, true>,   cudaFuncAttributeMaxDynamicSharedMemorySize, GEMM_SMEM2);

    // weight scratch layout (floats)
    const size_t M1 = 1024 * 1024;
    float* w_qkvE = wt;               // [1024][3072]
    float* w_qkvD = wt + 3 * M1;      // [1024][3072]
    float* w_kvD1 = wt + 6 * M1;      // [1024][2048]
    float* w_q1   = wt + 8 * M1;      // [1024][1024]
    float* w_em   = wt + 9 * M1;
    float* w_dm0  = wt + 10 * M1;
    float* w_dm1  = wt + 11 * M1;
    float* w_e1   = wt + 12 * M1;     // [1024][2048]
    float* w_d1   = wt + 14 * M1;
    float* w_e2   = wt + 16 * M1;     // [2048][1024]
    float* w_d2   = wt + 18 * M1;

    RCArgs rc;
    const int SQ4 = (int)(M1 / 4), R24 = (int)(M1 / 2);
    auto seg = [&](int i, const float* s, float* d, int n4, int ds) {
        rc.src[i] = (const float4*)s; rc.dst[i] = (float4*)d;
        rc.n4[i] = n4; rc.dstride4[i] = ds;
    };
    seg(0,  e_wq,  w_qkvE,        SQ4, 768);
    seg(1,  e_wk,  w_qkvE + 1024, SQ4, 768);
    seg(2,  e_wv,  w_qkvE + 2048, SQ4, 768);
    seg(3,  d_wq0, w_qkvD,        SQ4, 768);
    seg(4,  d_wk0, w_qkvD + 1024, SQ4, 768);
    seg(5,  d_wv0, w_qkvD + 2048, SQ4, 768);
    seg(6,  d_wk1, w_kvD1,        SQ4, 512);
    seg(7,  d_wv1, w_kvD1 + 1024, SQ4, 512);
    seg(8,  d_wq1, w_q1,  SQ4, 0);
    seg(9,  e_wm,  w_em,  SQ4, 0);
    seg(10, d_wm0, w_dm0, SQ4, 0);
    seg(11, d_wm1, w_dm1, SQ4, 0);
    seg(12, e_w1, w_e1, R24, 0);
    seg(13, d_w1, w_d1, R24, 0);
    seg(14, e_w2, w_e2, R24, 0);
    seg(15, d_w2, w_d2, R24, 0);
    seg(16, depth, depr, NL * CH / 4, 0);
    round_copy_multi<<<dim3(256, 17), 256>>>(rc);

    const dim3 blk(256);
    const dim3 gblk(128);
    const dim3 gU(CH / 128, NL / 128);          // N=1024
    const dim3 gF(2 * CH / 128, NL / 128);      // N=2048
    const dim3 gQKV(3 * CH / 128, NL / 128);    // N=3072

    auto attention = [&](const float* qp, int ldq, const float* kp, const float* vp, int ldkv) {
        attn_kv_tc<<<dim3(NHT, KVSPLIT), gblk>>>(kp, vp, ldkv, kvp, ksp);
        kv_reduce_kernel<<<(NHT * HD * HD + 255) / 256, blk>>>(kvp, kv);
        ks_reduce_kernel<<<NHT, 128>>>(ksp, ks);
        attn_out_tc<<<dim3(LQ / 128, NHT), gblk>>>(qp, ldq, kv, ks, attn);
    };

    // ===== encoder =====
    add_kernel<<<2048, blk>>>(context, pos, ctx, ctxr, NL * CH / 4);
    gemm_mma<false, true><<<gQKV, gblk, GEMM_SMEM2>>>(ctxr, w_qkvE, qkv, NL, CH, 3 * CH);
    attention(qkv, 3 * CH, qkv + CH, qkv + 2 * CH, 3 * CH);
    gemm_mma<false, false><<<gU, gblk, GEMM_SMEM2>>>(attn, w_em, msg, NL, CH, CH);
    ln_res_kernel<<<NL, blk>>>(ctx, msg, e_g1, e_b1, x, xr);
    gemm_mma<true, true><<<gF, gblk, GEMM_SMEM2>>>(xr, w_e1, hb, NL, CH, 2 * CH);
    gemm_mma<false, false><<<gU, gblk, GEMM_SMEM2>>>(hb, w_e2, msg, NL, 2 * CH, CH);
    ln_res_kernel<<<NL, blk>>>(x, msg, e_g2, e_b2, ctx, ctxr);

    // ===== decoder: self-attention =====
    gemm_mma<false, true><<<gQKV, gblk, GEMM_SMEM2>>>(depr, w_qkvD, qkv, NL, CH, 3 * CH);
    attention(qkv, 3 * CH, qkv + CH, qkv + 2 * CH, 3 * CH);
    gemm_mma<false, false><<<gU, gblk, GEMM_SMEM2>>>(attn, w_dm0, msg, NL, CH, CH);
    ln_res_kernel<<<NL, blk>>>(depth, msg, d_g0, d_b0, x, xr);

    // ===== decoder: cross-attention =====
    gemm_mma<false, false><<<gU, gblk, GEMM_SMEM2>>>(xr, w_q1, q, NL, CH, CH);
    gemm_mma<false, true><<<gF, gblk, GEMM_SMEM2>>>(ctxr, w_kvD1, hb, NL, CH, 2 * CH);
    attention(q, CH, hb, hb + CH, 2 * CH);
    gemm_mma<false, false><<<gU, gblk, GEMM_SMEM2>>>(attn, w_dm1, msg, NL, CH, CH);
    ln_res_kernel<<<NL, blk>>>(x, msg, d_g1, d_b1, yb, ybr);

    // ===== decoder: FFN =====
    gemm_mma<true, true><<<gF, gblk, GEMM_SMEM2>>>(ybr, w_d1, hb, NL, CH, 2 * CH);
    gemm_mma<false, false><<<gU, gblk, GEMM_SMEM2>>>(hb, w_d2, msg, NL, 2 * CH, CH);
    ln_res_kernel<<<NL, blk>>>(yb, msg, d_g2, d_b2, out, nullptr);
}

// round 10
// speedup vs baseline: 4.0057x; 1.1295x over previous
#include <cuda_runtime.h>
#include <cstdint>
#include <math.h>

#define NB 4
#define LQ 2048
#define CH 1024
#define NHD 8
#define HD 128
#define NL (NB * LQ)
#define NHT (NB * NHD)
#define KVSPLIT 8
#define EPS_ATTN 1e-6f
#define EPS_LN 1e-5f

// attention tiles
#define BKD 16
#define ASTR 20
#define BSTR 136
#define KV_ASTR 17

// GEMM tiles (BK=32, 2-stage, 3 CTAs/SM)
#define GSTAGES 2
#define BK2 32
#define ASTR2 36
#define A2_WORDS (128 * ASTR2)            // 4608
#define B2_WORDS (BK2 * BSTR)             // 4352
#define STG2_WORDS (A2_WORDS + B2_WORDS)  // 8960
#define GEMM_SMEM2 (GSTAGES * STG2_WORDS * 4)  // 71680

// ---------------- scratch ----------------
__device__ float g_ctx[NL * CH];
__device__ float g_ctx_r[NL * CH];
__device__ float g_q[NL * CH];
__device__ float g_qkv[NL * 3 * CH];
__device__ float g_attn[NL * CH];
__device__ float g_msg[NL * CH];
__device__ float g_x[NL * CH];
__device__ float g_x_r[NL * CH];
__device__ float g_y[NL * CH];
__device__ float g_y_r[NL * CH];
__device__ float g_h[NL * 2 * CH];
__device__ float g_depth_r[NL * CH];
__device__ float g_wt[20 * 1024 * 1024];
__device__ float g_kvpart[KVSPLIT * NHT * HD * HD];
__device__ float g_kv[NHT * HD * HD];
__device__ float g_kspart[KVSPLIT * NHT * HD];
__device__ float g_ksum[NHT * HD];

__device__ __forceinline__ float fmap(float x) { return x > 0.0f ? x + 1.0f : expf(x); }

__device__ __forceinline__ float tf32rf(float x) {
    uint32_t u;
    asm("cvt.rna.tf32.f32 %0, %1;" : "=r"(u) : "f"(x));
    return __uint_as_float(u);
}

__device__ __forceinline__ void cp16(uint32_t saddr, const void* g) {
    asm volatile("cp.async.cg.shared.global [%0], [%1], 16;" :: "r"(saddr), "l"(g));
}

__device__ __forceinline__ uint32_t smem_u32(const void* p) {
    uint32_t a;
    asm("{ .reg .u64 t; cvta.to.shared.u64 t, %1; cvt.u32.u64 %0, t; }" : "=r"(a) : "l"(p));
    return a;
}

__device__ __forceinline__ void mma_tf32(float* d,
                                         uint32_t a0, uint32_t a1, uint32_t a2, uint32_t a3,
                                         uint32_t b0, uint32_t b1) {
    asm volatile(
        "mma.sync.aligned.m16n8k8.row.col.f32.tf32.tf32.f32 "
        "{%0,%1,%2,%3}, {%4,%5,%6,%7}, {%8,%9}, {%0,%1,%2,%3};"
        : "+f"(d[0]), "+f"(d[1]), "+f"(d[2]), "+f"(d[3])
        : "r"(a0), "r"(a1), "r"(a2), "r"(a3), "r"(b0), "r"(b1));
}

// ---------------- merged round-copy (17 segments; optional column packing) ----------------
struct RCArgs {
    const float4* src[17];
    float4* dst[17];
    int n4[17];
    int dstride4[17];   // 0 = contiguous
};
__global__ void round_copy_multi(RCArgs a) {
    const int seg = blockIdx.y;
    const float4* __restrict__ in = a.src[seg];
    float4* __restrict__ out = a.dst[seg];
    const int n4 = a.n4[seg];
    const int ds = a.dstride4[seg];
    int idx = blockIdx.x * blockDim.x + threadIdx.x;
    int stride = gridDim.x * blockDim.x;
    for (int i = idx; i < n4; i += stride) {
        float4 v = in[i];
        v.x = tf32rf(v.x); v.y = tf32rf(v.y); v.z = tf32rf(v.z); v.w = tf32rf(v.w);
        int o = ds ? ((i >> 8) * ds + (i & 255)) : i;
        out[o] = v;
    }
}

// ---------------- tf32 tensor-core GEMM (cp.async 2-stage, BK=32, 3 CTAs/SM) ----------------
template <bool RELU, bool ROUND>
__global__ __launch_bounds__(128, 3) void gemm_mma(
    const float* __restrict__ A, const float* __restrict__ B, float* __restrict__ Cm,
    int M, int K, int Nn) {
    extern __shared__ uint32_t sm[];
    const uint32_t smaddr = smem_u32(sm);
    const int tid = threadIdx.x;
    const int wid = tid >> 5, lane = tid & 31;
    const int bm = blockIdx.y * 128;
    const int bn = blockIdx.x * 128;
    const int wm = (wid & 1) * 64;
    const int wn = (wid >> 1) * 64;
    const int r = lane >> 2, cq = lane & 3;

    float acc[4][8][4];
#pragma unroll
    for (int i = 0; i < 4; i++)
#pragma unroll
        for (int j = 0; j < 8; j++)
#pragma unroll
            for (int c = 0; c < 4; c++) acc[i][j][c] = 0.0f;

    const int KT = K / BK2;

    auto issue = [&](int s, int kt) {
        const uint32_t sbA = smaddr + s * (STG2_WORDS * 4);
        const float* Ag = A + (size_t)bm * K + (size_t)kt * BK2;
#pragma unroll
        for (int i = 0; i < 8; i++) {
            int idx = tid + 128 * i;
            int row = idx >> 3, c4 = (idx & 7) * 4;
            cp16(sbA + (row * ASTR2 + c4) * 4, Ag + (size_t)row * K + c4);
        }
        const uint32_t sbB = sbA + A2_WORDS * 4;
        const float* Bg = B + (size_t)kt * BK2 * Nn + bn;
#pragma unroll
        for (int i = 0; i < 8; i++) {
            int idx = tid + 128 * i;
            int kk = idx >> 5, n4 = (idx & 31) * 4;
            cp16(sbB + (kk * BSTR + n4) * 4, Bg + (size_t)kk * Nn + n4);
        }
        asm volatile("cp.async.commit_group;" ::: "memory");
    };

    issue(0, 0);

    for (int kt = 0; kt < KT; kt++) {
        const int buf = kt & 1;
        asm volatile("cp.async.wait_group 0;" ::: "memory");
        __syncthreads();
        if (kt + 1 < KT) issue(buf ^ 1, kt + 1);

        const uint32_t* Asb = sm + buf * STG2_WORDS;
        const uint32_t* Bsb = Asb + A2_WORDS;
#pragma unroll
        for (int s = 0; s < 4; s++) {
            uint32_t af[4][4];
#pragma unroll
            for (int i = 0; i < 4; i++) {
                const int arow = wm + 16 * i + r;
                const int kc = 8 * s + cq;
                af[i][0] = Asb[arow * ASTR2 + kc];
                af[i][1] = Asb[(arow + 8) * ASTR2 + kc];
                af[i][2] = Asb[arow * ASTR2 + kc + 4];
                af[i][3] = Asb[(arow + 8) * ASTR2 + kc + 4];
            }
            uint32_t bf[8][2];
#pragma unroll
            for (int j = 0; j < 8; j++) {
                const int ncol = wn + 8 * j + r;
                bf[j][0] = Bsb[(8 * s + cq) * BSTR + ncol];
                bf[j][1] = Bsb[(8 * s + cq + 4) * BSTR + ncol];
            }
#pragma unroll
            for (int i = 0; i < 4; i++)
#pragma unroll
                for (int j = 0; j < 8; j++)
                    mma_tf32(acc[i][j], af[i][0], af[i][1], af[i][2], af[i][3],
                             bf[j][0], bf[j][1]);
        }
    }

#pragma unroll
    for (int i = 0; i < 4; i++) {
        const int row0 = bm + wm + 16 * i + r;
#pragma unroll
        for (int j = 0; j < 8; j++) {
            const int col = bn + wn + 8 * j + 2 * cq;
            float2 v0, v1;
            v0.x = acc[i][j][0]; v0.y = acc[i][j][1];
            v1.x = acc[i][j][2]; v1.y = acc[i][j][3];
            if (RELU) {
                v0.x = fmaxf(v0.x, 0.f); v0.y = fmaxf(v0.y, 0.f);
                v1.x = fmaxf(v1.x, 0.f); v1.y = fmaxf(v1.y, 0.f);
            }
            if (ROUND) {
                v0.x = tf32rf(v0.x); v0.y = tf32rf(v0.y);
                v1.x = tf32rf(v1.x); v1.y = tf32rf(v1.y);
            }
            *(float2*)(Cm + (size_t)row0 * Nn + col) = v0;
            *(float2*)(Cm + (size_t)(row0 + 8) * Nn + col) = v1;
        }
    }
}

// ---------------- elementwise add (+ rounded copy) ----------------
__global__ void add_kernel(const float* __restrict__ a, const float* __restrict__ b,
                           float* __restrict__ o, float* __restrict__ o_r, int n4) {
    int idx = blockIdx.x * blockDim.x + threadIdx.x;
    int stride = gridDim.x * blockDim.x;
    const float4* a4 = (const float4*)a;
    const float4* b4 = (const float4*)b;
    float4* o4 = (float4*)o;
    float4* r4 = (float4*)o_r;
    for (int i = idx; i < n4; i += stride) {
        float4 x = a4[i], y = b4[i];
        x.x += y.x; x.y += y.y; x.z += y.z; x.w += y.w;
        o4[i] = x;
        float4 rr;
        rr.x = tf32rf(x.x); rr.y = tf32rf(x.y); rr.z = tf32rf(x.z); rr.w = tf32rf(x.w);
        r4[i] = rr;
    }
}

// ---------------- tensor-core attn KV (row stride ld) ----------------
__global__ __launch_bounds__(128) void attn_kv_tc(
    const float* __restrict__ Kg, const float* __restrict__ Vg, int ld,
    float* __restrict__ kvpart, float* __restrict__ kspart) {
    __shared__ uint32_t Kt[2][128 * KV_ASTR];
    __shared__ uint32_t Vs[2][BKD * BSTR];
    __shared__ float ksred[4][128];
    const uint32_t VsAddr = smem_u32(Vs);

    const int nh = blockIdx.x;
    const int split = blockIdx.y;
    const int n = nh >> 3, h = nh & 7;
    const int lbase = split * (LQ / KVSPLIT);
    const int tid = threadIdx.x;
    const int wid = tid >> 5, lane = tid & 31;
    const int wm = (wid & 1) * 64;
    const int wn = (wid >> 1) * 64;
    const int r = lane >> 2, cq = lane & 3;

    const int lrow = wid * 4 + (lane >> 3);
    const int dbase = (lane & 7) * 4;
    const size_t base = ((size_t)(n * LQ + lbase)) * ld + h * HD;

    float acc[4][8][4];
#pragma unroll
    for (int i = 0; i < 4; i++)
#pragma unroll
        for (int j = 0; j < 8; j++)
#pragma unroll
            for (int c = 0; c < 4; c++) acc[i][j][c] = 0.0f;
    float ksl[4][4];
#pragma unroll
    for (int i = 0; i < 4; i++)
#pragma unroll
        for (int j = 0; j < 4; j++) ksl[i][j] = 0.0f;

    float4 kreg[4];
    const int KT = (LQ / KVSPLIT) / BKD;

    auto ldgK = [&](int kt) {
#pragma unroll
        for (int i = 0; i < 4; i++)
            kreg[i] = *(const float4*)(Kg + base + (size_t)(kt * BKD + lrow) * ld + dbase + 32 * i);
    };
    auto stsK = [&](int buf) {
#pragma unroll
        for (int i = 0; i < 4; i++) {
            float fv[4] = {fmap(kreg[i].x), fmap(kreg[i].y), fmap(kreg[i].z), fmap(kreg[i].w)};
#pragma unroll
            for (int j = 0; j < 4; j++) {
                float rv = tf32rf(fv[j]);
                ksl[i][j] += rv;
                Kt[buf][(dbase + 32 * i + j) * KV_ASTR + lrow] = __float_as_uint(rv);
            }
        }
    };
    auto cpV = [&](int buf, int kt) {
#pragma unroll
        for (int i = 0; i < 4; i++) {
            int idx = tid + 128 * i;
            int kk = idx >> 5, n4 = (idx & 31) * 4;
            cp16(VsAddr + (buf * (BKD * BSTR) + kk * BSTR + n4) * 4,
                 Vg + base + (size_t)(kt * BKD + kk) * ld + n4);
        }
        asm volatile("cp.async.commit_group;" ::: "memory");
    };

    ldgK(0);
    cpV(0, 0);
    stsK(0);
    asm volatile("cp.async.wait_group 0;" ::: "memory");
    __syncthreads();

    for (int kt = 0; kt < KT; kt++) {
        const int buf = kt & 1;
        if (kt + 1 < KT) {
            cpV(buf ^ 1, kt + 1);
            ldgK(kt + 1);
        }
        const uint32_t* Asb = Kt[buf];
        const uint32_t* Bsb = Vs[buf];
#pragma unroll
        for (int s = 0; s < 2; s++) {
            uint32_t af[4][4];
#pragma unroll
            for (int i = 0; i < 4; i++) {
                const int arow = wm + 16 * i + r;
                const int kc = 8 * s + cq;
                af[i][0] = Asb[arow * KV_ASTR + kc];
                af[i][1] = Asb[(arow + 8) * KV_ASTR + kc];
                af[i][2] = Asb[arow * KV_ASTR + kc + 4];
                af[i][3] = Asb[(arow + 8) * KV_ASTR + kc + 4];
            }
            uint32_t bf[8][2];
#pragma unroll
            for (int j = 0; j < 8; j++) {
                const int ncol = wn + 8 * j + r;
                bf[j][0] = Bsb[(8 * s + cq) * BSTR + ncol];
                bf[j][1] = Bsb[(8 * s + cq + 4) * BSTR + ncol];
            }
#pragma unroll
            for (int i = 0; i < 4; i++)
#pragma unroll
                for (int j = 0; j < 8; j++)
                    mma_tf32(acc[i][j], af[i][0], af[i][1], af[i][2], af[i][3],
                             bf[j][0], bf[j][1]);
        }
        if (kt + 1 < KT) stsK(buf ^ 1);
        asm volatile("cp.async.wait_group 0;" ::: "memory");
        __syncthreads();
    }

    float* o = kvpart + (((size_t)(split * NHT + nh)) << 14);
#pragma unroll
    for (int i = 0; i < 4; i++) {
        const int row0 = wm + 16 * i + r;
#pragma unroll
        for (int j = 0; j < 8; j++) {
            const int col = wn + 8 * j + 2 * cq;
            float2 v0, v1;
            v0.x = acc[i][j][0]; v0.y = acc[i][j][1];
            v1.x = acc[i][j][2]; v1.y = acc[i][j][3];
            *(float2*)(o + (size_t)row0 * HD + col) = v0;
            *(float2*)(o + (size_t)(row0 + 8) * HD + col) = v1;
        }
    }

#pragma unroll
    for (int i = 0; i < 4; i++)
#pragma unroll
        for (int j = 0; j < 4; j++) {
            float v = ksl[i][j];
            v += __shfl_xor_sync(0xffffffffu, v, 8);
            v += __shfl_xor_sync(0xffffffffu, v, 16);
            ksl[i][j] = v;
        }
    if (lane < 8) {
#pragma unroll
        for (int i = 0; i < 4; i++)
#pragma unroll
            for (int j = 0; j < 4; j++)
                ksred[wid][32 * i + 4 * lane + j] = ksl[i][j];
    }
    __syncthreads();
    {
        int d = tid;
        float s = ksred[0][d] + ksred[1][d] + ksred[2][d] + ksred[3][d];
        kspart[(split * NHT + nh) * HD + d] = s;
    }
}

__global__ void kv_reduce_kernel(const float* __restrict__ part, float* __restrict__ kv) {
    int idx = blockIdx.x * 256 + threadIdx.x;
    if (idx < NHT * HD * HD) {
        int nh = idx >> 14;
        int i = idx & 16383;
        float s = 0.0f;
#pragma unroll
        for (int sp = 0; sp < KVSPLIT; sp++)
            s += part[(((size_t)(sp * NHT + nh)) << 14) + i];
        kv[idx] = tf32rf(s);
    }
}

__global__ void ks_reduce_kernel(const float* __restrict__ part, float* __restrict__ ks) {
    int idx = blockIdx.x * 128 + threadIdx.x;
    int nh = idx >> 7, d = idx & 127;
    float s = 0.0f;
#pragma unroll
    for (int sp = 0; sp < KVSPLIT; sp++)
        s += part[(sp * NHT + nh) * HD + d];
    ks[idx] = s;
}

// ---------------- tensor-core attn out (q row stride ldq) ----------------
__global__ __launch_bounds__(128) void attn_out_tc(
    const float* __restrict__ Qg, int ldq, const float* __restrict__ KV,
    const float* __restrict__ Ksum, float* __restrict__ Og) {
    __shared__ uint32_t Qs[2][128 * ASTR];
    __shared__ uint32_t Bs[2][BKD * BSTR];
    __shared__ float kss[HD];
    __shared__ float qks[128];
    const uint32_t BsAddr = smem_u32(Bs);

    const int nh = blockIdx.y;
    const int n = nh >> 3, h = nh & 7;
    const int l0 = blockIdx.x * 128;
    const int tid = threadIdx.x;
    const int wid = tid >> 5, lane = tid & 31;
    const int wm = (wid & 1) * 64;
    const int wn = (wid >> 1) * 64;
    const int r = lane >> 2, cq = lane & 3;

    kss[tid] = Ksum[nh * HD + tid];

    const size_t qbase = ((size_t)(n * LQ + l0)) * ldq + h * HD;
    const float* kvb = KV + ((size_t)nh << 14);

    const int qrow0 = tid >> 2;
    const int qc4 = (tid & 3) * 4;

    float acc[4][8][4];
#pragma unroll
    for (int i = 0; i < 4; i++)
#pragma unroll
        for (int j = 0; j < 8; j++)
#pragma unroll
            for (int c = 0; c < 4; c++) acc[i][j][c] = 0.0f;
    float qkp[4] = {0.f, 0.f, 0.f, 0.f};

    float4 qreg[4];
    const int KT = HD / BKD;

    auto ldgQ = [&](int kt) {
#pragma unroll
        for (int i = 0; i < 4; i++)
            qreg[i] = *(const float4*)(Qg + qbase + (size_t)(qrow0 + 32 * i) * ldq + kt * BKD + qc4);
    };
    auto stsQ = [&](int buf, int kt) {
#pragma unroll
        for (int i = 0; i < 4; i++) {
            float f0 = tf32rf(fmap(qreg[i].x));
            float f1 = tf32rf(fmap(qreg[i].y));
            float f2 = tf32rf(fmap(qreg[i].z));
            float f3 = tf32rf(fmap(qreg[i].w));
            const int dc = kt * BKD + qc4;
            qkp[i] += f0 * kss[dc] + f1 * kss[dc + 1] + f2 * kss[dc + 2] + f3 * kss[dc + 3];
            uint32_t* p = &Qs[buf][(qrow0 + 32 * i) * ASTR + qc4];
            p[0] = __float_as_uint(f0); p[1] = __float_as_uint(f1);
            p[2] = __float_as_uint(f2); p[3] = __float_as_uint(f3);
        }
    };
    auto cpB = [&](int buf, int kt) {
#pragma unroll
        for (int i = 0; i < 4; i++) {
            int idx = tid + 128 * i;
            int kk = idx >> 5, n4 = (idx & 31) * 4;
            cp16(BsAddr + (buf * (BKD * BSTR) + kk * BSTR + n4) * 4,
                 kvb + (size_t)(kt * BKD + kk) * HD + n4);
        }
        asm volatile("cp.async.commit_group;" ::: "memory");
    };

    ldgQ(0);
    cpB(0, 0);
    __syncthreads();   // kss visible to all warps before first stsQ
    stsQ(0, 0);
    asm volatile("cp.async.wait_group 0;" ::: "memory");
    __syncthreads();

    for (int kt = 0; kt < KT; kt++) {
        const int buf = kt & 1;
        if (kt + 1 < KT) {
            cpB(buf ^ 1, kt + 1);
            ldgQ(kt + 1);
        }
        const uint32_t* Asb = Qs[buf];
        const uint32_t* Bsb = Bs[buf];
#pragma unroll
        for (int s = 0; s < 2; s++) {
            uint32_t af[4][4];
#pragma unroll
            for (int i = 0; i < 4; i++) {
                const int arow = wm + 16 * i + r;
                const int kc = 8 * s + cq;
                af[i][0] = Asb[arow * ASTR + kc];
                af[i][1] = Asb[(arow + 8) * ASTR + kc];
                af[i][2] = Asb[arow * ASTR + kc + 4];
                af[i][3] = Asb[(arow + 8) * ASTR + kc + 4];
            }
            uint32_t bf[8][2];
#pragma unroll
            for (int j = 0; j < 8; j++) {
                const int ncol = wn + 8 * j + r;
                bf[j][0] = Bsb[(8 * s + cq) * BSTR + ncol];
                bf[j][1] = Bsb[(8 * s + cq + 4) * BSTR + ncol];
            }
#pragma unroll
            for (int i = 0; i < 4; i++)
#pragma unroll
                for (int j = 0; j < 8; j++)
                    mma_tf32(acc[i][j], af[i][0], af[i][1], af[i][2], af[i][3],
                             bf[j][0], bf[j][1]);
        }
        if (kt + 1 < KT) stsQ(buf ^ 1, kt + 1);
        asm volatile("cp.async.wait_group 0;" ::: "memory");
        __syncthreads();
    }

#pragma unroll
    for (int i = 0; i < 4; i++) {
        float v = qkp[i];
        v += __shfl_xor_sync(0xffffffffu, v, 1);
        v += __shfl_xor_sync(0xffffffffu, v, 2);
        if ((lane & 3) == 0) qks[qrow0 + 32 * i] = v;
    }
    __syncthreads();

#pragma unroll
    for (int i = 0; i < 4; i++) {
        const int row0 = wm + 16 * i + r;
        const float z0 = 1.0f / (qks[row0] + EPS_ATTN);
        const float z1 = 1.0f / (qks[row0 + 8] + EPS_ATTN);
        float* op0 = Og + ((size_t)(n * LQ + l0 + row0)) * CH + h * HD;
        float* op1 = Og + ((size_t)(n * LQ + l0 + row0 + 8)) * CH + h * HD;
#pragma unroll
        for (int j = 0; j < 8; j++) {
            const int col = wn + 8 * j + 2 * cq;
            float2 v0, v1;
            v0.x = tf32rf(acc[i][j][0] * z0); v0.y = tf32rf(acc[i][j][1] * z0);
            v1.x = tf32rf(acc[i][j][2] * z1); v1.y = tf32rf(acc[i][j][3] * z1);
            *(float2*)(op0 + col) = v0;
            *(float2*)(op1 + col) = v1;
        }
    }
}

// ---------------- fused residual + LayerNorm (+ optional rounded copy) ----------------
__global__ __launch_bounds__(256) void ln_res_kernel(
    const float* __restrict__ res, const float* __restrict__ y,
    const float* __restrict__ g, const float* __restrict__ b,
    float* __restrict__ out, float* __restrict__ out_r) {
    const int row = blockIdx.x;
    const int t = threadIdx.x;
    const size_t off = (size_t)row * CH + t * 4;
    float4 v = *(const float4*)(y + off);
    __shared__ float red[8];
    const int lane = t & 31, w = t >> 5;

    float s = v.x + v.y + v.z + v.w;
#pragma unroll
    for (int o = 16; o; o >>= 1) s += __shfl_xor_sync(0xffffffffu, s, o);
    if (!lane) red[w] = s;
    __syncthreads();
    float tot = red[0];
#pragma unroll
    for (int i = 1; i < 8; i++) tot += red[i];
    const float mean = tot * (1.0f / CH);

    float dx = v.x - mean, dy = v.y - mean, dz = v.z - mean, dw = v.w - mean;
    float sq = dx * dx + dy * dy + dz * dz + dw * dw;
    __syncthreads();
#pragma unroll
    for (int o = 16; o; o >>= 1) sq += __shfl_xor_sync(0xffffffffu, sq, o);
    if (!lane) red[w] = sq;
    __syncthreads();
    float vtot = red[0];
#pragma unroll
    for (int i = 1; i < 8; i++) vtot += red[i];
    const float rstd = rsqrtf(vtot * (1.0f / CH) + EPS_LN);

    float4 gv = *(const float4*)(g + t * 4);
    float4 bv = *(const float4*)(b + t * 4);
    float4 rv = *(const float4*)(res + off);
    float4 o;
    o.x = rv.x + dx * rstd * gv.x + bv.x;
    o.y = rv.y + dy * rstd * gv.y + bv.y;
    o.z = rv.z + dz * rstd * gv.z + bv.z;
    o.w = rv.w + dw * rstd * gv.w + bv.w;
    *(float4*)(out + off) = o;
    if (out_r) {
        float4 rr;
        rr.x = tf32rf(o.x); rr.y = tf32rf(o.y); rr.z = tf32rf(o.z); rr.w = tf32rf(o.w);
        *(float4*)(out_r + off) = rr;
    }
}

// ---------------- host orchestration ----------------
extern "C" void kernel_launch(void* const* d_in, const int* in_sizes, int n_in,
                              void* d_out, int out_size) {
    const float* depth   = (const float*)d_in[0];
    const float* context = (const float*)d_in[1];
    const float* pos     = (const float*)d_in[2];
    const float* e_wq = (const float*)d_in[3];
    const float* e_wk = (const float*)d_in[4];
    const float* e_wv = (const float*)d_in[5];
    const float* e_wm = (const float*)d_in[6];
    const float* e_w1 = (const float*)d_in[7];
    const float* e_w2 = (const float*)d_in[8];
    const float* e_g1 = (const float*)d_in[9];
    const float* e_b1 = (const float*)d_in[10];
    const float* e_g2 = (const float*)d_in[11];
    const float* e_b2 = (const float*)d_in[12];
    const float* d_wq0 = (const float*)d_in[13];
    const float* d_wk0 = (const float*)d_in[14];
    const float* d_wv0 = (const float*)d_in[15];
    const float* d_wm0 = (const float*)d_in[16];
    const float* d_wq1 = (const float*)d_in[17];
    const float* d_wk1 = (const float*)d_in[18];
    const float* d_wv1 = (const float*)d_in[19];
    const float* d_wm1 = (const float*)d_in[20];
    const float* d_w1 = (const float*)d_in[21];
    const float* d_w2 = (const float*)d_in[22];
    const float* d_g0 = (const float*)d_in[23];
    const float* d_b0 = (const float*)d_in[24];
    const float* d_g1 = (const float*)d_in[25];
    const float* d_b1 = (const float*)d_in[26];
    const float* d_g2 = (const float*)d_in[27];
    const float* d_b2 = (const float*)d_in[28];
    float* out = (float*)d_out;

    float *ctx, *ctxr, *q, *qkv, *attn, *msg, *x, *xr, *yb, *ybr, *hb;
    float *depr, *wt, *kvp, *kv, *ksp, *ks;
    cudaGetSymbolAddress((void**)&ctx,  g_ctx);
    cudaGetSymbolAddress((void**)&ctxr, g_ctx_r);
    cudaGetSymbolAddress((void**)&q,    g_q);
    cudaGetSymbolAddress((void**)&qkv,  g_qkv);
    cudaGetSymbolAddress((void**)&attn, g_attn);
    cudaGetSymbolAddress((void**)&msg,  g_msg);
    cudaGetSymbolAddress((void**)&x,    g_x);
    cudaGetSymbolAddress((void**)&xr,   g_x_r);
    cudaGetSymbolAddress((void**)&yb,   g_y);
    cudaGetSymbolAddress((void**)&ybr,  g_y_r);
    cudaGetSymbolAddress((void**)&hb,   g_h);
    cudaGetSymbolAddress((void**)&depr, g_depth_r);
    cudaGetSymbolAddress((void**)&wt,   g_wt);
    cudaGetSymbolAddress((void**)&kvp,  g_kvpart);
    cudaGetSymbolAddress((void**)&kv,   g_kv);
    cudaGetSymbolAddress((void**)&ksp,  g_kspart);
    cudaGetSymbolAddress((void**)&ks,   g_ksum);

    cudaFuncSetAttribute(gemm_mma<false, false>, cudaFuncAttributeMaxDynamicSharedMemorySize, GEMM_SMEM2);
    cudaFuncSetAttribute(gemm_mma<false, true>,  cudaFuncAttributeMaxDynamicSharedMemorySize, GEMM_SMEM2);
    cudaFuncSetAttribute(gemm_mma<true, true>,   cudaFuncAttributeMaxDynamicSharedMemorySize, GEMM_SMEM2);

    // weight scratch layout (floats)
    const size_t M1 = 1024 * 1024;
    float* w_qkvE = wt;               // [1024][3072]
    float* w_qkvD = wt + 3 * M1;      // [1024][3072]
    float* w_kvD1 = wt + 6 * M1;      // [1024][2048]
    float* w_q1   = wt + 8 * M1;      // [1024][1024]
    float* w_em   = wt + 9 * M1;
    float* w_dm0  = wt + 10 * M1;
    float* w_dm1  = wt + 11 * M1;
    float* w_e1   = wt + 12 * M1;     // [1024][2048]
    float* w_d1   = wt + 14 * M1;
    float* w_e2   = wt + 16 * M1;     // [2048][1024]
    float* w_d2   = wt + 18 * M1;

    RCArgs rc;
    const int SQ4 = (int)(M1 / 4), R24 = (int)(M1 / 2);
    auto seg = [&](int i, const float* s, float* d, int n4, int ds) {
        rc.src[i] = (const float4*)s; rc.dst[i] = (float4*)d;
        rc.n4[i] = n4; rc.dstride4[i] = ds;
    };
    seg(0,  e_wq,  w_qkvE,        SQ4, 768);
    seg(1,  e_wk,  w_qkvE + 1024, SQ4, 768);
    seg(2,  e_wv,  w_qkvE + 2048, SQ4, 768);
    seg(3,  d_wq0, w_qkvD,        SQ4, 768);
    seg(4,  d_wk0, w_qkvD + 1024, SQ4, 768);
    seg(5,  d_wv0, w_qkvD + 2048, SQ4, 768);
    seg(6,  d_wk1, w_kvD1,        SQ4, 512);
    seg(7,  d_wv1, w_kvD1 + 1024, SQ4, 512);
    seg(8,  d_wq1, w_q1,  SQ4, 0);
    seg(9,  e_wm,  w_em,  SQ4, 0);
    seg(10, d_wm0, w_dm0, SQ4, 0);
    seg(11, d_wm1, w_dm1, SQ4, 0);
    seg(12, e_w1, w_e1, R24, 0);
    seg(13, d_w1, w_d1, R24, 0);
    seg(14, e_w2, w_e2, R24, 0);
    seg(15, d_w2, w_d2, R24, 0);
    seg(16, depth, depr, NL * CH / 4, 0);
    round_copy_multi<<<dim3(256, 17), 256>>>(rc);

    const dim3 blk(256);
    const dim3 gblk(128);
    const dim3 gU(CH / 128, NL / 128);          // N=1024
    const dim3 gF(2 * CH / 128, NL / 128);      // N=2048
    const dim3 gQKV(3 * CH / 128, NL / 128);    // N=3072

    auto attention = [&](const float* qp, int ldq, const float* kp, const float* vp, int ldkv) {
        attn_kv_tc<<<dim3(NHT, KVSPLIT), gblk>>>(kp, vp, ldkv, kvp, ksp);
        kv_reduce_kernel<<<(NHT * HD * HD + 255) / 256, blk>>>(kvp, kv);
        ks_reduce_kernel<<<NHT, 128>>>(ksp, ks);
        attn_out_tc<<<dim3(LQ / 128, NHT), gblk>>>(qp, ldq, kv, ks, attn);
    };

    // ===== encoder =====
    add_kernel<<<2048, blk>>>(context, pos, ctx, ctxr, NL * CH / 4);
    gemm_mma<false, true><<<gQKV, gblk, GEMM_SMEM2>>>(ctxr, w_qkvE, qkv, NL, CH, 3 * CH);
    attention(qkv, 3 * CH, qkv + CH, qkv + 2 * CH, 3 * CH);
    gemm_mma<false, false><<<gU, gblk, GEMM_SMEM2>>>(attn, w_em, msg, NL, CH, CH);
    ln_res_kernel<<<NL, blk>>>(ctx, msg, e_g1, e_b1, x, xr);
    gemm_mma<true, true><<<gF, gblk, GEMM_SMEM2>>>(xr, w_e1, hb, NL, CH, 2 * CH);
    gemm_mma<false, false><<<gU, gblk, GEMM_SMEM2>>>(hb, w_e2, msg, NL, 2 * CH, CH);
    ln_res_kernel<<<NL, blk>>>(x, msg, e_g2, e_b2, ctx, ctxr);

    // ===== decoder: self-attention =====
    gemm_mma<false, true><<<gQKV, gblk, GEMM_SMEM2>>>(depr, w_qkvD, qkv, NL, CH, 3 * CH);
    attention(qkv, 3 * CH, qkv + CH, qkv + 2 * CH, 3 * CH);
    gemm_mma<false, false><<<gU, gblk, GEMM_SMEM2>>>(attn, w_dm0, msg, NL, CH, CH);
    ln_res_kernel<<<NL, blk>>>(depth, msg, d_g0, d_b0, x, xr);

    // ===== decoder: cross-attention =====
    gemm_mma<false, false><<<gU, gblk, GEMM_SMEM2>>>(xr, w_q1, q, NL, CH, CH);
    gemm_mma<false, true><<<gF, gblk, GEMM_SMEM2>>>(ctxr, w_kvD1, hb, NL, CH, 2 * CH);
    attention(q, CH, hb, hb + CH, 2 * CH);
    gemm_mma<false, false><<<gU, gblk, GEMM_SMEM2>>>(attn, w_dm1, msg, NL, CH, CH);
    ln_res_kernel<<<NL, blk>>>(x, msg, d_g1, d_b1, yb, ybr);

    // ===== decoder: FFN =====
    gemm_mma<true, true><<<gF, gblk, GEMM_SMEM2>>>(ybr, w_d1, hb, NL, CH, 2 * CH);
    gemm_mma<false, false><<<gU, gblk, GEMM_SMEM2>>>(hb, w_d2, msg, NL, 2 * CH, CH);
    ln_res_kernel<<<NL, blk>>>(yb, msg, d_g2, d_b2, out, nullptr);
}

// round 11
// speedup vs baseline: 6.5065x; 1.6243x over previous
#include <cuda_runtime.h>
#include <cuda_fp16.h>
#include <cstdint>
#include <math.h>

#define NB 4
#define LQ 2048
#define CH 1024
#define NHD 8
#define HD 128
#define NL (NB * LQ)
#define NHT (NB * NHD)
#define KVSPLIT 8
#define EPS_ATTN 1e-6f
#define EPS_LN 1e-5f

// attention tiles (tf32 path, unchanged)
#define BKD 16
#define ASTR 20
#define BSTR 136
#define KV_ASTR 17

// fp16 GEMM tiles: 64 halves (32 words) per stage, 2 stages, 3 CTAs/SM
#define ASTR2 36
#define A2_WORDS (128 * ASTR2)            // 4608
#define B2_WORDS (32 * BSTR)              // 4352
#define STG2_WORDS (A2_WORDS + B2_WORDS)  // 8960
#define GEMM_SMEM2 (2 * STG2_WORDS * 4)   // 71680

// ---------------- scratch ----------------
__device__ float g_ctx[NL * CH];
__device__ float g_q[NL * CH];
__device__ float g_qkv[NL * 3 * CH];
__device__ float g_msg[NL * CH];
__device__ float g_x[NL * CH];
__device__ float g_y[NL * CH];
__device__ float g_h[NL * 2 * CH];          // cross-attn K/V (fp32)
__device__ __half g_ctxh[NL * CH];
__device__ __half g_xh[NL * CH];
__device__ __half g_yh[NL * CH];
__device__ __half g_attnh[NL * CH];
__device__ __half g_deph[NL * CH];
__device__ __half g_hh[NL * 2 * CH];        // FFN hidden (fp16)
__device__ uint32_t g_wt[12 * 1024 * 1024]; // packed fp16 weights (half2 words)
__device__ float g_kvpart[KVSPLIT * NHT * HD * HD];
__device__ float g_kv[NHT * HD * HD];
__device__ float g_kspart[KVSPLIT * NHT * HD];
__device__ float g_ksum[NHT * HD];

__device__ __forceinline__ float fmap(float x) { return x > 0.0f ? x + 1.0f : expf(x); }

__device__ __forceinline__ float tf32rf(float x) {
    uint32_t u;
    asm("cvt.rna.tf32.f32 %0, %1;" : "=r"(u) : "f"(x));
    return __uint_as_float(u);
}

__device__ __forceinline__ void cp16(uint32_t saddr, const void* g) {
    asm volatile("cp.async.cg.shared.global [%0], [%1], 16;" :: "r"(saddr), "l"(g));
}

__device__ __forceinline__ uint32_t smem_u32(const void* p) {
    uint32_t a;
    asm("{ .reg .u64 t; cvta.to.shared.u64 t, %1; cvt.u32.u64 %0, t; }" : "=r"(a) : "l"(p));
    return a;
}

__device__ __forceinline__ void mma_tf32(float* d,
                                         uint32_t a0, uint32_t a1, uint32_t a2, uint32_t a3,
                                         uint32_t b0, uint32_t b1) {
    asm volatile(
        "mma.sync.aligned.m16n8k8.row.col.f32.tf32.tf32.f32 "
        "{%0,%1,%2,%3}, {%4,%5,%6,%7}, {%8,%9}, {%0,%1,%2,%3};"
        : "+f"(d[0]), "+f"(d[1]), "+f"(d[2]), "+f"(d[3])
        : "r"(a0), "r"(a1), "r"(a2), "r"(a3), "r"(b0), "r"(b1));
}

__device__ __forceinline__ void mma_f16(float* d,
                                        uint32_t a0, uint32_t a1, uint32_t a2, uint32_t a3,
                                        uint32_t b0, uint32_t b1) {
    asm volatile(
        "mma.sync.aligned.m16n8k16.row.col.f32.f16.f16.f32 "
        "{%0,%1,%2,%3}, {%4,%5,%6,%7}, {%8,%9}, {%0,%1,%2,%3};"
        : "+f"(d[0]), "+f"(d[1]), "+f"(d[2]), "+f"(d[3])
        : "r"(a0), "r"(a1), "r"(a2), "r"(a3), "r"(b0), "r"(b1));
}

// ---------------- weight pack: fp32 [K][N] -> half2 words [K/2][ostride] ----------------
// 17 segments; seg with lgN=0 is a flat fp32->fp16 pair convert (for activations).
struct PKArgs {
    const float* src[17];
    uint32_t* dst[17];
    int total[17];     // (K/2)*N words
    int lgN[17];
    int ostride[17];   // words per output k2-row
    int colofs[17];
};
__global__ void pack_w(PKArgs a) {
    const int seg = blockIdx.y;
    const float* __restrict__ s = a.src[seg];
    uint32_t* __restrict__ d = a.dst[seg];
    const int total = a.total[seg];
    const int lg = a.lgN[seg];
    const int Nm = (1 << lg) - 1;
    const int ostr = a.ostride[seg];
    const int co = a.colofs[seg];
    int idx = blockIdx.x * blockDim.x + threadIdx.x;
    int stride = gridDim.x * blockDim.x;
    for (int i = idx; i < total; i += stride) {
        int n = i & Nm;
        int k2 = i >> lg;
        size_t slo = ((size_t)k2 << (lg + 1)) + n;
        float lo = s[slo];
        float hi = s[slo + (1 << lg)];
        __half2 h = __floats2half2_rn(lo, hi);
        d[(size_t)k2 * ostr + co + n] = *(uint32_t*)&h;
    }
}

// ---------------- fp16 tensor-core GEMM (cp.async 2-stage, 64 halves/stage, 3 CTAs/SM) ----
// A: fp16 row-major [M][2*Kw] as words; B: packed [Kw][Nn] words. OUTM: 0=f32, 1=f32 tf32-rnd, 2=f16
template <bool RELU, int OUTM>
__global__ __launch_bounds__(128, 3) void gemm_h(
    const uint32_t* __restrict__ Aw, const uint32_t* __restrict__ Bw, void* __restrict__ Cout,
    int M, int Kw, int Nn) {
    extern __shared__ uint32_t sm[];
    const uint32_t smaddr = smem_u32(sm);
    const int tid = threadIdx.x;
    const int wid = tid >> 5, lane = tid & 31;
    const int bm = blockIdx.y * 128;
    const int bn = blockIdx.x * 128;
    const int wm = (wid & 1) * 64;
    const int wn = (wid >> 1) * 64;
    const int r = lane >> 2, cq = lane & 3;

    float acc[4][8][4];
#pragma unroll
    for (int i = 0; i < 4; i++)
#pragma unroll
        for (int j = 0; j < 8; j++)
#pragma unroll
            for (int c = 0; c < 4; c++) acc[i][j][c] = 0.0f;

    const int KT = Kw / 32;

    auto issue = [&](int s, int kt) {
        const uint32_t sbA = smaddr + s * (STG2_WORDS * 4);
        const uint32_t* Ag = Aw + (size_t)bm * Kw + (size_t)kt * 32;
#pragma unroll
        for (int i = 0; i < 8; i++) {
            int idx = tid + 128 * i;
            int row = idx >> 3, c4 = (idx & 7) * 4;
            cp16(sbA + (row * ASTR2 + c4) * 4, Ag + (size_t)row * Kw + c4);
        }
        const uint32_t sbB = sbA + A2_WORDS * 4;
        const uint32_t* Bg = Bw + (size_t)(kt * 32) * Nn + bn;
#pragma unroll
        for (int i = 0; i < 8; i++) {
            int idx = tid + 128 * i;
            int kk = idx >> 5, n4 = (idx & 31) * 4;
            cp16(sbB + (kk * BSTR + n4) * 4, Bg + (size_t)kk * Nn + n4);
        }
        asm volatile("cp.async.commit_group;" ::: "memory");
    };

    issue(0, 0);

    for (int kt = 0; kt < KT; kt++) {
        const int buf = kt & 1;
        asm volatile("cp.async.wait_group 0;" ::: "memory");
        __syncthreads();
        if (kt + 1 < KT) issue(buf ^ 1, kt + 1);

        const uint32_t* Asb = sm + buf * STG2_WORDS;
        const uint32_t* Bsb = Asb + A2_WORDS;
#pragma unroll
        for (int s = 0; s < 4; s++) {
            uint32_t af[4][4];
#pragma unroll
            for (int i = 0; i < 4; i++) {
                const int arow = wm + 16 * i + r;
                const int kc = 8 * s + cq;
                af[i][0] = Asb[arow * ASTR2 + kc];
                af[i][1] = Asb[(arow + 8) * ASTR2 + kc];
                af[i][2] = Asb[arow * ASTR2 + kc + 4];
                af[i][3] = Asb[(arow + 8) * ASTR2 + kc + 4];
            }
            uint32_t bf[8][2];
#pragma unroll
            for (int j = 0; j < 8; j++) {
                const int ncol = wn + 8 * j + r;
                bf[j][0] = Bsb[(8 * s + cq) * BSTR + ncol];
                bf[j][1] = Bsb[(8 * s + cq + 4) * BSTR + ncol];
            }
#pragma unroll
            for (int i = 0; i < 4; i++)
#pragma unroll
                for (int j = 0; j < 8; j++)
                    mma_f16(acc[i][j], af[i][0], af[i][1], af[i][2], af[i][3],
                            bf[j][0], bf[j][1]);
        }
    }

#pragma unroll
    for (int i = 0; i < 4; i++) {
        const int row0 = bm + wm + 16 * i + r;
#pragma unroll
        for (int j = 0; j < 8; j++) {
            const int col = bn + wn + 8 * j + 2 * cq;
            float v[4] = {acc[i][j][0], acc[i][j][1], acc[i][j][2], acc[i][j][3]};
            if (RELU) {
#pragma unroll
                for (int c = 0; c < 4; c++) v[c] = fmaxf(v[c], 0.f);
            }
            if (OUTM == 2) {
                __half* Ch = (__half*)Cout;
                __half2 h0 = __floats2half2_rn(v[0], v[1]);
                __half2 h1 = __floats2half2_rn(v[2], v[3]);
                *(__half2*)(Ch + (size_t)row0 * Nn + col) = h0;
                *(__half2*)(Ch + (size_t)(row0 + 8) * Nn + col) = h1;
            } else {
                if (OUTM == 1) {
#pragma unroll
                    for (int c = 0; c < 4; c++) v[c] = tf32rf(v[c]);
                }
                float* Cf = (float*)Cout;
                float2 v0, v1;
                v0.x = v[0]; v0.y = v[1]; v1.x = v[2]; v1.y = v[3];
                *(float2*)(Cf + (size_t)row0 * Nn + col) = v0;
                *(float2*)(Cf + (size_t)(row0 + 8) * Nn + col) = v1;
            }
        }
    }
}

// ---------------- elementwise add (fp32 out + fp16 copy) ----------------
__global__ void add_kernel(const float* __restrict__ a, const float* __restrict__ b,
                           float* __restrict__ o, __half* __restrict__ oh, int n4) {
    int idx = blockIdx.x * blockDim.x + threadIdx.x;
    int stride = gridDim.x * blockDim.x;
    const float4* a4 = (const float4*)a;
    const float4* b4 = (const float4*)b;
    float4* o4 = (float4*)o;
    for (int i = idx; i < n4; i += stride) {
        float4 x = a4[i], y = b4[i];
        x.x += y.x; x.y += y.y; x.z += y.z; x.w += y.w;
        o4[i] = x;
        __half2 h0 = __floats2half2_rn(x.x, x.y);
        __half2 h1 = __floats2half2_rn(x.z, x.w);
        uint2 u;
        u.x = *(uint32_t*)&h0; u.y = *(uint32_t*)&h1;
        *(uint2*)(oh + (size_t)i * 4) = u;
    }
}

// ---------------- tensor-core attn KV (tf32, row stride ld) ----------------
__global__ __launch_bounds__(128) void attn_kv_tc(
    const float* __restrict__ Kg, const float* __restrict__ Vg, int ld,
    float* __restrict__ kvpart, float* __restrict__ kspart) {
    __shared__ uint32_t Kt[2][128 * KV_ASTR];
    __shared__ uint32_t Vs[2][BKD * BSTR];
    __shared__ float ksred[4][128];
    const uint32_t VsAddr = smem_u32(Vs);

    const int nh = blockIdx.x;
    const int split = blockIdx.y;
    const int n = nh >> 3, h = nh & 7;
    const int lbase = split * (LQ / KVSPLIT);
    const int tid = threadIdx.x;
    const int wid = tid >> 5, lane = tid & 31;
    const int wm = (wid & 1) * 64;
    const int wn = (wid >> 1) * 64;
    const int r = lane >> 2, cq = lane & 3;

    const int lrow = wid * 4 + (lane >> 3);
    const int dbase = (lane & 7) * 4;
    const size_t base = ((size_t)(n * LQ + lbase)) * ld + h * HD;

    float acc[4][8][4];
#pragma unroll
    for (int i = 0; i < 4; i++)
#pragma unroll
        for (int j = 0; j < 8; j++)
#pragma unroll
            for (int c = 0; c < 4; c++) acc[i][j][c] = 0.0f;
    float ksl[4][4];
#pragma unroll
    for (int i = 0; i < 4; i++)
#pragma unroll
        for (int j = 0; j < 4; j++) ksl[i][j] = 0.0f;

    float4 kreg[4];
    const int KT = (LQ / KVSPLIT) / BKD;

    auto ldgK = [&](int kt) {
#pragma unroll
        for (int i = 0; i < 4; i++)
            kreg[i] = *(const float4*)(Kg + base + (size_t)(kt * BKD + lrow) * ld + dbase + 32 * i);
    };
    auto stsK = [&](int buf) {
#pragma unroll
        for (int i = 0; i < 4; i++) {
            float fv[4] = {fmap(kreg[i].x), fmap(kreg[i].y), fmap(kreg[i].z), fmap(kreg[i].w)};
#pragma unroll
            for (int j = 0; j < 4; j++) {
                float rv = tf32rf(fv[j]);
                ksl[i][j] += rv;
                Kt[buf][(dbase + 32 * i + j) * KV_ASTR + lrow] = __float_as_uint(rv);
            }
        }
    };
    auto cpV = [&](int buf, int kt) {
#pragma unroll
        for (int i = 0; i < 4; i++) {
            int idx = tid + 128 * i;
            int kk = idx >> 5, n4 = (idx & 31) * 4;
            cp16(VsAddr + (buf * (BKD * BSTR) + kk * BSTR + n4) * 4,
                 Vg + base + (size_t)(kt * BKD + kk) * ld + n4);
        }
        asm volatile("cp.async.commit_group;" ::: "memory");
    };

    ldgK(0);
    cpV(0, 0);
    stsK(0);
    asm volatile("cp.async.wait_group 0;" ::: "memory");
    __syncthreads();

    for (int kt = 0; kt < KT; kt++) {
        const int buf = kt & 1;
        if (kt + 1 < KT) {
            cpV(buf ^ 1, kt + 1);
            ldgK(kt + 1);
        }
        const uint32_t* Asb = Kt[buf];
        const uint32_t* Bsb = Vs[buf];
#pragma unroll
        for (int s = 0; s < 2; s++) {
            uint32_t af[4][4];
#pragma unroll
            for (int i = 0; i < 4; i++) {
                const int arow = wm + 16 * i + r;
                const int kc = 8 * s + cq;
                af[i][0] = Asb[arow * KV_ASTR + kc];
                af[i][1] = Asb[(arow + 8) * KV_ASTR + kc];
                af[i][2] = Asb[arow * KV_ASTR + kc + 4];
                af[i][3] = Asb[(arow + 8) * KV_ASTR + kc + 4];
            }
            uint32_t bf[8][2];
#pragma unroll
            for (int j = 0; j < 8; j++) {
                const int ncol = wn + 8 * j + r;
                bf[j][0] = Bsb[(8 * s + cq) * BSTR + ncol];
                bf[j][1] = Bsb[(8 * s + cq + 4) * BSTR + ncol];
            }
#pragma unroll
            for (int i = 0; i < 4; i++)
#pragma unroll
                for (int j = 0; j < 8; j++)
                    mma_tf32(acc[i][j], af[i][0], af[i][1], af[i][2], af[i][3],
                             bf[j][0], bf[j][1]);
        }
        if (kt + 1 < KT) stsK(buf ^ 1);
        asm volatile("cp.async.wait_group 0;" ::: "memory");
        __syncthreads();
    }

    float* o = kvpart + (((size_t)(split * NHT + nh)) << 14);
#pragma unroll
    for (int i = 0; i < 4; i++) {
        const int row0 = wm + 16 * i + r;
#pragma unroll
        for (int j = 0; j < 8; j++) {
            const int col = wn + 8 * j + 2 * cq;
            float2 v0, v1;
            v0.x = acc[i][j][0]; v0.y = acc[i][j][1];
            v1.x = acc[i][j][2]; v1.y = acc[i][j][3];
            *(float2*)(o + (size_t)row0 * HD + col) = v0;
            *(float2*)(o + (size_t)(row0 + 8) * HD + col) = v1;
        }
    }

#pragma unroll
    for (int i = 0; i < 4; i++)
#pragma unroll
        for (int j = 0; j < 4; j++) {
            float v = ksl[i][j];
            v += __shfl_xor_sync(0xffffffffu, v, 8);
            v += __shfl_xor_sync(0xffffffffu, v, 16);
            ksl[i][j] = v;
        }
    if (lane < 8) {
#pragma unroll
        for (int i = 0; i < 4; i++)
#pragma unroll
            for (int j = 0; j < 4; j++)
                ksred[wid][32 * i + 4 * lane + j] = ksl[i][j];
    }
    __syncthreads();
    {
        int d = tid;
        float s = ksred[0][d] + ksred[1][d] + ksred[2][d] + ksred[3][d];
        kspart[(split * NHT + nh) * HD + d] = s;
    }
}

__global__ void kv_reduce_kernel(const float* __restrict__ part, float* __restrict__ kv) {
    int idx = blockIdx.x * 256 + threadIdx.x;
    if (idx < NHT * HD * HD) {
        int nh = idx >> 14;
        int i = idx & 16383;
        float s = 0.0f;
#pragma unroll
        for (int sp = 0; sp < KVSPLIT; sp++)
            s += part[(((size_t)(sp * NHT + nh)) << 14) + i];
        kv[idx] = tf32rf(s);
    }
}

__global__ void ks_reduce_kernel(const float* __restrict__ part, float* __restrict__ ks) {
    int idx = blockIdx.x * 128 + threadIdx.x;
    int nh = idx >> 7, d = idx & 127;
    float s = 0.0f;
#pragma unroll
    for (int sp = 0; sp < KVSPLIT; sp++)
        s += part[(sp * NHT + nh) * HD + d];
    ks[idx] = s;
}

// ---------------- tensor-core attn out (tf32; fp16 output) ----------------
__global__ __launch_bounds__(128) void attn_out_tc(
    const float* __restrict__ Qg, int ldq, const float* __restrict__ KV,
    const float* __restrict__ Ksum, __half* __restrict__ Og) {
    __shared__ uint32_t Qs[2][128 * ASTR];
    __shared__ uint32_t Bs[2][BKD * BSTR];
    __shared__ float kss[HD];
    __shared__ float qks[128];
    const uint32_t BsAddr = smem_u32(Bs);

    const int nh = blockIdx.y;
    const int n = nh >> 3, h = nh & 7;
    const int l0 = blockIdx.x * 128;
    const int tid = threadIdx.x;
    const int wid = tid >> 5, lane = tid & 31;
    const int wm = (wid & 1) * 64;
    const int wn = (wid >> 1) * 64;
    const int r = lane >> 2, cq = lane & 3;

    kss[tid] = Ksum[nh * HD + tid];

    const size_t qbase = ((size_t)(n * LQ + l0)) * ldq + h * HD;
    const float* kvb = KV + ((size_t)nh << 14);

    const int qrow0 = tid >> 2;
    const int qc4 = (tid & 3) * 4;

    float acc[4][8][4];
#pragma unroll
    for (int i = 0; i < 4; i++)
#pragma unroll
        for (int j = 0; j < 8; j++)
#pragma unroll
            for (int c = 0; c < 4; c++) acc[i][j][c] = 0.0f;
    float qkp[4] = {0.f, 0.f, 0.f, 0.f};

    float4 qreg[4];
    const int KT = HD / BKD;

    auto ldgQ = [&](int kt) {
#pragma unroll
        for (int i = 0; i < 4; i++)
            qreg[i] = *(const float4*)(Qg + qbase + (size_t)(qrow0 + 32 * i) * ldq + kt * BKD + qc4);
    };
    auto stsQ = [&](int buf, int kt) {
#pragma unroll
        for (int i = 0; i < 4; i++) {
            float f0 = tf32rf(fmap(qreg[i].x));
            float f1 = tf32rf(fmap(qreg[i].y));
            float f2 = tf32rf(fmap(qreg[i].z));
            float f3 = tf32rf(fmap(qreg[i].w));
            const int dc = kt * BKD + qc4;
            qkp[i] += f0 * kss[dc] + f1 * kss[dc + 1] + f2 * kss[dc + 2] + f3 * kss[dc + 3];
            uint32_t* p = &Qs[buf][(qrow0 + 32 * i) * ASTR + qc4];
            p[0] = __float_as_uint(f0); p[1] = __float_as_uint(f1);
            p[2] = __float_as_uint(f2); p[3] = __float_as_uint(f3);
        }
    };
    auto cpB = [&](int buf, int kt) {
#pragma unroll
        for (int i = 0; i < 4; i++) {
            int idx = tid + 128 * i;
            int kk = idx >> 5, n4 = (idx & 31) * 4;
            cp16(BsAddr + (buf * (BKD * BSTR) + kk * BSTR + n4) * 4,
                 kvb + (size_t)(kt * BKD + kk) * HD + n4);
        }
        asm volatile("cp.async.commit_group;" ::: "memory");
    };

    ldgQ(0);
    cpB(0, 0);
    __syncthreads();   // kss visible before first stsQ
    stsQ(0, 0);
    asm volatile("cp.async.wait_group 0;" ::: "memory");
    __syncthreads();

    for (int kt = 0; kt < KT; kt++) {
        const int buf = kt & 1;
        if (kt + 1 < KT) {
            cpB(buf ^ 1, kt + 1);
            ldgQ(kt + 1);
        }
        const uint32_t* Asb = Qs[buf];
        const uint32_t* Bsb = Bs[buf];
#pragma unroll
        for (int s = 0; s < 2; s++) {
            uint32_t af[4][4];
#pragma unroll
            for (int i = 0; i < 4; i++) {
                const int arow = wm + 16 * i + r;
                const int kc = 8 * s + cq;
                af[i][0] = Asb[arow * ASTR + kc];
                af[i][1] = Asb[(arow + 8) * ASTR + kc];
                af[i][2] = Asb[arow * ASTR + kc + 4];
                af[i][3] = Asb[(arow + 8) * ASTR + kc + 4];
            }
            uint32_t bf[8][2];
#pragma unroll
            for (int j = 0; j < 8; j++) {
                const int ncol = wn + 8 * j + r;
                bf[j][0] = Bsb[(8 * s + cq) * BSTR + ncol];
                bf[j][1] = Bsb[(8 * s + cq + 4) * BSTR + ncol];
            }
#pragma unroll
            for (int i = 0; i < 4; i++)
#pragma unroll
                for (int j = 0; j < 8; j++)
                    mma_tf32(acc[i][j], af[i][0], af[i][1], af[i][2], af[i][3],
                             bf[j][0], bf[j][1]);
        }
        if (kt + 1 < KT) stsQ(buf ^ 1, kt + 1);
        asm volatile("cp.async.wait_group 0;" ::: "memory");
        __syncthreads();
    }

#pragma unroll
    for (int i = 0; i < 4; i++) {
        float v = qkp[i];
        v += __shfl_xor_sync(0xffffffffu, v, 1);
        v += __shfl_xor_sync(0xffffffffu, v, 2);
        if ((lane & 3) == 0) qks[qrow0 + 32 * i] = v;
    }
    __syncthreads();

#pragma unroll
    for (int i = 0; i < 4; i++) {
        const int row0 = wm + 16 * i + r;
        const float z0 = 1.0f / (qks[row0] + EPS_ATTN);
        const float z1 = 1.0f / (qks[row0 + 8] + EPS_ATTN);
        __half* op0 = Og + ((size_t)(n * LQ + l0 + row0)) * CH + h * HD;
        __half* op1 = Og + ((size_t)(n * LQ + l0 + row0 + 8)) * CH + h * HD;
#pragma unroll
        for (int j = 0; j < 8; j++) {
            const int col = wn + 8 * j + 2 * cq;
            __half2 h0 = __floats2half2_rn(acc[i][j][0] * z0, acc[i][j][1] * z0);
            __half2 h1 = __floats2half2_rn(acc[i][j][2] * z1, acc[i][j][3] * z1);
            *(__half2*)(op0 + col) = h0;
            *(__half2*)(op1 + col) = h1;
        }
    }
}

// ---------------- fused residual + LayerNorm (fp32 out + optional fp16 copy) ----------------
__global__ __launch_bounds__(256) void ln_res_kernel(
    const float* __restrict__ res, const float* __restrict__ y,
    const float* __restrict__ g, const float* __restrict__ b,
    float* __restrict__ out, __half* __restrict__ out_h) {
    const int row = blockIdx.x;
    const int t = threadIdx.x;
    const size_t off = (size_t)row * CH + t * 4;
    float4 v = *(const float4*)(y + off);
    __shared__ float red[8];
    const int lane = t & 31, w = t >> 5;

    float s = v.x + v.y + v.z + v.w;
#pragma unroll
    for (int o = 16; o; o >>= 1) s += __shfl_xor_sync(0xffffffffu, s, o);
    if (!lane) red[w] = s;
    __syncthreads();
    float tot = red[0];
#pragma unroll
    for (int i = 1; i < 8; i++) tot += red[i];
    const float mean = tot * (1.0f / CH);

    float dx = v.x - mean, dy = v.y - mean, dz = v.z - mean, dw = v.w - mean;
    float sq = dx * dx + dy * dy + dz * dz + dw * dw;
    __syncthreads();
#pragma unroll
    for (int o = 16; o; o >>= 1) sq += __shfl_xor_sync(0xffffffffu, sq, o);
    if (!lane) red[w] = sq;
    __syncthreads();
    float vtot = red[0];
#pragma unroll
    for (int i = 1; i < 8; i++) vtot += red[i];
    const float rstd = rsqrtf(vtot * (1.0f / CH) + EPS_LN);

    float4 gv = *(const float4*)(g + t * 4);
    float4 bv = *(const float4*)(b + t * 4);
    float4 rv = *(const float4*)(res + off);
    float4 o;
    o.x = rv.x + dx * rstd * gv.x + bv.x;
    o.y = rv.y + dy * rstd * gv.y + bv.y;
    o.z = rv.z + dz * rstd * gv.z + bv.z;
    o.w = rv.w + dw * rstd * gv.w + bv.w;
    *(float4*)(out + off) = o;
    if (out_h) {
        __half2 h0 = __floats2half2_rn(o.x, o.y);
        __half2 h1 = __floats2half2_rn(o.z, o.w);
        uint2 u;
        u.x = *(uint32_t*)&h0; u.y = *(uint32_t*)&h1;
        *(uint2*)(out_h + off) = u;
    }
}

// ---------------- host orchestration ----------------
extern "C" void kernel_launch(void* const* d_in, const int* in_sizes, int n_in,
                              void* d_out, int out_size) {
    const float* depth   = (const float*)d_in[0];
    const float* context = (const float*)d_in[1];
    const float* pos     = (const float*)d_in[2];
    const float* e_wq = (const float*)d_in[3];
    const float* e_wk = (const float*)d_in[4];
    const float* e_wv = (const float*)d_in[5];
    const float* e_wm = (const float*)d_in[6];
    const float* e_w1 = (const float*)d_in[7];
    const float* e_w2 = (const float*)d_in[8];
    const float* e_g1 = (const float*)d_in[9];
    const float* e_b1 = (const float*)d_in[10];
    const float* e_g2 = (const float*)d_in[11];
    const float* e_b2 = (const float*)d_in[12];
    const float* d_wq0 = (const float*)d_in[13];
    const float* d_wk0 = (const float*)d_in[14];
    const float* d_wv0 = (const float*)d_in[15];
    const float* d_wm0 = (const float*)d_in[16];
    const float* d_wq1 = (const float*)d_in[17];
    const float* d_wk1 = (const float*)d_in[18];
    const float* d_wv1 = (const float*)d_in[19];
    const float* d_wm1 = (const float*)d_in[20];
    const float* d_w1 = (const float*)d_in[21];
    const float* d_w2 = (const float*)d_in[22];
    const float* d_g0 = (const float*)d_in[23];
    const float* d_b0 = (const float*)d_in[24];
    const float* d_g1 = (const float*)d_in[25];
    const float* d_b1 = (const float*)d_in[26];
    const float* d_g2 = (const float*)d_in[27];
    const float* d_b2 = (const float*)d_in[28];
    float* out = (float*)d_out;

    float *ctx, *q, *qkv, *msg, *x, *yb, *hf, *kvp, *kv, *ksp, *ks;
    __half *ctxh, *xh, *ybh, *attnh, *deph, *hh;
    uint32_t* wt;
    cudaGetSymbolAddress((void**)&ctx,   g_ctx);
    cudaGetSymbolAddress((void**)&q,     g_q);
    cudaGetSymbolAddress((void**)&qkv,   g_qkv);
    cudaGetSymbolAddress((void**)&msg,   g_msg);
    cudaGetSymbolAddress((void**)&x,     g_x);
    cudaGetSymbolAddress((void**)&yb,    g_y);
    cudaGetSymbolAddress((void**)&hf,    g_h);
    cudaGetSymbolAddress((void**)&ctxh,  g_ctxh);
    cudaGetSymbolAddress((void**)&xh,    g_xh);
    cudaGetSymbolAddress((void**)&ybh,   g_yh);
    cudaGetSymbolAddress((void**)&attnh, g_attnh);
    cudaGetSymbolAddress((void**)&deph,  g_deph);
    cudaGetSymbolAddress((void**)&hh,    g_hh);
    cudaGetSymbolAddress((void**)&wt,    g_wt);
    cudaGetSymbolAddress((void**)&kvp,   g_kvpart);
    cudaGetSymbolAddress((void**)&kv,    g_kv);
    cudaGetSymbolAddress((void**)&ksp,   g_kspart);
    cudaGetSymbolAddress((void**)&ks,    g_ksum);

    cudaFuncSetAttribute(gemm_h<false, 0>, cudaFuncAttributeMaxDynamicSharedMemorySize, GEMM_SMEM2);
    cudaFuncSetAttribute(gemm_h<false, 1>, cudaFuncAttributeMaxDynamicSharedMemorySize, GEMM_SMEM2);
    cudaFuncSetAttribute(gemm_h<true, 2>,  cudaFuncAttributeMaxDynamicSharedMemorySize, GEMM_SMEM2);

    // packed weight layout (uint32 words), HM = 512K words
    const size_t HM = 512 * 1024;
    uint32_t* w_qkvE = wt + 0 * HM;    // [512][3072]
    uint32_t* w_qkvD = wt + 3 * HM;    // [512][3072]
    uint32_t* w_kvD1 = wt + 6 * HM;    // [512][2048]
    uint32_t* w_q1   = wt + 8 * HM;    // [512][1024]
    uint32_t* w_em   = wt + 9 * HM;
    uint32_t* w_dm0  = wt + 10 * HM;
    uint32_t* w_dm1  = wt + 11 * HM;
    uint32_t* w_e1   = wt + 12 * HM;   // [512][2048]
    uint32_t* w_d1   = wt + 14 * HM;
    uint32_t* w_e2   = wt + 16 * HM;   // [1024][1024]
    uint32_t* w_d2   = wt + 18 * HM;

    PKArgs pk;
    auto seg = [&](int i, const float* s, uint32_t* d, int K, int lgN, int ostr, int co) {
        pk.src[i] = s; pk.dst[i] = d;
        pk.total[i] = (K / 2) << lgN;
        pk.lgN[i] = lgN; pk.ostride[i] = ostr; pk.colofs[i] = co;
    };
    seg(0,  e_wq,  w_qkvE, 1024, 10, 3072, 0);
    seg(1,  e_wk,  w_qkvE, 1024, 10, 3072, 1024);
    seg(2,  e_wv,  w_qkvE, 1024, 10, 3072, 2048);
    seg(3,  d_wq0, w_qkvD, 1024, 10, 3072, 0);
    seg(4,  d_wk0, w_qkvD, 1024, 10, 3072, 1024);
    seg(5,  d_wv0, w_qkvD, 1024, 10, 3072, 2048);
    seg(6,  d_wk1, w_kvD1, 1024, 10, 2048, 0);
    seg(7,  d_wv1, w_kvD1, 1024, 10, 2048, 1024);
    seg(8,  d_wq1, w_q1,  1024, 10, 1024, 0);
    seg(9,  e_wm,  w_em,  1024, 10, 1024, 0);
    seg(10, d_wm0, w_dm0, 1024, 10, 1024, 0);
    seg(11, d_wm1, w_dm1, 1024, 10, 1024, 0);
    seg(12, e_w1, w_e1, 1024, 11, 2048, 0);
    seg(13, d_w1, w_d1, 1024, 11, 2048, 0);
    seg(14, e_w2, w_e2, 2048, 10, 1024, 0);
    seg(15, d_w2, w_d2, 2048, 10, 1024, 0);
    seg(16, depth, (uint32_t*)deph, NL * CH, 0, 1, 0);   // flat fp32->fp16 pairs
    pack_w<<<dim3(256, 17), 256>>>(pk);

    const dim3 blk(256);
    const dim3 gblk(128);
    const dim3 gU(CH / 128, NL / 128);          // N=1024
    const dim3 gF(2 * CH / 128, NL / 128);      // N=2048
    const dim3 gQKV(3 * CH / 128, NL / 128);    // N=3072

    auto attention = [&](const float* qp, int ldq, const float* kp, const float* vp, int ldkv) {
        attn_kv_tc<<<dim3(NHT, KVSPLIT), gblk>>>(kp, vp, ldkv, kvp, ksp);
        kv_reduce_kernel<<<(NHT * HD * HD + 255) / 256, blk>>>(kvp, kv);
        ks_reduce_kernel<<<NHT, 128>>>(ksp, ks);
        attn_out_tc<<<dim3(LQ / 128, NHT), gblk>>>(qp, ldq, kv, ks, attnh);
    };

    // ===== encoder =====
    add_kernel<<<2048, blk>>>(context, pos, ctx, ctxh, NL * CH / 4);
    gemm_h<false, 1><<<gQKV, gblk, GEMM_SMEM2>>>((const uint32_t*)ctxh, w_qkvE, qkv, NL, 512, 3 * CH);
    attention(qkv, 3 * CH, qkv + CH, qkv + 2 * CH, 3 * CH);
    gemm_h<false, 0><<<gU, gblk, GEMM_SMEM2>>>((const uint32_t*)attnh, w_em, msg, NL, 512, CH);
    ln_res_kernel<<<NL, blk>>>(ctx, msg, e_g1, e_b1, x, xh);
    gemm_h<true, 2><<<gF, gblk, GEMM_SMEM2>>>((const uint32_t*)xh, w_e1, hh, NL, 512, 2 * CH);
    gemm_h<false, 0><<<gU, gblk, GEMM_SMEM2>>>((const uint32_t*)hh, w_e2, msg, NL, 1024, CH);
    ln_res_kernel<<<NL, blk>>>(x, msg, e_g2, e_b2, ctx, ctxh);

    // ===== decoder: self-attention =====
    gemm_h<false, 1><<<gQKV, gblk, GEMM_SMEM2>>>((const uint32_t*)deph, w_qkvD, qkv, NL, 512, 3 * CH);
    attention(qkv, 3 * CH, qkv + CH, qkv + 2 * CH, 3 * CH);
    gemm_h<false, 0><<<gU, gblk, GEMM_SMEM2>>>((const uint32_t*)attnh, w_dm0, msg, NL, 512, CH);
    ln_res_kernel<<<NL, blk>>>(depth, msg, d_g0, d_b0, x, xh);

    // ===== decoder: cross-attention =====
    gemm_h<false, 0><<<gU, gblk, GEMM_SMEM2>>>((const uint32_t*)xh, w_q1, q, NL, 512, CH);
    gemm_h<false, 1><<<gF, gblk, GEMM_SMEM2>>>((const uint32_t*)ctxh, w_kvD1, hf, NL, 512, 2 * CH);
    attention(q, CH, hf, hf + CH, 2 * CH);
    gemm_h<false, 0><<<gU, gblk, GEMM_SMEM2>>>((const uint32_t*)attnh, w_dm1, msg, NL, 512, CH);
    ln_res_kernel<<<NL, blk>>>(x, msg, d_g1, d_b1, yb, ybh);

    // ===== decoder: FFN =====
    gemm_h<true, 2><<<gF, gblk, GEMM_SMEM2>>>((const uint32_t*)ybh, w_d1, hh, NL, 512, 2 * CH);
    gemm_h<false, 0><<<gU, gblk, GEMM_SMEM2>>>((const uint32_t*)hh, w_d2, msg, NL, 1024, CH);
    ln_res_kernel<<<NL, blk>>>(yb, msg, d_g2, d_b2, out, nullptr);
}

// round 14
// speedup vs baseline: 6.7047x; 1.0305x over previous
#include <cuda_runtime.h>
#include <cuda_fp16.h>
#include <cstdint>
#include <math.h>

#define NB 4
#define LQ 2048
#define CH 1024
#define NHD 8
#define HD 128
#define NL (NB * LQ)
#define NHT (NB * NHD)
#define KVSPLIT 8
#define EPS_ATTN 1e-6f
#define EPS_LN 1e-5f

// fp16 GEMM tiles: 64 halves (32 words) per stage, 2 stages, 3 CTAs/SM
#define BSTR 136
#define ASTR2 36
#define A2_WORDS (128 * ASTR2)            // 4608
#define B2_WORDS (32 * BSTR)              // 4352
#define STG2_WORDS (A2_WORDS + B2_WORDS)  // 8960
#define GEMM_SMEM2 (2 * STG2_WORDS * 4)   // 71680

// fp16 attention tiles
#define KH_ASTR 17     // Kt/Qs stride (words) — scalar STS, LDS fragments
#define VSTR 137       // attn_kv V stride (scalar STS only)
#define BCP_STR 136    // attn_out B stride (cp.async 16B => row byte stride % 16 == 0)

// ---------------- scratch (256B-aligned) ----------------
__device__ __align__(256) float g_ctx[NL * CH];
__device__ __align__(256) float g_msg[NL * CH];
__device__ __align__(256) float g_x[NL * CH];
__device__ __align__(256) float g_y[NL * CH];
__device__ __align__(256) __half g_ctxh[NL * CH];
__device__ __align__(256) __half g_xh[NL * CH];
__device__ __align__(256) __half g_yh[NL * CH];
__device__ __align__(256) __half g_attnh[NL * CH];
__device__ __align__(256) __half g_deph[NL * CH];
__device__ __align__(256) __half g_hh[NL * 2 * CH];
__device__ __align__(256) __half g_qkvh[NL * 3 * CH];
__device__ __align__(256) uint32_t g_wt[12 * 1024 * 1024];
__device__ __align__(256) float g_kvpart[KVSPLIT * NHT * HD * HD];
__device__ __align__(256) uint32_t g_kvh[NHT * (HD / 2) * HD];
__device__ __align__(256) float g_kspart[KVSPLIT * NHT * HD];
__device__ __align__(256) float g_ksum[NHT * HD];

__device__ __forceinline__ float fmap(float x) { return x > 0.0f ? x + 1.0f : expf(x); }

__device__ __forceinline__ void cp16(uint32_t saddr, const void* g) {
    asm volatile("cp.async.cg.shared.global [%0], [%1], 16;" :: "r"(saddr), "l"(g));
}

__device__ __forceinline__ uint32_t smem_u32(const void* p) {
    uint32_t a;
    asm("{ .reg .u64 t; cvta.to.shared.u64 t, %1; cvt.u32.u64 %0, t; }" : "=r"(a) : "l"(p));
    return a;
}

__device__ __forceinline__ void mma_f16(float* d,
                                        uint32_t a0, uint32_t a1, uint32_t a2, uint32_t a3,
                                        uint32_t b0, uint32_t b1) {
    asm volatile(
        "mma.sync.aligned.m16n8k16.row.col.f32.f16.f16.f32 "
        "{%0,%1,%2,%3}, {%4,%5,%6,%7}, {%8,%9}, {%0,%1,%2,%3};"
        : "+f"(d[0]), "+f"(d[1]), "+f"(d[2]), "+f"(d[3])
        : "r"(a0), "r"(a1), "r"(a2), "r"(a3), "r"(b0), "r"(b1));
}

// ---------------- weight pack: fp32 [K][N] -> half2 words [K/2][ostride] ----------------
struct PKArgs {
    const float* src[17];
    uint32_t* dst[17];
    int total[17];
    int lgN[17];
    int ostride[17];
    int colofs[17];
};
__global__ void pack_w(PKArgs a) {
    const int seg = blockIdx.y;
    const float* __restrict__ s = a.src[seg];
    uint32_t* __restrict__ d = a.dst[seg];
    const int total = a.total[seg];
    const int lg = a.lgN[seg];
    const int Nm = (1 << lg) - 1;
    const int ostr = a.ostride[seg];
    const int co = a.colofs[seg];
    int idx = blockIdx.x * blockDim.x + threadIdx.x;
    int stride = gridDim.x * blockDim.x;
    for (int i = idx; i < total; i += stride) {
        int n = i & Nm;
        int k2 = i >> lg;
        size_t slo = ((size_t)k2 << (lg + 1)) + n;
        float lo = s[slo];
        float hi = s[slo + (1 << lg)];
        __half2 h = __floats2half2_rn(lo, hi);
        d[(size_t)k2 * ostr + co + n] = *(uint32_t*)&h;
    }
}

// ---------------- fp16 tensor-core GEMM (cp.async 2-stage, 3 CTAs/SM) ----------------
// OUTM: 0 = fp32 out, 2 = fp16 out
template <bool RELU, int OUTM>
__global__ __launch_bounds__(128, 3) void gemm_h(
    const uint32_t* __restrict__ Aw, const uint32_t* __restrict__ Bw, void* __restrict__ Cout,
    int M, int Kw, int Nn) {
    extern __shared__ uint32_t sm[];
    const uint32_t smaddr = smem_u32(sm);
    const int tid = threadIdx.x;
    const int wid = tid >> 5, lane = tid & 31;
    const int bm = blockIdx.y * 128;
    const int bn = blockIdx.x * 128;
    const int wm = (wid & 1) * 64;
    const int wn = (wid >> 1) * 64;
    const int r = lane >> 2, cq = lane & 3;

    float acc[4][8][4];
#pragma unroll
    for (int i = 0; i < 4; i++)
#pragma unroll
        for (int j = 0; j < 8; j++)
#pragma unroll
            for (int c = 0; c < 4; c++) acc[i][j][c] = 0.0f;

    const int KT = Kw / 32;

    auto issue = [&](int s, int kt) {
        const uint32_t sbA = smaddr + s * (STG2_WORDS * 4);
        const uint32_t* Ag = Aw + (size_t)bm * Kw + (size_t)kt * 32;
#pragma unroll
        for (int i = 0; i < 8; i++) {
            int idx = tid + 128 * i;
            int row = idx >> 3, c4 = (idx & 7) * 4;
            cp16(sbA + (row * ASTR2 + c4) * 4, Ag + (size_t)row * Kw + c4);
        }
        const uint32_t sbB = sbA + A2_WORDS * 4;
        const uint32_t* Bg = Bw + (size_t)(kt * 32) * Nn + bn;
#pragma unroll
        for (int i = 0; i < 8; i++) {
            int idx = tid + 128 * i;
            int kk = idx >> 5, n4 = (idx & 31) * 4;
            cp16(sbB + (kk * BSTR + n4) * 4, Bg + (size_t)kk * Nn + n4);
        }
        asm volatile("cp.async.commit_group;" ::: "memory");
    };

    issue(0, 0);

    for (int kt = 0; kt < KT; kt++) {
        const int buf = kt & 1;
        asm volatile("cp.async.wait_group 0;" ::: "memory");
        __syncthreads();
        if (kt + 1 < KT) issue(buf ^ 1, kt + 1);

        const uint32_t* Asb = sm + buf * STG2_WORDS;
        const uint32_t* Bsb = Asb + A2_WORDS;
#pragma unroll
        for (int s = 0; s < 4; s++) {
            uint32_t af[4][4];
#pragma unroll
            for (int i = 0; i < 4; i++) {
                const int arow = wm + 16 * i + r;
                const int kc = 8 * s + cq;
                af[i][0] = Asb[arow * ASTR2 + kc];
                af[i][1] = Asb[(arow + 8) * ASTR2 + kc];
                af[i][2] = Asb[arow * ASTR2 + kc + 4];
                af[i][3] = Asb[(arow + 8) * ASTR2 + kc + 4];
            }
            uint32_t bf[8][2];
#pragma unroll
            for (int j = 0; j < 8; j++) {
                const int ncol = wn + 8 * j + r;
                bf[j][0] = Bsb[(8 * s + cq) * BSTR + ncol];
                bf[j][1] = Bsb[(8 * s + cq + 4) * BSTR + ncol];
            }
#pragma unroll
            for (int i = 0; i < 4; i++)
#pragma unroll
                for (int j = 0; j < 8; j++)
                    mma_f16(acc[i][j], af[i][0], af[i][1], af[i][2], af[i][3],
                            bf[j][0], bf[j][1]);
        }
    }

#pragma unroll
    for (int i = 0; i < 4; i++) {
        const int row0 = bm + wm + 16 * i + r;
#pragma unroll
        for (int j = 0; j < 8; j++) {
            const int col = bn + wn + 8 * j + 2 * cq;
            float v[4] = {acc[i][j][0], acc[i][j][1], acc[i][j][2], acc[i][j][3]};
            if (RELU) {
#pragma unroll
                for (int c = 0; c < 4; c++) v[c] = fmaxf(v[c], 0.f);
            }
            if (OUTM == 2) {
                __half* Ch = (__half*)Cout;
                __half2 h0 = __floats2half2_rn(v[0], v[1]);
                __half2 h1 = __floats2half2_rn(v[2], v[3]);
                *(__half2*)(Ch + (size_t)row0 * Nn + col) = h0;
                *(__half2*)(Ch + (size_t)(row0 + 8) * Nn + col) = h1;
            } else {
                float* Cf = (float*)Cout;
                float2 v0, v1;
                v0.x = v[0]; v0.y = v[1]; v1.x = v[2]; v1.y = v[3];
                *(float2*)(Cf + (size_t)row0 * Nn + col) = v0;
                *(float2*)(Cf + (size_t)(row0 + 8) * Nn + col) = v1;
            }
        }
    }
}

// ---------------- elementwise add (fp32 out + fp16 copy) ----------------
__global__ void add_kernel(const float* __restrict__ a, const float* __restrict__ b,
                           float* __restrict__ o, __half* __restrict__ oh, int n4) {
    int idx = blockIdx.x * blockDim.x + threadIdx.x;
    int stride = gridDim.x * blockDim.x;
    const float4* a4 = (const float4*)a;
    const float4* b4 = (const float4*)b;
    float4* o4 = (float4*)o;
    for (int i = idx; i < n4; i += stride) {
        float4 x = a4[i], y = b4[i];
        x.x += y.x; x.y += y.y; x.z += y.z; x.w += y.w;
        o4[i] = x;
        __half2 h0 = __floats2half2_rn(x.x, x.y);
        __half2 h1 = __floats2half2_rn(x.z, x.w);
        uint2 u;
        u.x = *(uint32_t*)&h0; u.y = *(uint32_t*)&h1;
        *(uint2*)(oh + (size_t)i * 4) = u;
    }
}

// ---------------- fp16 attn KV: KV = fmap(K)^T @ V over L-slice + ksum ----------------
__global__ __launch_bounds__(128) void attn_kv_h(
    const __half* __restrict__ Kg, const __half* __restrict__ Vg, int ld,
    float* __restrict__ kvpart, float* __restrict__ kspart) {
    __shared__ uint32_t Kt[2][128 * KH_ASTR];  // [d][w]
    __shared__ uint32_t Vs[2][16 * VSTR];      // [w][v]
    __shared__ float ksp[16][129];

    const int nh = blockIdx.x;
    const int split = blockIdx.y;
    const int n = nh >> 3, h = nh & 7;
    const int lbase = split * (LQ / KVSPLIT);
    const int tid = threadIdx.x;
    const int wid = tid >> 5, lane = tid & 31;
    const int wm = (wid & 1) * 64;
    const int wn = (wid >> 1) * 64;
    const int r = lane >> 2, cq = lane & 3;

    const int w = tid & 15;          // l-pair index (l = 2w, 2w+1)
    const int db = (tid >> 4) * 16;  // d / v base
    const size_t base = ((size_t)(n * LQ + lbase)) * ld + h * HD;

    float acc[4][8][4];
#pragma unroll
    for (int i = 0; i < 4; i++)
#pragma unroll
        for (int j = 0; j < 8; j++)
#pragma unroll
            for (int c = 0; c < 4; c++) acc[i][j][c] = 0.0f;
    float kacc[16];
#pragma unroll
    for (int i = 0; i < 16; i++) kacc[i] = 0.0f;

    uint4 kr[4], vr[4];
    const int KT = (LQ / KVSPLIT) / 32;   // 8

    auto ldg = [&](int kt) {
        const __half* kp = Kg + base + (size_t)(kt * 32 + 2 * w) * ld + db;
        kr[0] = *(const uint4*)kp;
        kr[1] = *(const uint4*)(kp + 8);
        kr[2] = *(const uint4*)(kp + ld);
        kr[3] = *(const uint4*)(kp + ld + 8);
        const __half* vp = Vg + base + (size_t)(kt * 32 + 2 * w) * ld + db;
        vr[0] = *(const uint4*)vp;
        vr[1] = *(const uint4*)(vp + 8);
        vr[2] = *(const uint4*)(vp + ld);
        vr[3] = *(const uint4*)(vp + ld + 8);
    };
    auto sts = [&](int buf) {
        const __half* kh = (const __half*)kr;
        const __half* vh = (const __half*)vr;
#pragma unroll
        for (int i = 0; i < 16; i++) {
            float lo = fmap(__half2float(kh[i]));
            float hi = fmap(__half2float(kh[16 + i]));
            __half2 p = __floats2half2_rn(lo, hi);
            float2 pr = __half22float2(p);
            kacc[i] += pr.x + pr.y;
            Kt[buf][(db + i) * KH_ASTR + w] = *(uint32_t*)&p;
            __half2 pv = __halves2half2(vh[i], vh[16 + i]);
            Vs[buf][w * VSTR + db + i] = *(uint32_t*)&pv;
        }
    };

    ldg(0);
    sts(0);
    __syncthreads();

    for (int kt = 0; kt < KT; kt++) {
        const int buf = kt & 1;
        if (kt + 1 < KT) ldg(kt + 1);

        const uint32_t* Asb = Kt[buf];
        const uint32_t* Bsb = Vs[buf];
#pragma unroll
        for (int s = 0; s < 2; s++) {
            uint32_t af[4][4];
#pragma unroll
            for (int i = 0; i < 4; i++) {
                const int arow = wm + 16 * i + r;
                const int kc = 8 * s + cq;
                af[i][0] = Asb[arow * KH_ASTR + kc];
                af[i][1] = Asb[(arow + 8) * KH_ASTR + kc];
                af[i][2] = Asb[arow * KH_ASTR + kc + 4];
                af[i][3] = Asb[(arow + 8) * KH_ASTR + kc + 4];
            }
            uint32_t bf[8][2];
#pragma unroll
            for (int j = 0; j < 8; j++) {
                const int ncol = wn + 8 * j + r;
                bf[j][0] = Bsb[(8 * s + cq) * VSTR + ncol];
                bf[j][1] = Bsb[(8 * s + cq + 4) * VSTR + ncol];
            }
#pragma unroll
            for (int i = 0; i < 4; i++)
#pragma unroll
                for (int j = 0; j < 8; j++)
                    mma_f16(acc[i][j], af[i][0], af[i][1], af[i][2], af[i][3],
                            bf[j][0], bf[j][1]);
        }
        __syncthreads();
        if (kt + 1 < KT) {
            sts(buf ^ 1);
            __syncthreads();
        }
    }

    float* o = kvpart + (((size_t)(split * NHT + nh)) << 14);
#pragma unroll
    for (int i = 0; i < 4; i++) {
        const int row0 = wm + 16 * i + r;
#pragma unroll
        for (int j = 0; j < 8; j++) {
            const int col = wn + 8 * j + 2 * cq;
            float2 v0, v1;
            v0.x = acc[i][j][0]; v0.y = acc[i][j][1];
            v1.x = acc[i][j][2]; v1.y = acc[i][j][3];
            *(float2*)(o + (size_t)row0 * HD + col) = v0;
            *(float2*)(o + (size_t)(row0 + 8) * HD + col) = v1;
        }
    }

#pragma unroll
    for (int i = 0; i < 16; i++) ksp[w][db + i] = kacc[i];
    __syncthreads();
    {
        int d = tid;
        float s = 0.0f;
#pragma unroll
        for (int j = 0; j < 16; j++) s += ksp[j][d];
        kspart[(split * NHT + nh) * HD + d] = s;
    }
}

// ---------------- KV reduce -> packed half2 words [d/2][v] ----------------
__global__ void kv_reduce_h(const float* __restrict__ part, uint32_t* __restrict__ kvh) {
    int idx = blockIdx.x * 256 + threadIdx.x;
    if (idx < NHT * (HD / 2) * HD) {
        int nh = idx >> 13;
        int d2 = (idx >> 7) & 63;
        int v = idx & 127;
        float lo = 0.0f, hi = 0.0f;
#pragma unroll
        for (int sp = 0; sp < KVSPLIT; sp++) {
            const float* p = part + (((size_t)(sp * NHT + nh)) << 14);
            lo += p[(2 * d2) * HD + v];
            hi += p[(2 * d2 + 1) * HD + v];
        }
        __half2 h = __floats2half2_rn(lo, hi);
        kvh[idx] = *(uint32_t*)&h;
    }
}

__global__ void ks_reduce_kernel(const float* __restrict__ part, float* __restrict__ ks) {
    int idx = blockIdx.x * 128 + threadIdx.x;
    int nh = idx >> 7, d = idx & 127;
    float s = 0.0f;
#pragma unroll
    for (int sp = 0; sp < KVSPLIT; sp++)
        s += part[(sp * NHT + nh) * HD + d];
    ks[idx] = s;
}

// ---------------- fp16 attn out: O = fmap(Q) @ KV * Z ----------------
__global__ __launch_bounds__(128) void attn_out_h(
    const __half* __restrict__ Qg, int ldq, const uint32_t* __restrict__ KVh,
    const float* __restrict__ Ksum, __half* __restrict__ Og) {
    __shared__ uint32_t Qs[2][128 * KH_ASTR];
    __shared__ uint32_t Bs[2][16 * BCP_STR];   // stride 136: cp.async rows 16B-aligned
    __shared__ float kss[HD];
    __shared__ float qks[128];
    const uint32_t BsAddr = smem_u32(Bs);

    const int nh = blockIdx.y;
    const int n = nh >> 3, h = nh & 7;
    const int l0 = blockIdx.x * 128;
    const int tid = threadIdx.x;
    const int wid = tid >> 5, lane = tid & 31;
    const int wm = (wid & 1) * 64;
    const int wn = (wid >> 1) * 64;
    const int r = lane >> 2, cq = lane & 3;

    kss[tid] = Ksum[nh * HD + tid];

    const size_t qbase = ((size_t)(n * LQ + l0)) * ldq + h * HD;
    const uint32_t* kvb = KVh + ((size_t)nh << 13);

    const int qrow0 = tid >> 2;
    const int qw4 = (tid & 3) * 4;

    float acc[4][8][4];
#pragma unroll
    for (int i = 0; i < 4; i++)
#pragma unroll
        for (int j = 0; j < 8; j++)
#pragma unroll
            for (int c = 0; c < 4; c++) acc[i][j][c] = 0.0f;
    float qkp[4] = {0.f, 0.f, 0.f, 0.f};

    uint4 qr[4];
    const int KT = HD / 32;   // 4

    auto ldgQ = [&](int kt) {
#pragma unroll
        for (int i = 0; i < 4; i++)
            qr[i] = *(const uint4*)(Qg + qbase + (size_t)(qrow0 + 32 * i) * ldq + kt * 32 + qw4 * 2);
    };
    auto stsQ = [&](int buf, int kt) {
#pragma unroll
        for (int i = 0; i < 4; i++) {
            const __half* qh = (const __half*)&qr[i];
#pragma unroll
            for (int j = 0; j < 4; j++) {
                float lo = fmap(__half2float(qh[2 * j]));
                float hi = fmap(__half2float(qh[2 * j + 1]));
                __half2 p = __floats2half2_rn(lo, hi);
                float2 pr = __half22float2(p);
                const int dc = kt * 32 + (qw4 + j) * 2;
                qkp[i] += pr.x * kss[dc] + pr.y * kss[dc + 1];
                Qs[buf][(qrow0 + 32 * i) * KH_ASTR + qw4 + j] = *(uint32_t*)&p;
            }
        }
    };
    auto cpB = [&](int buf, int kt) {
#pragma unroll
        for (int i = 0; i < 4; i++) {
            int idx = tid + 128 * i;
            int kk = idx >> 5, v4 = (idx & 31) * 4;
            cp16(BsAddr + (buf * (16 * BCP_STR) + kk * BCP_STR + v4) * 4,
                 kvb + (size_t)(kt * 16 + kk) * HD + v4);
        }
        asm volatile("cp.async.commit_group;" ::: "memory");
    };

    ldgQ(0);
    cpB(0, 0);
    __syncthreads();   // kss visible to all warps BEFORE first stsQ reads it
    stsQ(0, 0);
    asm volatile("cp.async.wait_group 0;" ::: "memory");
    __syncthreads();

    for (int kt = 0; kt < KT; kt++) {
        const int buf = kt & 1;
        if (kt + 1 < KT) {
            cpB(buf ^ 1, kt + 1);
            ldgQ(kt + 1);
        }
        const uint32_t* Asb = Qs[buf];
        const uint32_t* Bsb = Bs[buf];
#pragma unroll
        for (int s = 0; s < 2; s++) {
            uint32_t af[4][4];
#pragma unroll
            for (int i = 0; i < 4; i++) {
                const int arow = wm + 16 * i + r;
                const int kc = 8 * s + cq;
                af[i][0] = Asb[arow * KH_ASTR + kc];
                af[i][1] = Asb[(arow + 8) * KH_ASTR + kc];
                af[i][2] = Asb[arow * KH_ASTR + kc + 4];
                af[i][3] = Asb[(arow + 8) * KH_ASTR + kc + 4];
            }
            uint32_t bf[8][2];
#pragma unroll
            for (int j = 0; j < 8; j++) {
                const int ncol = wn + 8 * j + r;
                bf[j][0] = Bsb[(8 * s + cq) * BCP_STR + ncol];
                bf[j][1] = Bsb[(8 * s + cq + 4) * BCP_STR + ncol];
            }
#pragma unroll
            for (int i = 0; i < 4; i++)
#pragma unroll
                for (int j = 0; j < 8; j++)
                    mma_f16(acc[i][j], af[i][0], af[i][1], af[i][2], af[i][3],
                            bf[j][0], bf[j][1]);
        }
        if (kt + 1 < KT) stsQ(buf ^ 1, kt + 1);
        asm volatile("cp.async.wait_group 0;" ::: "memory");
        __syncthreads();
    }

#pragma unroll
    for (int i = 0; i < 4; i++) {
        float v = qkp[i];
        v += __shfl_xor_sync(0xffffffffu, v, 1);
        v += __shfl_xor_sync(0xffffffffu, v, 2);
        if ((lane & 3) == 0) qks[qrow0 + 32 * i] = v;
    }
    __syncthreads();

#pragma unroll
    for (int i = 0; i < 4; i++) {
        const int row0 = wm + 16 * i + r;
        const float z0 = 1.0f / (qks[row0] + EPS_ATTN);
        const float z1 = 1.0f / (qks[row0 + 8] + EPS_ATTN);
        __half* op0 = Og + ((size_t)(n * LQ + l0 + row0)) * CH + h * HD;
        __half* op1 = Og + ((size_t)(n * LQ + l0 + row0 + 8)) * CH + h * HD;
#pragma unroll
        for (int j = 0; j < 8; j++) {
            const int col = wn + 8 * j + 2 * cq;
            __half2 h0 = __floats2half2_rn(acc[i][j][0] * z0, acc[i][j][1] * z0);
            __half2 h1 = __floats2half2_rn(acc[i][j][2] * z1, acc[i][j][3] * z1);
            *(__half2*)(op0 + col) = h0;
            *(__half2*)(op1 + col) = h1;
        }
    }
}

// ---------------- fused residual + LayerNorm (fp32 out + optional fp16 copy) ----------------
__global__ __launch_bounds__(256) void ln_res_kernel(
    const float* __restrict__ res, const float* __restrict__ y,
    const float* __restrict__ g, const float* __restrict__ b,
    float* __restrict__ out, __half* __restrict__ out_h) {
    const int row = blockIdx.x;
    const int t = threadIdx.x;
    const size_t off = (size_t)row * CH + t * 4;
    float4 v = *(const float4*)(y + off);
    __shared__ float red[8];
    const int lane = t & 31, w = t >> 5;

    float s = v.x + v.y + v.z + v.w;
#pragma unroll
    for (int o = 16; o; o >>= 1) s += __shfl_xor_sync(0xffffffffu, s, o);
    if (!lane) red[w] = s;
    __syncthreads();
    float tot = red[0];
#pragma unroll
    for (int i = 1; i < 8; i++) tot += red[i];
    const float mean = tot * (1.0f / CH);

    float dx = v.x - mean, dy = v.y - mean, dz = v.z - mean, dw = v.w - mean;
    float sq = dx * dx + dy * dy + dz * dz + dw * dw;
    __syncthreads();
#pragma unroll
    for (int o = 16; o; o >>= 1) sq += __shfl_xor_sync(0xffffffffu, sq, o);
    if (!lane) red[w] = sq;
    __syncthreads();
    float vtot = red[0];
#pragma unroll
    for (int i = 1; i < 8; i++) vtot += red[i];
    const float rstd = rsqrtf(vtot * (1.0f / CH) + EPS_LN);

    float4 gv = *(const float4*)(g + t * 4);
    float4 bv = *(const float4*)(b + t * 4);
    float4 rv = *(const float4*)(res + off);
    float4 o;
    o.x = rv.x + dx * rstd * gv.x + bv.x;
    o.y = rv.y + dy * rstd * gv.y + bv.y;
    o.z = rv.z + dz * rstd * gv.z + bv.z;
    o.w = rv.w + dw * rstd * gv.w + bv.w;
    *(float4*)(out + off) = o;
    if (out_h) {
        __half2 h0 = __floats2half2_rn(o.x, o.y);
        __half2 h1 = __floats2half2_rn(o.z, o.w);
        uint2 u;
        u.x = *(uint32_t*)&h0; u.y = *(uint32_t*)&h1;
        *(uint2*)(out_h + off) = u;
    }
}

// ---------------- host orchestration ----------------
extern "C" void kernel_launch(void* const* d_in, const int* in_sizes, int n_in,
                              void* d_out, int out_size) {
    const float* depth   = (const float*)d_in[0];
    const float* context = (const float*)d_in[1];
    const float* pos     = (const float*)d_in[2];
    const float* e_wq = (const float*)d_in[3];
    const float* e_wk = (const float*)d_in[4];
    const float* e_wv = (const float*)d_in[5];
    const float* e_wm = (const float*)d_in[6];
    const float* e_w1 = (const float*)d_in[7];
    const float* e_w2 = (const float*)d_in[8];
    const float* e_g1 = (const float*)d_in[9];
    const float* e_b1 = (const float*)d_in[10];
    const float* e_g2 = (const float*)d_in[11];
    const float* e_b2 = (const float*)d_in[12];
    const float* d_wq0 = (const float*)d_in[13];
    const float* d_wk0 = (const float*)d_in[14];
    const float* d_wv0 = (const float*)d_in[15];
    const float* d_wm0 = (const float*)d_in[16];
    const float* d_wq1 = (const float*)d_in[17];
    const float* d_wk1 = (const float*)d_in[18];
    const float* d_wv1 = (const float*)d_in[19];
    const float* d_wm1 = (const float*)d_in[20];
    const float* d_w1 = (const float*)d_in[21];
    const float* d_w2 = (const float*)d_in[22];
    const float* d_g0 = (const float*)d_in[23];
    const float* d_b0 = (const float*)d_in[24];
    const float* d_g1 = (const float*)d_in[25];
    const float* d_b1 = (const float*)d_in[26];
    const float* d_g2 = (const float*)d_in[27];
    const float* d_b2 = (const float*)d_in[28];
    float* out = (float*)d_out;

    float *ctx, *msg, *x, *yb, *kvp, *ksp, *ks;
    __half *ctxh, *xh, *ybh, *attnh, *deph, *hh, *qkvh;
    uint32_t *wt, *kvh;
    cudaGetSymbolAddress((void**)&ctx,   g_ctx);
    cudaGetSymbolAddress((void**)&msg,   g_msg);
    cudaGetSymbolAddress((void**)&x,     g_x);
    cudaGetSymbolAddress((void**)&yb,    g_y);
    cudaGetSymbolAddress((void**)&ctxh,  g_ctxh);
    cudaGetSymbolAddress((void**)&xh,    g_xh);
    cudaGetSymbolAddress((void**)&ybh,   g_yh);
    cudaGetSymbolAddress((void**)&attnh, g_attnh);
    cudaGetSymbolAddress((void**)&deph,  g_deph);
    cudaGetSymbolAddress((void**)&hh,    g_hh);
    cudaGetSymbolAddress((void**)&qkvh,  g_qkvh);
    cudaGetSymbolAddress((void**)&wt,    g_wt);
    cudaGetSymbolAddress((void**)&kvp,   g_kvpart);
    cudaGetSymbolAddress((void**)&kvh,   g_kvh);
    cudaGetSymbolAddress((void**)&ksp,   g_kspart);
    cudaGetSymbolAddress((void**)&ks,    g_ksum);

    cudaFuncSetAttribute(gemm_h<false, 0>, cudaFuncAttributeMaxDynamicSharedMemorySize, GEMM_SMEM2);
    cudaFuncSetAttribute(gemm_h<false, 2>, cudaFuncAttributeMaxDynamicSharedMemorySize, GEMM_SMEM2);
    cudaFuncSetAttribute(gemm_h<true, 2>,  cudaFuncAttributeMaxDynamicSharedMemorySize, GEMM_SMEM2);

    const size_t HM = 512 * 1024;
    uint32_t* w_qkvE = wt + 0 * HM;
    uint32_t* w_qkvD = wt + 3 * HM;
    uint32_t* w_kvD1 = wt + 6 * HM;
    uint32_t* w_q1   = wt + 8 * HM;
    uint32_t* w_em   = wt + 9 * HM;
    uint32_t* w_dm0  = wt + 10 * HM;
    uint32_t* w_dm1  = wt + 11 * HM;
    uint32_t* w_e1   = wt + 12 * HM;
    uint32_t* w_d1   = wt + 14 * HM;
    uint32_t* w_e2   = wt + 16 * HM;
    uint32_t* w_d2   = wt + 18 * HM;

    PKArgs pk;
    auto seg = [&](int i, const float* s, uint32_t* d, int K, int lgN, int ostr, int co) {
        pk.src[i] = s; pk.dst[i] = d;
        pk.total[i] = (K / 2) << lgN;
        pk.lgN[i] = lgN; pk.ostride[i] = ostr; pk.colofs[i] = co;
    };
    seg(0,  e_wq,  w_qkvE, 1024, 10, 3072, 0);
    seg(1,  e_wk,  w_qkvE, 1024, 10, 3072, 1024);
    seg(2,  e_wv,  w_qkvE, 1024, 10, 3072, 2048);
    seg(3,  d_wq0, w_qkvD, 1024, 10, 3072, 0);
    seg(4,  d_wk0, w_qkvD, 1024, 10, 3072, 1024);
    seg(5,  d_wv0, w_qkvD, 1024, 10, 3072, 2048);
    seg(6,  d_wk1, w_kvD1, 1024, 10, 2048, 0);
    seg(7,  d_wv1, w_kvD1, 1024, 10, 2048, 1024);
    seg(8,  d_wq1, w_q1,  1024, 10, 1024, 0);
    seg(9,  e_wm,  w_em,  1024, 10, 1024, 0);
    seg(10, d_wm0, w_dm0, 1024, 10, 1024, 0);
    seg(11, d_wm1, w_dm1, 1024, 10, 1024, 0);
    seg(12, e_w1, w_e1, 1024, 11, 2048, 0);
    seg(13, d_w1, w_d1, 1024, 11, 2048, 0);
    seg(14, e_w2, w_e2, 2048, 10, 1024, 0);
    seg(15, d_w2, w_d2, 2048, 10, 1024, 0);
    seg(16, depth, (uint32_t*)deph, NL * CH, 0, 1, 0);
    pack_w<<<dim3(256, 17), 256>>>(pk);

    const dim3 blk(256);
    const dim3 gblk(128);
    const dim3 gU(CH / 128, NL / 128);
    const dim3 gF(2 * CH / 128, NL / 128);
    const dim3 gQKV(3 * CH / 128, NL / 128);

    auto attention = [&](const __half* qp, int ldq, const __half* kp, const __half* vp, int ldkv) {
        attn_kv_h<<<dim3(NHT, KVSPLIT), gblk>>>(kp, vp, ldkv, kvp, ksp);
        kv_reduce_h<<<(NHT * (HD / 2) * HD + 255) / 256, blk>>>(kvp, kvh);
        ks_reduce_kernel<<<NHT, 128>>>(ksp, ks);
        attn_out_h<<<dim3(LQ / 128, NHT), gblk>>>(qp, ldq, kvh, ks, attnh);
    };

    // ===== encoder =====
    add_kernel<<<2048, blk>>>(context, pos, ctx, ctxh, NL * CH / 4);
    gemm_h<false, 2><<<gQKV, gblk, GEMM_SMEM2>>>((const uint32_t*)ctxh, w_qkvE, qkvh, NL, 512, 3 * CH);
    attention(qkvh, 3 * CH, qkvh + CH, qkvh + 2 * CH, 3 * CH);
    gemm_h<false, 0><<<gU, gblk, GEMM_SMEM2>>>((const uint32_t*)attnh, w_em, msg, NL, 512, CH);
    ln_res_kernel<<<NL, blk>>>(ctx, msg, e_g1, e_b1, x, xh);
    gemm_h<true, 2><<<gF, gblk, GEMM_SMEM2>>>((const uint32_t*)xh, w_e1, hh, NL, 512, 2 * CH);
    gemm_h<false, 0><<<gU, gblk, GEMM_SMEM2>>>((const uint32_t*)hh, w_e2, msg, NL, 1024, CH);
    ln_res_kernel<<<NL, blk>>>(x, msg, e_g2, e_b2, ctx, ctxh);

    // ===== decoder: self-attention =====
    gemm_h<false, 2><<<gQKV, gblk, GEMM_SMEM2>>>((const uint32_t*)deph, w_qkvD, qkvh, NL, 512, 3 * CH);
    attention(qkvh, 3 * CH, qkvh + CH, qkvh + 2 * CH, 3 * CH);
    gemm_h<false, 0><<<gU, gblk, GEMM_SMEM2>>>((const uint32_t*)attnh, w_dm0, msg, NL, 512, CH);
    ln_res_kernel<<<NL, blk>>>(depth, msg, d_g0, d_b0, x, xh);

    // ===== decoder: cross-attention =====
    {
        __half* crossq = qkvh;
        __half* crosskv = qkvh + (size_t)NL * CH;
        gemm_h<false, 2><<<gU, gblk, GEMM_SMEM2>>>((const uint32_t*)xh, w_q1, crossq, NL, 512, CH);
        gemm_h<false, 2><<<gF, gblk, GEMM_SMEM2>>>((const uint32_t*)ctxh, w_kvD1, crosskv, NL, 512, 2 * CH);
        attention(crossq, CH, crosskv, crosskv + CH, 2 * CH);
    }
    gemm_h<false, 0><<<gU, gblk, GEMM_SMEM2>>>((const uint32_t*)attnh, w_dm1, msg, NL, 512, CH);
    ln_res_kernel<<<NL, blk>>>(x, msg, d_g1, d_b1, yb, ybh);

    // ===== decoder: FFN =====
    gemm_h<true, 2><<<gF, gblk, GEMM_SMEM2>>>((const uint32_t*)ybh, w_d1, hh, NL, 512, 2 * CH);
    gemm_h<false, 0><<<gU, gblk, GEMM_SMEM2>>>((const uint32_t*)hh, w_d2, msg, NL, 1024, CH);
    ln_res_kernel<<<NL, blk>>>(yb, msg, d_g2, d_b2, out, nullptr);
}